// round 1
// baseline (speedup 1.0000x reference)
#include <cuda_runtime.h>
#include <math.h>

#define D      1024
#define CLS    16
#define NSAMP  4096
#define MQ     4096
#define NT     16   // D / 64

// ---------------- scratch (device globals; no allocations allowed) ----------------
__device__ float g_Sigma[CLS][D][D];   // sigma, then Cholesky factor R (lower) in place
__device__ float g_V[CLS][D][D];       // V = R^{-1} (lower; diag blocks have explicit upper zeros)
__device__ float g_Base[D][D];
__device__ float g_L[D][D];
__device__ float g_sums[CLS][D];
__device__ float g_mu[CLS][D];
__device__ float g_s[CLS][D];
__device__ float g_nx[MQ];
__device__ float g_xm[MQ][CLS];
__device__ float g_ssc[CLS];
__device__ float g_mmc[CLS];
__device__ int   g_cnt[CLS];
__device__ int   g_start[CLS];
__device__ int   g_idx[NSAMP];
__device__ float g_kap;
__device__ float g_coef[CLS];      // kap + Nj
__device__ float g_invscale[CLS];  // 1/(nu_ + Nj + d + 2)

// ---------------- per-class sums + counts (deterministic) ----------------
__global__ void k_stats(const float* __restrict__ X, const int* __restrict__ y) {
    __shared__ int sy[NSAMP];
    int tid = threadIdx.x;
    for (int n = tid; n < NSAMP; n += blockDim.x) sy[n] = y[n];
    __syncthreads();
    int k = blockIdx.x * blockDim.x + tid;  // 8 blocks * 128 = 1024 columns
    float acc[CLS];
#pragma unroll
    for (int c = 0; c < CLS; c++) acc[c] = 0.f;
    for (int n = 0; n < NSAMP; n++) {
        int cls = sy[n];
        float v = X[(size_t)n * D + k];
#pragma unroll
        for (int c = 0; c < CLS; c++) acc[c] += (cls == c) ? v : 0.f;
    }
#pragma unroll
    for (int c = 0; c < CLS; c++) g_sums[c][k] = acc[c];
    if (blockIdx.x == 0) {
        __shared__ int scnt[CLS];
        if (tid < CLS) scnt[tid] = 0;
        __syncthreads();
        for (int n = tid; n < NSAMP; n += blockDim.x) atomicAdd(&scnt[sy[n]], 1);
        __syncthreads();
        if (tid < CLS) g_cnt[tid] = scnt[tid];
    }
}

// ---------------- counting sort by class + scalar params (single thread) ----------------
__global__ void k_sort_params(const int* __restrict__ y, const float* __restrict__ kappa,
                              const float* __restrict__ nu) {
    if (threadIdx.x == 0) {
        int off[CLS];
        int s = 0;
        for (int c = 0; c < CLS; c++) { g_start[c] = s; off[c] = s; s += g_cnt[c]; }
        for (int n = 0; n < NSAMP; n++) { int c = y[n]; g_idx[off[c]++] = n; }
        float kap = fabsf(kappa[0]) + 1e-6f;
        g_kap = kap;
        float nu_ = fmaxf(nu[0], (float)(D - 1) + 1e-6f);
        for (int c = 0; c < CLS; c++) {
            float Nj = (float)g_cnt[c];
            g_coef[c] = kap + Nj;
            g_invscale[c] = 1.0f / (nu_ + Nj + (float)D + 2.0f);
        }
    }
}

// ---------------- mu[c] = (kap*m + sums[c]) / (kap+Nj) ----------------
__global__ void k_mu(const float* __restrict__ m) {
    int c = blockIdx.y;
    int k = blockIdx.x * blockDim.x + threadIdx.x;
    g_mu[c][k] = (g_kap * m[k] + g_sums[c][k]) / g_coef[c];
}

// ---------------- build L = diag(|td|) + strict lower of tl ----------------
__global__ void k_buildL(const float* __restrict__ td, const float* __restrict__ tl) {
    int i = blockIdx.x;
    for (int k = threadIdx.x; k < D; k += blockDim.x) {
        float v;
        if (k < i) v = tl[(size_t)i * D + k];
        else if (k == i) v = fabsf(td[i]);
        else v = 0.f;
        g_L[i][k] = v;
    }
}

// ---------------- Base = L L^T + kap m m^T ----------------
__global__ __launch_bounds__(256) void k_base(const float* __restrict__ m) {
    __shared__ float As[16][65];
    __shared__ float Bs[16][65];
    int i0 = blockIdx.x * 64, j0 = blockIdx.y * 64;
    int tid = threadIdx.x, tx = tid & 15, ty = tid >> 4;
    float acc[4][4] = {};
    for (int k0 = 0; k0 < D; k0 += 16) {
#pragma unroll
        for (int t = 0; t < 4; t++) {
            int idx = tid + 256 * t;
            int ii = idx >> 4, kk = idx & 15;
            As[kk][ii] = g_L[i0 + ii][k0 + kk];
            Bs[kk][ii] = g_L[j0 + ii][k0 + kk];
        }
        __syncthreads();
#pragma unroll
        for (int kk = 0; kk < 16; kk++) {
            float a[4], b[4];
#pragma unroll
            for (int q = 0; q < 4; q++) a[q] = As[kk][4 * ty + q];
#pragma unroll
            for (int q = 0; q < 4; q++) b[q] = Bs[kk][4 * tx + q];
#pragma unroll
            for (int p = 0; p < 4; p++)
#pragma unroll
                for (int q = 0; q < 4; q++) acc[p][q] += a[p] * b[q];
        }
        __syncthreads();
    }
    float kap = g_kap;
#pragma unroll
    for (int p = 0; p < 4; p++) {
        int i = i0 + 4 * ty + p;
        float mi = m[i];
#pragma unroll
        for (int q = 0; q < 4; q++) {
            int j = j0 + 4 * tx + q;
            g_Base[i][j] = acc[p][q] + kap * mi * m[j];
        }
    }
}

// ---------------- Sigma[c] = (Base + S_c - coef*mu mu^T) * invscale ----------------
__global__ __launch_bounds__(256) void k_sigma(const float* __restrict__ X) {
    __shared__ float As[16][64];
    __shared__ float Bs[16][64];
    int c = blockIdx.z;
    int i0 = blockIdx.x * 64, j0 = blockIdx.y * 64;
    int tid = threadIdx.x, tx = tid & 15, ty = tid >> 4;
    int cnt = g_cnt[c], start = g_start[c];
    float acc[4][4] = {};
    for (int r0 = 0; r0 < cnt; r0 += 16) {
#pragma unroll
        for (int t = 0; t < 4; t++) {
            int idx = tid + 256 * t;
            int kk = idx >> 6, ii = idx & 63;
            int rg = r0 + kk;
            int row = (rg < cnt) ? g_idx[start + rg] : -1;
            As[kk][ii] = (row >= 0) ? X[(size_t)row * D + i0 + ii] : 0.f;
            Bs[kk][ii] = (row >= 0) ? X[(size_t)row * D + j0 + ii] : 0.f;
        }
        __syncthreads();
#pragma unroll
        for (int kk = 0; kk < 16; kk++) {
            float a[4], b[4];
#pragma unroll
            for (int q = 0; q < 4; q++) a[q] = As[kk][4 * ty + q];
#pragma unroll
            for (int q = 0; q < 4; q++) b[q] = Bs[kk][4 * tx + q];
#pragma unroll
            for (int p = 0; p < 4; p++)
#pragma unroll
                for (int q = 0; q < 4; q++) acc[p][q] += a[p] * b[q];
        }
        __syncthreads();
    }
    float coef = g_coef[c], inv = g_invscale[c];
#pragma unroll
    for (int p = 0; p < 4; p++) {
        int i = i0 + 4 * ty + p;
        float mui = g_mu[c][i];
#pragma unroll
        for (int q = 0; q < 4; q++) {
            int j = j0 + 4 * tx + q;
            g_Sigma[c][i][j] = (g_Base[i][j] + acc[p][q] - coef * mui * g_mu[c][j]) * inv;
        }
    }
}

// ---------------- blocked Cholesky: factor diag block + panel solve ----------------
__global__ __launch_bounds__(512) void k_chol_panel(int kb) {
    __shared__ float Ds[64][65];
    int c = blockIdx.x;
    int tid = threadIdx.x;
    int base = kb * 64;
    for (int e = tid; e < 64 * 64; e += 512) {
        int i = e >> 6, j = e & 63;
        Ds[i][j] = g_Sigma[c][base + i][base + j];
    }
    __syncthreads();
    for (int j = 0; j < 64; j++) {
        if (tid == 0) Ds[j][j] = sqrtf(Ds[j][j]);
        __syncthreads();
        if (tid > j && tid < 64) Ds[tid][j] /= Ds[j][j];
        __syncthreads();
        for (int e = tid; e < 64 * 64; e += 512) {
            int i = e >> 6, kc = e & 63;
            if (i > j && kc > j && kc <= i) Ds[i][kc] -= Ds[i][j] * Ds[kc][j];
        }
        __syncthreads();
    }
    // store lower of diag tile
    for (int e = tid; e < 64 * 64; e += 512) {
        int i = e >> 6, j = e & 63;
        if (j <= i) g_Sigma[c][base + i][base + j] = Ds[i][j];
    }
    __syncthreads();
    // panel rows below: solve L11 x^T = a^T (forward substitution) per row
    int nrows = D - base - 64;
    for (int rr = tid; rr < nrows; rr += 512) {
        int row = base + 64 + rr;
        float a[64];
#pragma unroll
        for (int k = 0; k < 64; k++) a[k] = g_Sigma[c][row][base + k];
#pragma unroll
        for (int j = 0; j < 64; j++) {
            float t = a[j];
#pragma unroll
            for (int k = 0; k < j; k++) t -= a[k] * Ds[j][k];
            a[j] = t / Ds[j][j];
        }
#pragma unroll
        for (int k = 0; k < 64; k++) g_Sigma[c][row][base + k] = a[k];
    }
}

// ---------------- trailing syrk update: A[ti,tj] -= P_ti P_tj^T ----------------
__global__ __launch_bounds__(256) void k_chol_trail(int kb) {
    int c = blockIdx.y;
    int pidx = blockIdx.x;
    int ti = kb + 1;
    while (pidx >= ti - kb) { pidx -= ti - kb; ti++; }
    int tj = kb + 1 + pidx;
    __shared__ float As[16][65], Bs[16][65];
    int tid = threadIdx.x, tx = tid & 15, ty = tid >> 4;
    int i0 = ti * 64, j0 = tj * 64, kbase = kb * 64;
    float acc[4][4] = {};
    for (int k0 = 0; k0 < 64; k0 += 16) {
#pragma unroll
        for (int t = 0; t < 4; t++) {
            int idx = tid + 256 * t;
            int ii = idx >> 4, kk = idx & 15;
            As[kk][ii] = g_Sigma[c][i0 + ii][kbase + k0 + kk];
            Bs[kk][ii] = g_Sigma[c][j0 + ii][kbase + k0 + kk];
        }
        __syncthreads();
#pragma unroll
        for (int kk = 0; kk < 16; kk++) {
            float a[4], b[4];
#pragma unroll
            for (int q = 0; q < 4; q++) a[q] = As[kk][4 * ty + q];
#pragma unroll
            for (int q = 0; q < 4; q++) b[q] = Bs[kk][4 * tx + q];
#pragma unroll
            for (int p = 0; p < 4; p++)
#pragma unroll
                for (int q = 0; q < 4; q++) acc[p][q] += a[p] * b[q];
        }
        __syncthreads();
    }
#pragma unroll
    for (int p = 0; p < 4; p++)
#pragma unroll
        for (int q = 0; q < 4; q++)
            g_Sigma[c][i0 + 4 * ty + p][j0 + 4 * tx + q] -= acc[p][q];
}

// ---------------- invert 64x64 diagonal blocks of R -> V diag (upper zeros) ----------------
__global__ __launch_bounds__(64) void k_triinv_diag() {
    __shared__ float Ds[64][65];
    int t = blockIdx.x, c = blockIdx.y;
    int tid = threadIdx.x;
    int base = t * 64;
    for (int e = tid; e < 64 * 64; e += 64) {
        int i = e >> 6, j = e & 63;
        Ds[i][j] = (j <= i) ? g_Sigma[c][base + i][base + j] : 0.f;
    }
    __syncthreads();
    int j = tid;  // each thread computes one column of the inverse
    float x[64];
#pragma unroll
    for (int i = 0; i < 64; i++) {
        float tval = (i == j) ? 1.0f : 0.0f;
#pragma unroll
        for (int k = 0; k < i; k++) tval -= Ds[i][k] * x[k];
        x[i] = tval / Ds[i][i];  // yields 0 for i<j automatically
    }
#pragma unroll
    for (int i = 0; i < 64; i++) g_V[c][base + i][base + j] = x[i];
}

// ---------------- off-diagonal V blocks, level by level ----------------
__global__ __launch_bounds__(256) void k_triinv_off(int lev) {
    __shared__ float Ash[64][17];
    __shared__ float Bsh[16][65];
    __shared__ float Ts[64][65];
    __shared__ float Dsh[64][65];
    int c = blockIdx.y;
    int jb = blockIdx.x;
    int ib = jb + lev;
    int tid = threadIdx.x, tx = tid & 15, ty = tid >> 4;
    float acc[4][4] = {};
    int kr0 = jb * 64, kr1 = ib * 64;
    for (int k0 = kr0; k0 < kr1; k0 += 16) {
#pragma unroll
        for (int t = 0; t < 4; t++) {
            int idx = tid + 256 * t;
            {
                int ii = idx >> 4, kk = idx & 15;
                Ash[ii][kk] = g_Sigma[c][ib * 64 + ii][k0 + kk];
            }
            {
                int kk = idx >> 6, jj = idx & 63;
                Bsh[kk][jj] = g_V[c][k0 + kk][jb * 64 + jj];
            }
        }
        __syncthreads();
#pragma unroll
        for (int kk = 0; kk < 16; kk++) {
            float a[4], b[4];
#pragma unroll
            for (int q = 0; q < 4; q++) a[q] = Ash[4 * ty + q][kk];
#pragma unroll
            for (int q = 0; q < 4; q++) b[q] = Bsh[kk][4 * tx + q];
#pragma unroll
            for (int p = 0; p < 4; p++)
#pragma unroll
                for (int q = 0; q < 4; q++) acc[p][q] += a[p] * b[q];
        }
        __syncthreads();
    }
    // stash tmp, load Dinv(ib) = V[ib][ib]
#pragma unroll
    for (int p = 0; p < 4; p++)
#pragma unroll
        for (int q = 0; q < 4; q++) Ts[4 * ty + p][4 * tx + q] = acc[p][q];
    for (int e = tid; e < 64 * 64; e += 256) {
        int i = e >> 6, j = e & 63;
        Dsh[i][j] = g_V[c][ib * 64 + i][ib * 64 + j];
    }
    __syncthreads();
    float acc2[4][4] = {};
#pragma unroll 4
    for (int q = 0; q < 64; q++) {
        float dv[4], tv[4];
#pragma unroll
        for (int p = 0; p < 4; p++) dv[p] = Dsh[4 * ty + p][q];
#pragma unroll
        for (int b = 0; b < 4; b++) tv[b] = Ts[q][4 * tx + b];
#pragma unroll
        for (int p = 0; p < 4; p++)
#pragma unroll
            for (int b = 0; b < 4; b++) acc2[p][b] += dv[p] * tv[b];
    }
#pragma unroll
    for (int p = 0; p < 4; p++)
#pragma unroll
        for (int b = 0; b < 4; b++)
            g_V[c][ib * 64 + 4 * ty + p][jb * 64 + 4 * tx + b] = -acc2[p][b];
}

// ---------------- s_c = V_c mu_c (one warp per row) ----------------
__global__ void k_svec() {
    int c = blockIdx.y;
    int warp = threadIdx.x >> 5, lane = threadIdx.x & 31;
    int row = blockIdx.x * 8 + warp;
    float acc = 0.f;
    for (int k = lane; k <= row; k += 32) acc += g_V[c][row][k] * g_mu[c][k];
    for (int o = 16; o > 0; o >>= 1) acc += __shfl_down_sync(0xffffffffu, acc, o);
    if (lane == 0) g_s[c][row] = acc;
}

// ---------------- per-class scalars: ss = |s|^2, mm = |mu|^2 ----------------
__global__ void k_scalars() {
    int c = blockIdx.x;
    __shared__ float r1[256], r2[256];
    float a = 0.f, b = 0.f;
    for (int k = threadIdx.x; k < D; k += 256) {
        float sv = g_s[c][k];  a += sv * sv;
        float mv = g_mu[c][k]; b += mv * mv;
    }
    r1[threadIdx.x] = a; r2[threadIdx.x] = b;
    __syncthreads();
    for (int o = 128; o > 0; o >>= 1) {
        if (threadIdx.x < o) { r1[threadIdx.x] += r1[threadIdx.x + o]; r2[threadIdx.x] += r2[threadIdx.x + o]; }
        __syncthreads();
    }
    if (threadIdx.x == 0) { g_ssc[c] = r1[0]; g_mmc[c] = r2[0]; }
}

// ---------------- nx[m] = |Xq[m]|^2 ----------------
__global__ void k_nx(const float* __restrict__ Xq) {
    int warp = threadIdx.x >> 5, lane = threadIdx.x & 31;
    int row = blockIdx.x * 8 + warp;
    float acc = 0.f;
    for (int k = lane; k < D; k += 32) { float v = Xq[(size_t)row * D + k]; acc += v * v; }
    for (int o = 16; o > 0; o >>= 1) acc += __shfl_down_sync(0xffffffffu, acc, o);
    if (lane == 0) g_nx[row] = acc;
}

// ---------------- xm[m][c] = Xq[m] . mu[c] ----------------
__global__ void k_xm(const float* __restrict__ Xq) {
    int warp = threadIdx.x >> 5, lane = threadIdx.x & 31;
    int row = blockIdx.x * 8 + warp;
    float acc[CLS];
#pragma unroll
    for (int c = 0; c < CLS; c++) acc[c] = 0.f;
    for (int k = lane; k < D; k += 32) {
        float v = Xq[(size_t)row * D + k];
#pragma unroll
        for (int c = 0; c < CLS; c++) acc[c] += v * g_mu[c][k];
    }
#pragma unroll
    for (int c = 0; c < CLS; c++) {
        float a = acc[c];
        for (int o = 16; o > 0; o >>= 1) a += __shfl_down_sync(0xffffffffu, a, o);
        if (lane == 0) g_xm[row][c] = a;
    }
}

// ---------------- W = Xq V^T (triangular-skip) fused with logits ----------------
__global__ __launch_bounds__(256) void k_logits(const float* __restrict__ Xq, float* __restrict__ out) {
    __shared__ float Xs[16][65];
    __shared__ float Vs[16][65];
    __shared__ float red[64][17];
    int c = blockIdx.y;
    int m0 = blockIdx.x * 64;
    int tid = threadIdx.x, tx = tid & 15, ty = tid >> 4;
    float q2[4] = {}, qb[4] = {};
    for (int jt = 0; jt < NT; jt++) {
        int j0 = jt * 64;
        float w[4][4] = {};
        int kend = j0 + 64;  // V[j,k]=0 for k>j: skip upper tiles
        for (int k0 = 0; k0 < kend; k0 += 16) {
#pragma unroll
            for (int t = 0; t < 4; t++) {
                int idx = tid + 256 * t;
                int ii = idx >> 4, kk = idx & 15;
                Xs[kk][ii] = Xq[(size_t)(m0 + ii) * D + k0 + kk];
                Vs[kk][ii] = g_V[c][j0 + ii][k0 + kk];
            }
            __syncthreads();
#pragma unroll
            for (int kk = 0; kk < 16; kk++) {
                float a[4], b[4];
#pragma unroll
                for (int q = 0; q < 4; q++) a[q] = Xs[kk][4 * ty + q];
#pragma unroll
                for (int q = 0; q < 4; q++) b[q] = Vs[kk][4 * tx + q];
#pragma unroll
                for (int p = 0; p < 4; p++)
#pragma unroll
                    for (int q = 0; q < 4; q++) w[p][q] += a[p] * b[q];
            }
            __syncthreads();
        }
#pragma unroll
        for (int q = 0; q < 4; q++) {
            float sv = g_s[c][j0 + 4 * tx + q];
#pragma unroll
            for (int p = 0; p < 4; p++) {
                q2[p] += w[p][q] * w[p][q];
                qb[p] += w[p][q] * sv;
            }
        }
    }
    // deterministic cross-tx reduction
#pragma unroll
    for (int p = 0; p < 4; p++) red[4 * ty + p][tx] = q2[p];
    __syncthreads();
    float q2row = 0.f;
    if (tid < 64) {
        for (int t = 0; t < 16; t++) q2row += red[tid][t];
    }
    __syncthreads();
#pragma unroll
    for (int p = 0; p < 4; p++) red[4 * ty + p][tx] = qb[p];
    __syncthreads();
    if (tid < 64) {
        float qbrow = 0.f;
        for (int t = 0; t < 16; t++) qbrow += red[tid][t];
        int mrow = m0 + tid;
        float dq = g_nx[mrow] - 2.f * g_xm[mrow][c] + g_mmc[c];
        float qm = q2row - 2.f * qbrow + g_ssc[c];
        out[(size_t)mrow * CLS + c] = -0.9f * qm - 0.1f * dq;
    }
}

// ---------------- launch ----------------
extern "C" void kernel_launch(void* const* d_in, const int* in_sizes, int n_in,
                              void* d_out, int out_size) {
    const float* X     = (const float*)d_in[0];
    const int*   y     = (const int*)d_in[1];
    const float* Xq    = (const float*)d_in[2];
    const float* m     = (const float*)d_in[3];
    const float* kappa = (const float*)d_in[4];
    const float* nu    = (const float*)d_in[5];
    const float* td    = (const float*)d_in[6];
    const float* tl    = (const float*)d_in[7];
    float* out = (float*)d_out;

    k_stats<<<8, 128>>>(X, y);
    k_sort_params<<<1, 32>>>(y, kappa, nu);
    k_mu<<<dim3(4, CLS), 256>>>(m);
    k_buildL<<<D, 256>>>(td, tl);
    k_base<<<dim3(NT, NT), 256>>>(m);
    k_sigma<<<dim3(NT, NT, CLS), 256>>>(X);

    for (int kb = 0; kb < NT; kb++) {
        k_chol_panel<<<CLS, 512>>>(kb);
        int T = NT - 1 - kb;
        if (T > 0) k_chol_trail<<<dim3(T * (T + 1) / 2, CLS), 256>>>(kb);
    }

    k_triinv_diag<<<dim3(NT, CLS), 64>>>();
    for (int lev = 1; lev < NT; lev++)
        k_triinv_off<<<dim3(NT - lev, CLS), 256>>>(lev);

    k_svec<<<dim3(D / 8, CLS), 256>>>();
    k_scalars<<<CLS, 256>>>();
    k_nx<<<MQ / 8, 256>>>(Xq);
    k_xm<<<MQ / 8, 256>>>(Xq);
    k_logits<<<dim3(MQ / 64, CLS), 256>>>(Xq, out);
}

// round 3
// speedup vs baseline: 1.7417x; 1.7417x over previous
#include <cuda_runtime.h>
#include <cuda_bf16.h>
#include <math.h>
#include <stdint.h>

#define D      1024
#define CLS    16
#define NSAMP  4096
#define MQ     4096
#define NT     16   // D / 64

// ---------------- scratch (device globals; no allocations allowed) ----------------
__device__ float g_Sigma[CLS][D][D];   // sigma, then Cholesky factor R (lower) in place
__device__ float g_V[CLS][D][D];       // V = R^{-1} (lower; diag blocks have explicit upper zeros)
__device__ float g_Base[D][D];
__device__ float g_L[D][D];
__device__ float g_part[8][CLS][D];
__device__ float g_sums[CLS][D];
__device__ float g_mu[CLS][D];
__device__ float g_s[CLS][D];
__device__ float g_nx[MQ];
__device__ float g_xm[MQ][CLS];
__device__ float g_ssc[CLS];
__device__ float g_mmc[CLS];
__device__ int   g_cnt[CLS];
__device__ int   g_cntp[8][CLS];
__device__ int   g_start[CLS];
__device__ int   g_idx[NSAMP];
__device__ float g_kap;
__device__ float g_coef[CLS];      // kap + Nj
__device__ float g_invscale[CLS];  // 1/(nu_ + Nj + d + 2)

// bf16 split-precision operands for the tensor-core query GEMM
__device__ __nv_bfloat16 g_Xqh[MQ][D];
__device__ __nv_bfloat16 g_Xql[MQ][D];
__device__ __nv_bfloat16 g_Vh[CLS][D][D];
__device__ __nv_bfloat16 g_Vl[CLS][D][D];

// ================= warp-mma helpers (base-target PTX: ldmatrix + mma.sync) =======
__device__ __forceinline__ uint32_t smem_u32(const void* p) {
    uint32_t a;
    asm("{ .reg .u64 t; cvta.to.shared.u64 t, %1; cvt.u32.u64 %0, t; }" : "=r"(a) : "l"(p));
    return a;
}
__device__ __forceinline__ void ldsm4(uint32_t* r, uint32_t a) {
    asm volatile("ldmatrix.sync.aligned.m8n8.x4.shared.b16 {%0,%1,%2,%3}, [%4];"
                 : "=r"(r[0]), "=r"(r[1]), "=r"(r[2]), "=r"(r[3]) : "r"(a));
}
__device__ __forceinline__ void mma16816(float* d, const uint32_t* a, const uint32_t* b) {
    asm volatile(
        "mma.sync.aligned.m16n8k16.row.col.f32.bf16.bf16.f32 "
        "{%0,%1,%2,%3}, {%4,%5,%6,%7}, {%8,%9}, {%0,%1,%2,%3};"
        : "+f"(d[0]), "+f"(d[1]), "+f"(d[2]), "+f"(d[3])
        : "r"(a[0]), "r"(a[1]), "r"(a[2]), "r"(a[3]), "r"(b[0]), "r"(b[1]));
}

// ---------------- per-class partial sums + counts (deterministic) ----------------
__global__ void k_stats1(const float* __restrict__ X, const int* __restrict__ y) {
    __shared__ int sy[512];
    int tid = threadIdx.x;
    int r0 = blockIdx.y * 512;
    for (int n = tid; n < 512; n += 128) sy[n] = y[r0 + n];
    __syncthreads();
    int k = blockIdx.x * 128 + tid;
    float acc[CLS];
#pragma unroll
    for (int c = 0; c < CLS; c++) acc[c] = 0.f;
    for (int n = 0; n < 512; n++) {
        float v = X[(size_t)(r0 + n) * D + k];
        int cls = sy[n];
#pragma unroll
        for (int c = 0; c < CLS; c++) acc[c] += (cls == c) ? v : 0.f;
    }
#pragma unroll
    for (int c = 0; c < CLS; c++) g_part[blockIdx.y][c][k] = acc[c];
    if (blockIdx.x == 0) {
        __shared__ int scnt[CLS];
        if (tid < CLS) scnt[tid] = 0;
        __syncthreads();
        for (int n = tid; n < 512; n += 128) atomicAdd(&scnt[sy[n]], 1);
        __syncthreads();
        if (tid < CLS) g_cntp[blockIdx.y][tid] = scnt[tid];
    }
}

__global__ void k_stats2() {
    int idx = blockIdx.x * 256 + threadIdx.x;  // 64 blocks -> 16384
    int c = idx >> 10, k = idx & 1023;
    float s = 0.f;
#pragma unroll
    for (int r = 0; r < 8; r++) s += g_part[r][c][k];
    g_sums[c][k] = s;
}

// ---------------- counting sort (warp-ballot) + scalar params ----------------
__global__ void k_sort_params(const int* __restrict__ y, const float* __restrict__ kappa,
                              const float* __restrict__ nu) {
    __shared__ int s_start[CLS];
    int lane = threadIdx.x;
    if (lane == 0) {
        int s = 0;
        for (int c = 0; c < CLS; c++) {
            int t = 0;
            for (int r = 0; r < 8; r++) t += g_cntp[r][c];
            g_cnt[c] = t; g_start[c] = s; s_start[c] = s; s += t;
        }
        float kap = fabsf(kappa[0]) + 1e-6f;
        g_kap = kap;
        float nu_ = fmaxf(nu[0], (float)(D - 1) + 1e-6f);
        for (int c = 0; c < CLS; c++) {
            float Nj = (float)g_cnt[c];
            g_coef[c] = kap + Nj;
            g_invscale[c] = 1.0f / (nu_ + Nj + (float)D + 2.0f);
        }
    }
    __syncthreads();
    int off[CLS];
#pragma unroll
    for (int c = 0; c < CLS; c++) off[c] = s_start[c];
    unsigned below = (1u << lane) - 1u;
    for (int n0 = 0; n0 < NSAMP; n0 += 32) {
        int v = y[n0 + lane];
#pragma unroll
        for (int c = 0; c < CLS; c++) {
            unsigned m = __ballot_sync(0xffffffffu, v == c);
            if (v == c) g_idx[off[c] + __popc(m & below)] = n0 + lane;
            off[c] += __popc(m);
        }
    }
}

// ---------------- mu[c] = (kap*m + sums[c]) / (kap+Nj) ----------------
__global__ void k_mu(const float* __restrict__ m) {
    int c = blockIdx.y;
    int k = blockIdx.x * blockDim.x + threadIdx.x;
    g_mu[c][k] = (g_kap * m[k] + g_sums[c][k]) / g_coef[c];
}

// ---------------- build L = diag(|td|) + strict lower of tl ----------------
__global__ void k_buildL(const float* __restrict__ td, const float* __restrict__ tl) {
    int i = blockIdx.x;
    for (int k = threadIdx.x; k < D; k += blockDim.x) {
        float v;
        if (k < i) v = tl[(size_t)i * D + k];
        else if (k == i) v = fabsf(td[i]);
        else v = 0.f;
        g_L[i][k] = v;
    }
}

// ---------------- Base = L L^T + kap m m^T ----------------
__global__ __launch_bounds__(256) void k_base(const float* __restrict__ m) {
    __shared__ float As[16][65];
    __shared__ float Bs[16][65];
    int i0 = blockIdx.x * 64, j0 = blockIdx.y * 64;
    int tid = threadIdx.x, tx = tid & 15, ty = tid >> 4;
    float acc[4][4] = {};
    for (int k0 = 0; k0 < D; k0 += 16) {
#pragma unroll
        for (int t = 0; t < 4; t++) {
            int idx = tid + 256 * t;
            int ii = idx >> 4, kk = idx & 15;
            As[kk][ii] = g_L[i0 + ii][k0 + kk];
            Bs[kk][ii] = g_L[j0 + ii][k0 + kk];
        }
        __syncthreads();
#pragma unroll
        for (int kk = 0; kk < 16; kk++) {
            float a[4], b[4];
#pragma unroll
            for (int q = 0; q < 4; q++) a[q] = As[kk][4 * ty + q];
#pragma unroll
            for (int q = 0; q < 4; q++) b[q] = Bs[kk][4 * tx + q];
#pragma unroll
            for (int p = 0; p < 4; p++)
#pragma unroll
                for (int q = 0; q < 4; q++) acc[p][q] += a[p] * b[q];
        }
        __syncthreads();
    }
    float kap = g_kap;
#pragma unroll
    for (int p = 0; p < 4; p++) {
        int i = i0 + 4 * ty + p;
        float mi = m[i];
#pragma unroll
        for (int q = 0; q < 4; q++) {
            int j = j0 + 4 * tx + q;
            g_Base[i][j] = acc[p][q] + kap * mi * m[j];
        }
    }
}

// ---------------- Sigma[c] = (Base + S_c - coef*mu mu^T) * invscale (fp32) --------
__global__ __launch_bounds__(256) void k_sigma(const float* __restrict__ X) {
    __shared__ float As[16][64];
    __shared__ float Bs[16][64];
    int c = blockIdx.z;
    int i0 = blockIdx.x * 64, j0 = blockIdx.y * 64;
    int tid = threadIdx.x, tx = tid & 15, ty = tid >> 4;
    int cnt = g_cnt[c], start = g_start[c];
    float acc[4][4] = {};
    for (int r0 = 0; r0 < cnt; r0 += 16) {
#pragma unroll
        for (int t = 0; t < 4; t++) {
            int idx = tid + 256 * t;
            int kk = idx >> 6, ii = idx & 63;
            int rg = r0 + kk;
            int row = (rg < cnt) ? g_idx[start + rg] : -1;
            As[kk][ii] = (row >= 0) ? X[(size_t)row * D + i0 + ii] : 0.f;
            Bs[kk][ii] = (row >= 0) ? X[(size_t)row * D + j0 + ii] : 0.f;
        }
        __syncthreads();
#pragma unroll
        for (int kk = 0; kk < 16; kk++) {
            float a[4], b[4];
#pragma unroll
            for (int q = 0; q < 4; q++) a[q] = As[kk][4 * ty + q];
#pragma unroll
            for (int q = 0; q < 4; q++) b[q] = Bs[kk][4 * tx + q];
#pragma unroll
            for (int p = 0; p < 4; p++)
#pragma unroll
                for (int q = 0; q < 4; q++) acc[p][q] += a[p] * b[q];
        }
        __syncthreads();
    }
    float coef = g_coef[c], inv = g_invscale[c];
#pragma unroll
    for (int p = 0; p < 4; p++) {
        int i = i0 + 4 * ty + p;
        float mui = g_mu[c][i];
#pragma unroll
        for (int q = 0; q < 4; q++) {
            int j = j0 + 4 * tx + q;
            g_Sigma[c][i][j] = (g_Base[i][j] + acc[p][q] - coef * mui * g_mu[c][j]) * inv;
        }
    }
}

// ---------------- blocked Cholesky: factor diag block + panel solve ----------------
__global__ __launch_bounds__(512) void k_chol_panel(int kb) {
    __shared__ float Ds[64][65];
    int c = blockIdx.x;
    int tid = threadIdx.x;
    int base = kb * 64;
    for (int e = tid; e < 64 * 64; e += 512) {
        int i = e >> 6, j = e & 63;
        Ds[i][j] = g_Sigma[c][base + i][base + j];
    }
    __syncthreads();
    for (int j = 0; j < 64; j++) {
        if (tid == 0) Ds[j][j] = sqrtf(Ds[j][j]);
        __syncthreads();
        if (tid > j && tid < 64) Ds[tid][j] /= Ds[j][j];
        __syncthreads();
        for (int e = tid; e < 64 * 64; e += 512) {
            int i = e >> 6, kc = e & 63;
            if (i > j && kc > j && kc <= i) Ds[i][kc] -= Ds[i][j] * Ds[kc][j];
        }
        __syncthreads();
    }
    for (int e = tid; e < 64 * 64; e += 512) {
        int i = e >> 6, j = e & 63;
        if (j <= i) g_Sigma[c][base + i][base + j] = Ds[i][j];
    }
    __syncthreads();
    int nrows = D - base - 64;
    for (int rr = tid; rr < nrows; rr += 512) {
        int row = base + 64 + rr;
        float a[64];
#pragma unroll
        for (int k = 0; k < 64; k++) a[k] = g_Sigma[c][row][base + k];
#pragma unroll
        for (int j = 0; j < 64; j++) {
            float t = a[j];
#pragma unroll
            for (int k = 0; k < j; k++) t -= a[k] * Ds[j][k];
            a[j] = t / Ds[j][j];
        }
#pragma unroll
        for (int k = 0; k < 64; k++) g_Sigma[c][row][base + k] = a[k];
    }
}

// ---------------- trailing syrk update: A[ti,tj] -= P_ti P_tj^T ----------------
__global__ __launch_bounds__(256) void k_chol_trail(int kb) {
    int c = blockIdx.y;
    int pidx = blockIdx.x;
    int ti = kb + 1;
    while (pidx >= ti - kb) { pidx -= ti - kb; ti++; }
    int tj = kb + 1 + pidx;
    __shared__ float As[16][65], Bs[16][65];
    int tid = threadIdx.x, tx = tid & 15, ty = tid >> 4;
    int i0 = ti * 64, j0 = tj * 64, kbase = kb * 64;
    float acc[4][4] = {};
    for (int k0 = 0; k0 < 64; k0 += 16) {
#pragma unroll
        for (int t = 0; t < 4; t++) {
            int idx = tid + 256 * t;
            int ii = idx >> 4, kk = idx & 15;
            As[kk][ii] = g_Sigma[c][i0 + ii][kbase + k0 + kk];
            Bs[kk][ii] = g_Sigma[c][j0 + ii][kbase + k0 + kk];
        }
        __syncthreads();
#pragma unroll
        for (int kk = 0; kk < 16; kk++) {
            float a[4], b[4];
#pragma unroll
            for (int q = 0; q < 4; q++) a[q] = As[kk][4 * ty + q];
#pragma unroll
            for (int q = 0; q < 4; q++) b[q] = Bs[kk][4 * tx + q];
#pragma unroll
            for (int p = 0; p < 4; p++)
#pragma unroll
                for (int q = 0; q < 4; q++) acc[p][q] += a[p] * b[q];
        }
        __syncthreads();
    }
#pragma unroll
    for (int p = 0; p < 4; p++)
#pragma unroll
        for (int q = 0; q < 4; q++)
            g_Sigma[c][i0 + 4 * ty + p][j0 + 4 * tx + q] -= acc[p][q];
}

// ---------------- invert 64x64 diagonal blocks of R -> V diag ----------------
__global__ __launch_bounds__(64) void k_triinv_diag() {
    __shared__ float Ds[64][65];
    int t = blockIdx.x, c = blockIdx.y;
    int tid = threadIdx.x;
    int base = t * 64;
    for (int e = tid; e < 64 * 64; e += 64) {
        int i = e >> 6, j = e & 63;
        Ds[i][j] = (j <= i) ? g_Sigma[c][base + i][base + j] : 0.f;
    }
    __syncthreads();
    int j = tid;
    float x[64];
#pragma unroll
    for (int i = 0; i < 64; i++) {
        float tval = (i == j) ? 1.0f : 0.0f;
#pragma unroll
        for (int k = 0; k < i; k++) tval -= Ds[i][k] * x[k];
        x[i] = tval / Ds[i][i];
    }
#pragma unroll
    for (int i = 0; i < 64; i++) g_V[c][base + i][base + j] = x[i];
}

// ---------------- off-diagonal V blocks, level by level ----------------
__global__ __launch_bounds__(256) void k_triinv_off(int lev) {
    __shared__ float Ash[64][17];
    __shared__ float Bsh[16][65];
    __shared__ float Ts[64][65];
    __shared__ float Dsh[64][65];
    int c = blockIdx.y;
    int jb = blockIdx.x;
    int ib = jb + lev;
    int tid = threadIdx.x, tx = tid & 15, ty = tid >> 4;
    float acc[4][4] = {};
    int kr0 = jb * 64, kr1 = ib * 64;
    for (int k0 = kr0; k0 < kr1; k0 += 16) {
#pragma unroll
        for (int t = 0; t < 4; t++) {
            int idx = tid + 256 * t;
            {
                int ii = idx >> 4, kk = idx & 15;
                Ash[ii][kk] = g_Sigma[c][ib * 64 + ii][k0 + kk];
            }
            {
                int kk = idx >> 6, jj = idx & 63;
                Bsh[kk][jj] = g_V[c][k0 + kk][jb * 64 + jj];
            }
        }
        __syncthreads();
#pragma unroll
        for (int kk = 0; kk < 16; kk++) {
            float a[4], b[4];
#pragma unroll
            for (int q = 0; q < 4; q++) a[q] = Ash[4 * ty + q][kk];
#pragma unroll
            for (int q = 0; q < 4; q++) b[q] = Bsh[kk][4 * tx + q];
#pragma unroll
            for (int p = 0; p < 4; p++)
#pragma unroll
                for (int q = 0; q < 4; q++) acc[p][q] += a[p] * b[q];
        }
        __syncthreads();
    }
#pragma unroll
    for (int p = 0; p < 4; p++)
#pragma unroll
        for (int q = 0; q < 4; q++) Ts[4 * ty + p][4 * tx + q] = acc[p][q];
    for (int e = tid; e < 64 * 64; e += 256) {
        int i = e >> 6, j = e & 63;
        Dsh[i][j] = g_V[c][ib * 64 + i][ib * 64 + j];
    }
    __syncthreads();
    float acc2[4][4] = {};
#pragma unroll 4
    for (int q = 0; q < 64; q++) {
        float dv[4], tv[4];
#pragma unroll
        for (int p = 0; p < 4; p++) dv[p] = Dsh[4 * ty + p][q];
#pragma unroll
        for (int b = 0; b < 4; b++) tv[b] = Ts[q][4 * tx + b];
#pragma unroll
        for (int p = 0; p < 4; p++)
#pragma unroll
            for (int b = 0; b < 4; b++) acc2[p][b] += dv[p] * tv[b];
    }
#pragma unroll
    for (int p = 0; p < 4; p++)
#pragma unroll
        for (int b = 0; b < 4; b++)
            g_V[c][ib * 64 + 4 * ty + p][jb * 64 + 4 * tx + b] = -acc2[p][b];
}

// ---------------- bf16 hi/lo conversions ----------------
__global__ void k_cvt_xq(const float* __restrict__ Xq) {
    int i = blockIdx.x * 256 + threadIdx.x;  // 16384 blocks
    float x = Xq[i];
    __nv_bfloat16 h = __float2bfloat16(x);
    ((__nv_bfloat16*)g_Xqh)[i] = h;
    ((__nv_bfloat16*)g_Xql)[i] = __float2bfloat16(x - __bfloat162float(h));
}
__global__ void k_cvt_v() {
    size_t i = (size_t)blockIdx.x * 256 + threadIdx.x;  // 65536 blocks
    float x = ((const float*)g_V)[i];
    __nv_bfloat16 h = __float2bfloat16(x);
    ((__nv_bfloat16*)g_Vh)[i] = h;
    ((__nv_bfloat16*)g_Vl)[i] = __float2bfloat16(x - __bfloat162float(h));
}

// ---------------- s_c = V_c mu_c ----------------
__global__ void k_svec() {
    int c = blockIdx.y;
    int warp = threadIdx.x >> 5, lane = threadIdx.x & 31;
    int row = blockIdx.x * 8 + warp;
    float acc = 0.f;
    for (int k = lane; k <= row; k += 32) acc += g_V[c][row][k] * g_mu[c][k];
    for (int o = 16; o > 0; o >>= 1) acc += __shfl_down_sync(0xffffffffu, acc, o);
    if (lane == 0) g_s[c][row] = acc;
}

// ---------------- per-class scalars ----------------
__global__ void k_scalars() {
    int c = blockIdx.x;
    __shared__ float r1[256], r2[256];
    float a = 0.f, b = 0.f;
    for (int k = threadIdx.x; k < D; k += 256) {
        float sv = g_s[c][k];  a += sv * sv;
        float mv = g_mu[c][k]; b += mv * mv;
    }
    r1[threadIdx.x] = a; r2[threadIdx.x] = b;
    __syncthreads();
    for (int o = 128; o > 0; o >>= 1) {
        if (threadIdx.x < o) { r1[threadIdx.x] += r1[threadIdx.x + o]; r2[threadIdx.x] += r2[threadIdx.x + o]; }
        __syncthreads();
    }
    if (threadIdx.x == 0) { g_ssc[c] = r1[0]; g_mmc[c] = r2[0]; }
}

// ---------------- nx[m] = |Xq[m]|^2 ----------------
__global__ void k_nx(const float* __restrict__ Xq) {
    int warp = threadIdx.x >> 5, lane = threadIdx.x & 31;
    int row = blockIdx.x * 8 + warp;
    float acc = 0.f;
    for (int k = lane; k < D; k += 32) { float v = Xq[(size_t)row * D + k]; acc += v * v; }
    for (int o = 16; o > 0; o >>= 1) acc += __shfl_down_sync(0xffffffffu, acc, o);
    if (lane == 0) g_nx[row] = acc;
}

// ---------------- xm[m][c] = Xq[m] . mu[c] ----------------
__global__ void k_xm(const float* __restrict__ Xq) {
    int warp = threadIdx.x >> 5, lane = threadIdx.x & 31;
    int row = blockIdx.x * 8 + warp;
    float acc[CLS];
#pragma unroll
    for (int c = 0; c < CLS; c++) acc[c] = 0.f;
    for (int k = lane; k < D; k += 32) {
        float v = Xq[(size_t)row * D + k];
#pragma unroll
        for (int c = 0; c < CLS; c++) acc[c] += v * g_mu[c][k];
    }
#pragma unroll
    for (int c = 0; c < CLS; c++) {
        float a = acc[c];
        for (int o = 16; o > 0; o >>= 1) a += __shfl_down_sync(0xffffffffu, a, o);
        if (lane == 0) g_xm[row][c] = a;
    }
}

// ================= warp-mma logits: W = Xq V^T (bf16 split, triangular skip) ======
// Dynamic smem layout (bytes):
//   Ah [128 rows][72 bf16]  @0      (18432)
//   Al                      @18432  (18432)
//   Bh [64 rows][72 bf16]   @36864  (9216)
//   Bl                      @46080  (9216)   total 55296
// After the mainloop, bytes [0,8192) are reused as the q2/qb reduction buffer.
#define LG_ROWB 144            // 72 bf16 row stride in bytes
#define LG_SMEM 55296

__global__ __launch_bounds__(256) void k_logits_mma(float* __restrict__ out) {
    extern __shared__ char smem[];
    char* sAh = smem;
    char* sAl = smem + 18432;
    char* sBh = smem + 36864;
    char* sBl = smem + 46080;

    int tid = threadIdx.x, lane = tid & 31, wid = tid >> 5;
    int wm = wid >> 1, wn = wid & 1;
    int c = blockIdx.y, m0 = blockIdx.x * 128;

    // ldmatrix lane base addresses (bytes)
    uint32_t aH = smem_u32(sAh) + (uint32_t)((wm * 32 + (lane & 15)) * LG_ROWB + (lane >> 4) * 16);
    uint32_t aL = aH + 18432;
    uint32_t bH = smem_u32(sBh) + (uint32_t)((wn * 32 + ((lane & 16) >> 1) + (lane & 7)) * LG_ROWB
                                             + ((lane & 8) ? 16 : 0));
    uint32_t bL = bH + 9216;

    float q2[2][2] = {}, qb[2][2] = {};

    for (int jt = 0; jt < NT; jt++) {
        float acc[2][4][4];
#pragma unroll
        for (int ms = 0; ms < 2; ms++)
#pragma unroll
            for (int nt = 0; nt < 4; nt++)
#pragma unroll
                for (int q = 0; q < 4; q++) acc[ms][nt][q] = 0.f;

        for (int kt = 0; kt <= jt; kt++) {
            __syncthreads();
            // A tiles: 128x64 hi & lo
#pragma unroll
            for (int i = 0; i < 4; i++) {
                int idx = tid + 256 * i;
                int r = idx >> 3, c8 = idx & 7;
                int so = r * LG_ROWB + c8 * 16;
                const uint4* srcH = (const uint4*)&g_Xqh[m0 + r][kt * 64 + c8 * 8];
                const uint4* srcL = (const uint4*)&g_Xql[m0 + r][kt * 64 + c8 * 8];
                *(uint4*)(sAh + so) = *srcH;
                *(uint4*)(sAl + so) = *srcL;
            }
            // B tiles: 64x64 hi & lo
#pragma unroll
            for (int i = 0; i < 2; i++) {
                int idx = tid + 256 * i;
                int r = idx >> 3, c8 = idx & 7;
                int so = r * LG_ROWB + c8 * 16;
                *(uint4*)(sBh + so) = *(const uint4*)&g_Vh[c][jt * 64 + r][kt * 64 + c8 * 8];
                *(uint4*)(sBl + so) = *(const uint4*)&g_Vl[c][jt * 64 + r][kt * 64 + c8 * 8];
            }
            __syncthreads();

#pragma unroll
            for (int ks = 0; ks < 4; ks++) {
                uint32_t ah[2][4], al[2][4], bh[8], bl[8];
                ldsm4(ah[0], aH + ks * 32);
                ldsm4(ah[1], aH + 16 * LG_ROWB + ks * 32);
                ldsm4(al[0], aL + ks * 32);
                ldsm4(al[1], aL + 16 * LG_ROWB + ks * 32);
                ldsm4(&bh[0], bH + ks * 32);
                ldsm4(&bh[4], bH + 16 * LG_ROWB + ks * 32);
                ldsm4(&bl[0], bL + ks * 32);
                ldsm4(&bl[4], bL + 16 * LG_ROWB + ks * 32);
#pragma unroll
                for (int ms = 0; ms < 2; ms++)
#pragma unroll
                    for (int nt = 0; nt < 4; nt++) {
                        float* d = acc[ms][nt];
                        mma16816(d, ah[ms], &bh[nt * 2]);
                        mma16816(d, al[ms], &bh[nt * 2]);
                        mma16816(d, ah[ms], &bl[nt * 2]);
                    }
            }
        }
        // fold this jt's W tile into q2/qb (deterministic, per-thread)
#pragma unroll
        for (int ms = 0; ms < 2; ms++)
#pragma unroll
            for (int nt = 0; nt < 4; nt++) {
                int jc = jt * 64 + wn * 32 + nt * 8 + 2 * (lane & 3);
                float s0 = g_s[c][jc], s1 = g_s[c][jc + 1];
                float* d = acc[ms][nt];
                q2[ms][0] += d[0] * d[0] + d[1] * d[1];
                qb[ms][0] += d[0] * s0 + d[1] * s1;
                q2[ms][1] += d[2] * d[2] + d[3] * d[3];
                qb[ms][1] += d[2] * s0 + d[3] * s1;
            }
    }

    // cross-thread per-row reduction (8 deterministic slots per row)
    __syncthreads();
    float* rq = (float*)smem;            // [128][8]
    float* rb = (float*)(smem + 4096);   // [128][8]
    int slot = wn * 4 + (lane & 3);
    int g = lane >> 2;
#pragma unroll
    for (int ms = 0; ms < 2; ms++)
#pragma unroll
        for (int go = 0; go < 2; go++) {
            int row = wm * 32 + ms * 16 + go * 8 + g;
            rq[row * 8 + slot] = q2[ms][go];
            rb[row * 8 + slot] = qb[ms][go];
        }
    __syncthreads();
    if (tid < 128) {
        float q2r = 0.f, qbr = 0.f;
#pragma unroll
        for (int t = 0; t < 8; t++) { q2r += rq[tid * 8 + t]; qbr += rb[tid * 8 + t]; }
        int row = m0 + tid;
        float dq = g_nx[row] - 2.f * g_xm[row][c] + g_mmc[c];
        float qm = q2r - 2.f * qbr + g_ssc[c];
        out[(size_t)row * CLS + c] = -0.9f * qm - 0.1f * dq;
    }
}

// ---------------- launch ----------------
extern "C" void kernel_launch(void* const* d_in, const int* in_sizes, int n_in,
                              void* d_out, int out_size) {
    const float* X     = (const float*)d_in[0];
    const int*   y     = (const int*)d_in[1];
    const float* Xq    = (const float*)d_in[2];
    const float* m     = (const float*)d_in[3];
    const float* kappa = (const float*)d_in[4];
    const float* nu    = (const float*)d_in[5];
    const float* td    = (const float*)d_in[6];
    const float* tl    = (const float*)d_in[7];
    float* out = (float*)d_out;

    cudaFuncSetAttribute(k_logits_mma, cudaFuncAttributeMaxDynamicSharedMemorySize, LG_SMEM);

    k_stats1<<<dim3(8, 8), 128>>>(X, y);
    k_sort_params<<<1, 32>>>(y, kappa, nu);
    k_stats2<<<64, 256>>>();
    k_mu<<<dim3(4, CLS), 256>>>(m);
    k_cvt_xq<<<16384, 256>>>(Xq);
    k_buildL<<<D, 256>>>(td, tl);
    k_base<<<dim3(NT, NT), 256>>>(m);
    k_sigma<<<dim3(NT, NT, CLS), 256>>>(X);

    for (int kb = 0; kb < NT; kb++) {
        k_chol_panel<<<CLS, 512>>>(kb);
        int T = NT - 1 - kb;
        if (T > 0) k_chol_trail<<<dim3(T * (T + 1) / 2, CLS), 256>>>(kb);
    }

    k_triinv_diag<<<dim3(NT, CLS), 64>>>();
    for (int lev = 1; lev < NT; lev++)
        k_triinv_off<<<dim3(NT - lev, CLS), 256>>>(lev);

    k_cvt_v<<<65536, 256>>>();
    k_svec<<<dim3(D / 8, CLS), 256>>>();
    k_scalars<<<CLS, 256>>>();
    k_nx<<<MQ / 8, 256>>>(Xq);
    k_xm<<<MQ / 8, 256>>>(Xq);
    k_logits_mma<<<dim3(MQ / 128, CLS), 256, LG_SMEM>>>(out);
}

// round 4
// speedup vs baseline: 1.7572x; 1.0089x over previous
#include <cuda_runtime.h>
#include <cuda_bf16.h>
#include <math.h>
#include <stdint.h>

#define D      1024
#define CLS    16
#define NSAMP  4096
#define MQ     4096
#define NT     16   // D / 64

// ---------------- scratch (device globals; no allocations allowed) ----------------
__device__ float g_Sigma[CLS][D][D];   // sigma, then Cholesky factor R (lower) in place
__device__ float g_V[CLS][D][D];       // V = R^{-1} (lower; diag blocks have explicit upper zeros)
__device__ float g_Base[D][D];
__device__ float g_L[D][D];
__device__ float g_part[8][CLS][D];
__device__ float g_sums[CLS][D];
__device__ float g_mu[CLS][D];
__device__ float g_s[CLS][D];
__device__ float g_nx[MQ];
__device__ float g_xm[MQ][CLS];
__device__ float g_ssc[CLS];
__device__ float g_mmc[CLS];
__device__ int   g_cnt[CLS];
__device__ int   g_cntp[8][CLS];
__device__ int   g_start[CLS];
__device__ int   g_idx[NSAMP];
__device__ float g_kap;
__device__ float g_coef[CLS];      // kap + Nj
__device__ float g_invscale[CLS];  // 1/(nu_ + Nj + d + 2)

// bf16 split-precision operands for the tensor-core query GEMM
__device__ __nv_bfloat16 g_Xqh[MQ][D];
__device__ __nv_bfloat16 g_Xql[MQ][D];
__device__ __nv_bfloat16 g_Vh[CLS][D][D];
__device__ __nv_bfloat16 g_Vl[CLS][D][D];

// ================= warp-mma helpers (base-target PTX: ldmatrix + mma.sync) =======
__device__ __forceinline__ uint32_t smem_u32(const void* p) {
    uint32_t a;
    asm("{ .reg .u64 t; cvta.to.shared.u64 t, %1; cvt.u32.u64 %0, t; }" : "=r"(a) : "l"(p));
    return a;
}
__device__ __forceinline__ void ldsm4(uint32_t* r, uint32_t a) {
    asm volatile("ldmatrix.sync.aligned.m8n8.x4.shared.b16 {%0,%1,%2,%3}, [%4];"
                 : "=r"(r[0]), "=r"(r[1]), "=r"(r[2]), "=r"(r[3]) : "r"(a));
}
__device__ __forceinline__ void mma16816(float* d, const uint32_t* a, const uint32_t* b) {
    asm volatile(
        "mma.sync.aligned.m16n8k16.row.col.f32.bf16.bf16.f32 "
        "{%0,%1,%2,%3}, {%4,%5,%6,%7}, {%8,%9}, {%0,%1,%2,%3};"
        : "+f"(d[0]), "+f"(d[1]), "+f"(d[2]), "+f"(d[3])
        : "r"(a[0]), "r"(a[1]), "r"(a[2]), "r"(a[3]), "r"(b[0]), "r"(b[1]));
}

// ---------------- per-class partial sums + counts (deterministic) ----------------
__global__ void k_stats1(const float* __restrict__ X, const int* __restrict__ y) {
    __shared__ int sy[512];
    int tid = threadIdx.x;
    int r0 = blockIdx.y * 512;
    for (int n = tid; n < 512; n += 128) sy[n] = y[r0 + n];
    __syncthreads();
    int k = blockIdx.x * 128 + tid;
    float acc[CLS];
#pragma unroll
    for (int c = 0; c < CLS; c++) acc[c] = 0.f;
    for (int n = 0; n < 512; n++) {
        float v = X[(size_t)(r0 + n) * D + k];
        int cls = sy[n];
#pragma unroll
        for (int c = 0; c < CLS; c++) acc[c] += (cls == c) ? v : 0.f;
    }
#pragma unroll
    for (int c = 0; c < CLS; c++) g_part[blockIdx.y][c][k] = acc[c];
    if (blockIdx.x == 0) {
        __shared__ int scnt[CLS];
        if (tid < CLS) scnt[tid] = 0;
        __syncthreads();
        for (int n = tid; n < 512; n += 128) atomicAdd(&scnt[sy[n]], 1);
        __syncthreads();
        if (tid < CLS) g_cntp[blockIdx.y][tid] = scnt[tid];
    }
}

__global__ void k_stats2() {
    int idx = blockIdx.x * 256 + threadIdx.x;  // 64 blocks -> 16384
    int c = idx >> 10, k = idx & 1023;
    float s = 0.f;
#pragma unroll
    for (int r = 0; r < 8; r++) s += g_part[r][c][k];
    g_sums[c][k] = s;
}

// ---------------- counting sort (warp-ballot) + scalar params ----------------
__global__ void k_sort_params(const int* __restrict__ y, const float* __restrict__ kappa,
                              const float* __restrict__ nu) {
    __shared__ int s_start[CLS];
    int lane = threadIdx.x;
    if (lane == 0) {
        int s = 0;
        for (int c = 0; c < CLS; c++) {
            int t = 0;
            for (int r = 0; r < 8; r++) t += g_cntp[r][c];
            g_cnt[c] = t; g_start[c] = s; s_start[c] = s; s += t;
        }
        float kap = fabsf(kappa[0]) + 1e-6f;
        g_kap = kap;
        float nu_ = fmaxf(nu[0], (float)(D - 1) + 1e-6f);
        for (int c = 0; c < CLS; c++) {
            float Nj = (float)g_cnt[c];
            g_coef[c] = kap + Nj;
            g_invscale[c] = 1.0f / (nu_ + Nj + (float)D + 2.0f);
        }
    }
    __syncthreads();
    int off[CLS];
#pragma unroll
    for (int c = 0; c < CLS; c++) off[c] = s_start[c];
    unsigned below = (1u << lane) - 1u;
    for (int n0 = 0; n0 < NSAMP; n0 += 32) {
        int v = y[n0 + lane];
#pragma unroll
        for (int c = 0; c < CLS; c++) {
            unsigned m = __ballot_sync(0xffffffffu, v == c);
            if (v == c) g_idx[off[c] + __popc(m & below)] = n0 + lane;
            off[c] += __popc(m);
        }
    }
}

// ---------------- mu[c] = (kap*m + sums[c]) / (kap+Nj) ----------------
__global__ void k_mu(const float* __restrict__ m) {
    int c = blockIdx.y;
    int k = blockIdx.x * blockDim.x + threadIdx.x;
    g_mu[c][k] = (g_kap * m[k] + g_sums[c][k]) / g_coef[c];
}

// ---------------- build L = diag(|td|) + strict lower of tl ----------------
__global__ void k_buildL(const float* __restrict__ td, const float* __restrict__ tl) {
    int i = blockIdx.x;
    for (int k = threadIdx.x; k < D; k += blockDim.x) {
        float v;
        if (k < i) v = tl[(size_t)i * D + k];
        else if (k == i) v = fabsf(td[i]);
        else v = 0.f;
        g_L[i][k] = v;
    }
}

// ---------------- Base = L L^T + kap m m^T ----------------
__global__ __launch_bounds__(256) void k_base(const float* __restrict__ m) {
    __shared__ float As[16][65];
    __shared__ float Bs[16][65];
    int i0 = blockIdx.x * 64, j0 = blockIdx.y * 64;
    int tid = threadIdx.x, tx = tid & 15, ty = tid >> 4;
    float acc[4][4] = {};
    for (int k0 = 0; k0 < D; k0 += 16) {
#pragma unroll
        for (int t = 0; t < 4; t++) {
            int idx = tid + 256 * t;
            int ii = idx >> 4, kk = idx & 15;
            As[kk][ii] = g_L[i0 + ii][k0 + kk];
            Bs[kk][ii] = g_L[j0 + ii][k0 + kk];
        }
        __syncthreads();
#pragma unroll
        for (int kk = 0; kk < 16; kk++) {
            float a[4], b[4];
#pragma unroll
            for (int q = 0; q < 4; q++) a[q] = As[kk][4 * ty + q];
#pragma unroll
            for (int q = 0; q < 4; q++) b[q] = Bs[kk][4 * tx + q];
#pragma unroll
            for (int p = 0; p < 4; p++)
#pragma unroll
                for (int q = 0; q < 4; q++) acc[p][q] += a[p] * b[q];
        }
        __syncthreads();
    }
    float kap = g_kap;
#pragma unroll
    for (int p = 0; p < 4; p++) {
        int i = i0 + 4 * ty + p;
        float mi = m[i];
#pragma unroll
        for (int q = 0; q < 4; q++) {
            int j = j0 + 4 * tx + q;
            g_Base[i][j] = acc[p][q] + kap * mi * m[j];
        }
    }
}

// ---------------- Sigma[c] = (Base + S_c - coef*mu mu^T) * invscale (fp32) --------
__global__ __launch_bounds__(256) void k_sigma(const float* __restrict__ X) {
    __shared__ float As[16][64];
    __shared__ float Bs[16][64];
    int c = blockIdx.z;
    int i0 = blockIdx.x * 64, j0 = blockIdx.y * 64;
    int tid = threadIdx.x, tx = tid & 15, ty = tid >> 4;
    int cnt = g_cnt[c], start = g_start[c];
    float acc[4][4] = {};
    for (int r0 = 0; r0 < cnt; r0 += 16) {
#pragma unroll
        for (int t = 0; t < 4; t++) {
            int idx = tid + 256 * t;
            int kk = idx >> 6, ii = idx & 63;
            int rg = r0 + kk;
            int row = (rg < cnt) ? g_idx[start + rg] : -1;
            As[kk][ii] = (row >= 0) ? X[(size_t)row * D + i0 + ii] : 0.f;
            Bs[kk][ii] = (row >= 0) ? X[(size_t)row * D + j0 + ii] : 0.f;
        }
        __syncthreads();
#pragma unroll
        for (int kk = 0; kk < 16; kk++) {
            float a[4], b[4];
#pragma unroll
            for (int q = 0; q < 4; q++) a[q] = As[kk][4 * ty + q];
#pragma unroll
            for (int q = 0; q < 4; q++) b[q] = Bs[kk][4 * tx + q];
#pragma unroll
            for (int p = 0; p < 4; p++)
#pragma unroll
                for (int q = 0; q < 4; q++) acc[p][q] += a[p] * b[q];
        }
        __syncthreads();
    }
    float coef = g_coef[c], inv = g_invscale[c];
#pragma unroll
    for (int p = 0; p < 4; p++) {
        int i = i0 + 4 * ty + p;
        float mui = g_mu[c][i];
#pragma unroll
        for (int q = 0; q < 4; q++) {
            int j = j0 + 4 * tx + q;
            g_Sigma[c][i][j] = (g_Base[i][j] + acc[p][q] - coef * mui * g_mu[c][j]) * inv;
        }
    }
}

// ---------------- blocked Cholesky: factor diag block + panel solve ----------------
__global__ __launch_bounds__(512) void k_chol_panel(int kb) {
    __shared__ float Ds[64][65];
    int c = blockIdx.x;
    int tid = threadIdx.x;
    int base = kb * 64;
    for (int e = tid; e < 64 * 64; e += 512) {
        int i = e >> 6, j = e & 63;
        Ds[i][j] = g_Sigma[c][base + i][base + j];
    }
    __syncthreads();
    for (int j = 0; j < 64; j++) {
        if (tid == 0) Ds[j][j] = sqrtf(Ds[j][j]);
        __syncthreads();
        if (tid > j && tid < 64) Ds[tid][j] /= Ds[j][j];
        __syncthreads();
        for (int e = tid; e < 64 * 64; e += 512) {
            int i = e >> 6, kc = e & 63;
            if (i > j && kc > j && kc <= i) Ds[i][kc] -= Ds[i][j] * Ds[kc][j];
        }
        __syncthreads();
    }
    for (int e = tid; e < 64 * 64; e += 512) {
        int i = e >> 6, j = e & 63;
        if (j <= i) g_Sigma[c][base + i][base + j] = Ds[i][j];
    }
    __syncthreads();
    int nrows = D - base - 64;
    for (int rr = tid; rr < nrows; rr += 512) {
        int row = base + 64 + rr;
        float a[64];
#pragma unroll
        for (int k = 0; k < 64; k++) a[k] = g_Sigma[c][row][base + k];
#pragma unroll
        for (int j = 0; j < 64; j++) {
            float t = a[j];
#pragma unroll
            for (int k = 0; k < j; k++) t -= a[k] * Ds[j][k];
            a[j] = t / Ds[j][j];
        }
#pragma unroll
        for (int k = 0; k < 64; k++) g_Sigma[c][row][base + k] = a[k];
    }
}

// ---------------- trailing syrk update: A[ti,tj] -= P_ti P_tj^T ----------------
__global__ __launch_bounds__(256) void k_chol_trail(int kb) {
    int c = blockIdx.y;
    int pidx = blockIdx.x;
    int ti = kb + 1;
    while (pidx >= ti - kb) { pidx -= ti - kb; ti++; }
    int tj = kb + 1 + pidx;
    __shared__ float As[16][65], Bs[16][65];
    int tid = threadIdx.x, tx = tid & 15, ty = tid >> 4;
    int i0 = ti * 64, j0 = tj * 64, kbase = kb * 64;
    float acc[4][4] = {};
    for (int k0 = 0; k0 < 64; k0 += 16) {
#pragma unroll
        for (int t = 0; t < 4; t++) {
            int idx = tid + 256 * t;
            int ii = idx >> 4, kk = idx & 15;
            As[kk][ii] = g_Sigma[c][i0 + ii][kbase + k0 + kk];
            Bs[kk][ii] = g_Sigma[c][j0 + ii][kbase + k0 + kk];
        }
        __syncthreads();
#pragma unroll
        for (int kk = 0; kk < 16; kk++) {
            float a[4], b[4];
#pragma unroll
            for (int q = 0; q < 4; q++) a[q] = As[kk][4 * ty + q];
#pragma unroll
            for (int q = 0; q < 4; q++) b[q] = Bs[kk][4 * tx + q];
#pragma unroll
            for (int p = 0; p < 4; p++)
#pragma unroll
                for (int q = 0; q < 4; q++) acc[p][q] += a[p] * b[q];
        }
        __syncthreads();
    }
#pragma unroll
    for (int p = 0; p < 4; p++)
#pragma unroll
        for (int q = 0; q < 4; q++)
            g_Sigma[c][i0 + 4 * ty + p][j0 + 4 * tx + q] -= acc[p][q];
}

// ---------------- invert 64x64 diagonal blocks of R -> V diag ----------------
__global__ __launch_bounds__(64) void k_triinv_diag() {
    __shared__ float Ds[64][65];
    int t = blockIdx.x, c = blockIdx.y;
    int tid = threadIdx.x;
    int base = t * 64;
    for (int e = tid; e < 64 * 64; e += 64) {
        int i = e >> 6, j = e & 63;
        Ds[i][j] = (j <= i) ? g_Sigma[c][base + i][base + j] : 0.f;
    }
    __syncthreads();
    int j = tid;
    float x[64];
#pragma unroll
    for (int i = 0; i < 64; i++) {
        float tval = (i == j) ? 1.0f : 0.0f;
#pragma unroll
        for (int k = 0; k < i; k++) tval -= Ds[i][k] * x[k];
        x[i] = tval / Ds[i][i];
    }
#pragma unroll
    for (int i = 0; i < 64; i++) g_V[c][base + i][base + j] = x[i];
}

// ---------------- off-diagonal V blocks, level by level ----------------
__global__ __launch_bounds__(256) void k_triinv_off(int lev) {
    __shared__ float Ash[64][17];
    __shared__ float Bsh[16][65];
    __shared__ float Ts[64][65];
    __shared__ float Dsh[64][65];
    int c = blockIdx.y;
    int jb = blockIdx.x;
    int ib = jb + lev;
    int tid = threadIdx.x, tx = tid & 15, ty = tid >> 4;
    float acc[4][4] = {};
    int kr0 = jb * 64, kr1 = ib * 64;
    for (int k0 = kr0; k0 < kr1; k0 += 16) {
#pragma unroll
        for (int t = 0; t < 4; t++) {
            int idx = tid + 256 * t;
            {
                int ii = idx >> 4, kk = idx & 15;
                Ash[ii][kk] = g_Sigma[c][ib * 64 + ii][k0 + kk];
            }
            {
                int kk = idx >> 6, jj = idx & 63;
                Bsh[kk][jj] = g_V[c][k0 + kk][jb * 64 + jj];
            }
        }
        __syncthreads();
#pragma unroll
        for (int kk = 0; kk < 16; kk++) {
            float a[4], b[4];
#pragma unroll
            for (int q = 0; q < 4; q++) a[q] = Ash[4 * ty + q][kk];
#pragma unroll
            for (int q = 0; q < 4; q++) b[q] = Bsh[kk][4 * tx + q];
#pragma unroll
            for (int p = 0; p < 4; p++)
#pragma unroll
                for (int q = 0; q < 4; q++) acc[p][q] += a[p] * b[q];
        }
        __syncthreads();
    }
#pragma unroll
    for (int p = 0; p < 4; p++)
#pragma unroll
        for (int q = 0; q < 4; q++) Ts[4 * ty + p][4 * tx + q] = acc[p][q];
    for (int e = tid; e < 64 * 64; e += 256) {
        int i = e >> 6, j = e & 63;
        Dsh[i][j] = g_V[c][ib * 64 + i][ib * 64 + j];
    }
    __syncthreads();
    float acc2[4][4] = {};
#pragma unroll 4
    for (int q = 0; q < 64; q++) {
        float dv[4], tv[4];
#pragma unroll
        for (int p = 0; p < 4; p++) dv[p] = Dsh[4 * ty + p][q];
#pragma unroll
        for (int b = 0; b < 4; b++) tv[b] = Ts[q][4 * tx + b];
#pragma unroll
        for (int p = 0; p < 4; p++)
#pragma unroll
            for (int b = 0; b < 4; b++) acc2[p][b] += dv[p] * tv[b];
    }
#pragma unroll
    for (int p = 0; p < 4; p++)
#pragma unroll
        for (int b = 0; b < 4; b++)
            g_V[c][ib * 64 + 4 * ty + p][jb * 64 + 4 * tx + b] = -acc2[p][b];
}

// ---------------- bf16 hi/lo conversions ----------------
__global__ void k_cvt_xq(const float* __restrict__ Xq) {
    int i = blockIdx.x * 256 + threadIdx.x;  // 16384 blocks
    float x = Xq[i];
    __nv_bfloat16 h = __float2bfloat16(x);
    ((__nv_bfloat16*)g_Xqh)[i] = h;
    ((__nv_bfloat16*)g_Xql)[i] = __float2bfloat16(x - __bfloat162float(h));
}
__global__ void k_cvt_v() {
    size_t i = (size_t)blockIdx.x * 256 + threadIdx.x;  // 65536 blocks
    float x = ((const float*)g_V)[i];
    __nv_bfloat16 h = __float2bfloat16(x);
    ((__nv_bfloat16*)g_Vh)[i] = h;
    ((__nv_bfloat16*)g_Vl)[i] = __float2bfloat16(x - __bfloat162float(h));
}

// ---------------- s_c = V_c mu_c ----------------
__global__ void k_svec() {
    int c = blockIdx.y;
    int warp = threadIdx.x >> 5, lane = threadIdx.x & 31;
    int row = blockIdx.x * 8 + warp;
    float acc = 0.f;
    for (int k = lane; k <= row; k += 32) acc += g_V[c][row][k] * g_mu[c][k];
    for (int o = 16; o > 0; o >>= 1) acc += __shfl_down_sync(0xffffffffu, acc, o);
    if (lane == 0) g_s[c][row] = acc;
}

// ---------------- per-class scalars ----------------
__global__ void k_scalars() {
    int c = blockIdx.x;
    __shared__ float r1[256], r2[256];
    float a = 0.f, b = 0.f;
    for (int k = threadIdx.x; k < D; k += 256) {
        float sv = g_s[c][k];  a += sv * sv;
        float mv = g_mu[c][k]; b += mv * mv;
    }
    r1[threadIdx.x] = a; r2[threadIdx.x] = b;
    __syncthreads();
    for (int o = 128; o > 0; o >>= 1) {
        if (threadIdx.x < o) { r1[threadIdx.x] += r1[threadIdx.x + o]; r2[threadIdx.x] += r2[threadIdx.x + o]; }
        __syncthreads();
    }
    if (threadIdx.x == 0) { g_ssc[c] = r1[0]; g_mmc[c] = r2[0]; }
}

// ---------------- nx[m] = |Xq[m]|^2 ----------------
__global__ void k_nx(const float* __restrict__ Xq) {
    int warp = threadIdx.x >> 5, lane = threadIdx.x & 31;
    int row = blockIdx.x * 8 + warp;
    float acc = 0.f;
    for (int k = lane; k < D; k += 32) { float v = Xq[(size_t)row * D + k]; acc += v * v; }
    for (int o = 16; o > 0; o >>= 1) acc += __shfl_down_sync(0xffffffffu, acc, o);
    if (lane == 0) g_nx[row] = acc;
}

// ---------------- xm[m][c] = Xq[m] . mu[c] ----------------
__global__ void k_xm(const float* __restrict__ Xq) {
    int warp = threadIdx.x >> 5, lane = threadIdx.x & 31;
    int row = blockIdx.x * 8 + warp;
    float acc[CLS];
#pragma unroll
    for (int c = 0; c < CLS; c++) acc[c] = 0.f;
    for (int k = lane; k < D; k += 32) {
        float v = Xq[(size_t)row * D + k];
#pragma unroll
        for (int c = 0; c < CLS; c++) acc[c] += v * g_mu[c][k];
    }
#pragma unroll
    for (int c = 0; c < CLS; c++) {
        float a = acc[c];
        for (int o = 16; o > 0; o >>= 1) a += __shfl_down_sync(0xffffffffu, a, o);
        if (lane == 0) g_xm[row][c] = a;
    }
}

// ================= warp-mma logits: W = Xq V^T (bf16 split, triangular skip) ======
// Dynamic smem layout (bytes):
//   Ah [128 rows][72 bf16]  @0      (18432)
//   Al                      @18432  (18432)
//   Bh [64 rows][72 bf16]   @36864  (9216)
//   Bl                      @46080  (9216)   total 55296
// After the mainloop, bytes [0,8192) are reused as the q2/qb reduction buffer.
#define LG_ROWB 144            // 72 bf16 row stride in bytes
#define LG_SMEM 55296

__global__ __launch_bounds__(256) void k_logits_mma(float* __restrict__ out) {
    extern __shared__ char smem[];
    char* sAh = smem;
    char* sAl = smem + 18432;
    char* sBh = smem + 36864;
    char* sBl = smem + 46080;

    int tid = threadIdx.x, lane = tid & 31, wid = tid >> 5;
    int wm = wid >> 1, wn = wid & 1;
    int c = blockIdx.y, m0 = blockIdx.x * 128;

    // ldmatrix lane base addresses (bytes)
    uint32_t aH = smem_u32(sAh) + (uint32_t)((wm * 32 + (lane & 15)) * LG_ROWB + (lane >> 4) * 16);
    uint32_t aL = aH + 18432;
    uint32_t bH = smem_u32(sBh) + (uint32_t)((wn * 32 + ((lane & 16) >> 1) + (lane & 7)) * LG_ROWB
                                             + ((lane & 8) ? 16 : 0));
    uint32_t bL = bH + 9216;

    float q2[2][2] = {}, qb[2][2] = {};

    for (int jt = 0; jt < NT; jt++) {
        float acc[2][4][4];
#pragma unroll
        for (int ms = 0; ms < 2; ms++)
#pragma unroll
            for (int nt = 0; nt < 4; nt++)
#pragma unroll
                for (int q = 0; q < 4; q++) acc[ms][nt][q] = 0.f;

        for (int kt = 0; kt <= jt; kt++) {
            __syncthreads();
            // A tiles: 128x64 hi & lo
#pragma unroll
            for (int i = 0; i < 4; i++) {
                int idx = tid + 256 * i;
                int r = idx >> 3, c8 = idx & 7;
                int so = r * LG_ROWB + c8 * 16;
                const uint4* srcH = (const uint4*)&g_Xqh[m0 + r][kt * 64 + c8 * 8];
                const uint4* srcL = (const uint4*)&g_Xql[m0 + r][kt * 64 + c8 * 8];
                *(uint4*)(sAh + so) = *srcH;
                *(uint4*)(sAl + so) = *srcL;
            }
            // B tiles: 64x64 hi & lo
#pragma unroll
            for (int i = 0; i < 2; i++) {
                int idx = tid + 256 * i;
                int r = idx >> 3, c8 = idx & 7;
                int so = r * LG_ROWB + c8 * 16;
                *(uint4*)(sBh + so) = *(const uint4*)&g_Vh[c][jt * 64 + r][kt * 64 + c8 * 8];
                *(uint4*)(sBl + so) = *(const uint4*)&g_Vl[c][jt * 64 + r][kt * 64 + c8 * 8];
            }
            __syncthreads();

#pragma unroll
            for (int ks = 0; ks < 4; ks++) {
                uint32_t ah[2][4], al[2][4], bh[8], bl[8];
                ldsm4(ah[0], aH + ks * 32);
                ldsm4(ah[1], aH + 16 * LG_ROWB + ks * 32);
                ldsm4(al[0], aL + ks * 32);
                ldsm4(al[1], aL + 16 * LG_ROWB + ks * 32);
                ldsm4(&bh[0], bH + ks * 32);
                ldsm4(&bh[4], bH + 16 * LG_ROWB + ks * 32);
                ldsm4(&bl[0], bL + ks * 32);
                ldsm4(&bl[4], bL + 16 * LG_ROWB + ks * 32);
#pragma unroll
                for (int ms = 0; ms < 2; ms++)
#pragma unroll
                    for (int nt = 0; nt < 4; nt++) {
                        float* d = acc[ms][nt];
                        mma16816(d, ah[ms], &bh[nt * 2]);
                        mma16816(d, al[ms], &bh[nt * 2]);
                        mma16816(d, ah[ms], &bl[nt * 2]);
                    }
            }
        }
        // fold this jt's W tile into q2/qb (deterministic, per-thread)
#pragma unroll
        for (int ms = 0; ms < 2; ms++)
#pragma unroll
            for (int nt = 0; nt < 4; nt++) {
                int jc = jt * 64 + wn * 32 + nt * 8 + 2 * (lane & 3);
                float s0 = g_s[c][jc], s1 = g_s[c][jc + 1];
                float* d = acc[ms][nt];
                q2[ms][0] += d[0] * d[0] + d[1] * d[1];
                qb[ms][0] += d[0] * s0 + d[1] * s1;
                q2[ms][1] += d[2] * d[2] + d[3] * d[3];
                qb[ms][1] += d[2] * s0 + d[3] * s1;
            }
    }

    // cross-thread per-row reduction (8 deterministic slots per row)
    __syncthreads();
    float* rq = (float*)smem;            // [128][8]
    float* rb = (float*)(smem + 4096);   // [128][8]
    int slot = wn * 4 + (lane & 3);
    int g = lane >> 2;
#pragma unroll
    for (int ms = 0; ms < 2; ms++)
#pragma unroll
        for (int go = 0; go < 2; go++) {
            int row = wm * 32 + ms * 16 + go * 8 + g;
            rq[row * 8 + slot] = q2[ms][go];
            rb[row * 8 + slot] = qb[ms][go];
        }
    __syncthreads();
    if (tid < 128) {
        float q2r = 0.f, qbr = 0.f;
#pragma unroll
        for (int t = 0; t < 8; t++) { q2r += rq[tid * 8 + t]; qbr += rb[tid * 8 + t]; }
        int row = m0 + tid;
        float dq = g_nx[row] - 2.f * g_xm[row][c] + g_mmc[c];
        float qm = q2r - 2.f * qbr + g_ssc[c];
        out[(size_t)row * CLS + c] = -0.9f * qm - 0.1f * dq;
    }
}

// ---------------- launch ----------------
extern "C" void kernel_launch(void* const* d_in, const int* in_sizes, int n_in,
                              void* d_out, int out_size) {
    const float* X     = (const float*)d_in[0];
    const int*   y     = (const int*)d_in[1];
    const float* Xq    = (const float*)d_in[2];
    const float* m     = (const float*)d_in[3];
    const float* kappa = (const float*)d_in[4];
    const float* nu    = (const float*)d_in[5];
    const float* td    = (const float*)d_in[6];
    const float* tl    = (const float*)d_in[7];
    float* out = (float*)d_out;

    cudaFuncSetAttribute(k_logits_mma, cudaFuncAttributeMaxDynamicSharedMemorySize, LG_SMEM);

    k_stats1<<<dim3(8, 8), 128>>>(X, y);
    k_sort_params<<<1, 32>>>(y, kappa, nu);
    k_stats2<<<64, 256>>>();
    k_mu<<<dim3(4, CLS), 256>>>(m);
    k_cvt_xq<<<16384, 256>>>(Xq);
    k_buildL<<<D, 256>>>(td, tl);
    k_base<<<dim3(NT, NT), 256>>>(m);
    k_sigma<<<dim3(NT, NT, CLS), 256>>>(X);

    for (int kb = 0; kb < NT; kb++) {
        k_chol_panel<<<CLS, 512>>>(kb);
        int T = NT - 1 - kb;
        if (T > 0) k_chol_trail<<<dim3(T * (T + 1) / 2, CLS), 256>>>(kb);
    }

    k_triinv_diag<<<dim3(NT, CLS), 64>>>();
    for (int lev = 1; lev < NT; lev++)
        k_triinv_off<<<dim3(NT - lev, CLS), 256>>>(lev);

    k_cvt_v<<<65536, 256>>>();
    k_svec<<<dim3(D / 8, CLS), 256>>>();
    k_scalars<<<CLS, 256>>>();
    k_nx<<<MQ / 8, 256>>>(Xq);
    k_xm<<<MQ / 8, 256>>>(Xq);
    k_logits_mma<<<dim3(MQ / 128, CLS), 256, LG_SMEM>>>(out);
}

// round 5
// speedup vs baseline: 2.8590x; 1.6271x over previous
#include <cuda_runtime.h>
#include <cuda_bf16.h>
#include <math.h>
#include <stdint.h>

#define D      1024
#define CLS    16
#define NSAMP  4096
#define MQ     4096
#define NT     16

__device__ float g_Sigma[CLS][D][D];
__device__ float g_V[CLS][D][D];
__device__ float g_Base[D][D];
__device__ float g_L[D][D];
__device__ float g_part[8][CLS][D];
__device__ float g_sums[CLS][D];
__device__ float g_mu[CLS][D];
__device__ float g_s[CLS][D];
__device__ float g_nx[MQ];
__device__ float g_xm[MQ][CLS];
__device__ float g_ssc[CLS];
__device__ float g_mmc[CLS];
__device__ int   g_cnt[CLS];
__device__ int   g_cntp[8][CLS];
__device__ int   g_start[CLS];
__device__ int   g_idx[NSAMP];
__device__ float g_kap;
__device__ float g_coef[CLS];
__device__ float g_invscale[CLS];

__device__ __nv_bfloat16 g_Xqh[MQ][D];
__device__ __nv_bfloat16 g_Xql[MQ][D];
__device__ __nv_bfloat16 g_Vh[CLS][D][D];
__device__ __nv_bfloat16 g_Vl[CLS][D][D];

__device__ __forceinline__ uint32_t smem_u32(const void* p) {
    uint32_t a;
    asm("{ .reg .u64 t; cvta.to.shared.u64 t, %1; cvt.u32.u64 %0, t; }" : "=r"(a) : "l"(p));
    return a;
}
__device__ __forceinline__ void ldsm4(uint32_t* r, uint32_t a) {
    asm volatile("ldmatrix.sync.aligned.m8n8.x4.shared.b16 {%0,%1,%2,%3}, [%4];"
                 : "=r"(r[0]), "=r"(r[1]), "=r"(r[2]), "=r"(r[3]) : "r"(a));
}
__device__ __forceinline__ void mma16816(float* d, const uint32_t* a, const uint32_t* b) {
    asm volatile(
        "mma.sync.aligned.m16n8k16.row.col.f32.bf16.bf16.f32 "
        "{%0,%1,%2,%3}, {%4,%5,%6,%7}, {%8,%9}, {%0,%1,%2,%3};"
        : "+f"(d[0]), "+f"(d[1]), "+f"(d[2]), "+f"(d[3])
        : "r"(a[0]), "r"(a[1]), "r"(a[2]), "r"(a[3]), "r"(b[0]), "r"(b[1]));
}
__device__ __forceinline__ void mma_tf32(float* d, const uint32_t* a, const uint32_t* b) {
    asm volatile(
        "mma.sync.aligned.m16n8k8.row.col.f32.tf32.tf32.f32 "
        "{%0,%1,%2,%3}, {%4,%5,%6,%7}, {%8,%9}, {%0,%1,%2,%3};"
        : "+f"(d[0]), "+f"(d[1]), "+f"(d[2]), "+f"(d[3])
        : "r"(a[0]), "r"(a[1]), "r"(a[2]), "r"(a[3]), "r"(b[0]), "r"(b[1]));
}
__device__ __forceinline__ float tf32_rn(float x) {
    uint32_t u;
    asm("cvt.rna.tf32.f32 %0, %1;" : "=r"(u) : "f"(x));
    return __uint_as_float(u);
}
#define FB(x) (__float_as_uint(x))
#define MMA3(d, ah, bh, al, bl) { mma_tf32(d, ah, bh); mma_tf32(d, ah, bl); mma_tf32(d, al, bh); }

// ---------------- stats ----------------
__global__ void k_stats1(const float* __restrict__ X, const int* __restrict__ y) {
    __shared__ int sy[512];
    int tid = threadIdx.x;
    int r0 = blockIdx.y * 512;
    for (int n = tid; n < 512; n += 128) sy[n] = y[r0 + n];
    __syncthreads();
    int k = blockIdx.x * 128 + tid;
    float acc[CLS];
#pragma unroll
    for (int c = 0; c < CLS; c++) acc[c] = 0.f;
    for (int n = 0; n < 512; n++) {
        float v = X[(size_t)(r0 + n) * D + k];
        int cls = sy[n];
#pragma unroll
        for (int c = 0; c < CLS; c++) acc[c] += (cls == c) ? v : 0.f;
    }
#pragma unroll
    for (int c = 0; c < CLS; c++) g_part[blockIdx.y][c][k] = acc[c];
    if (blockIdx.x == 0) {
        __shared__ int scnt[CLS];
        if (tid < CLS) scnt[tid] = 0;
        __syncthreads();
        for (int n = tid; n < 512; n += 128) atomicAdd(&scnt[sy[n]], 1);
        __syncthreads();
        if (tid < CLS) g_cntp[blockIdx.y][tid] = scnt[tid];
    }
}
__global__ void k_stats2() {
    int idx = blockIdx.x * 256 + threadIdx.x;
    int c = idx >> 10, k = idx & 1023;
    float s = 0.f;
#pragma unroll
    for (int r = 0; r < 8; r++) s += g_part[r][c][k];
    g_sums[c][k] = s;
}
__global__ void k_sort_params(const int* __restrict__ y, const float* __restrict__ kappa,
                              const float* __restrict__ nu) {
    __shared__ int s_start[CLS];
    int lane = threadIdx.x;
    if (lane == 0) {
        int s = 0;
        for (int c = 0; c < CLS; c++) {
            int t = 0;
            for (int r = 0; r < 8; r++) t += g_cntp[r][c];
            g_cnt[c] = t; g_start[c] = s; s_start[c] = s; s += t;
        }
        float kap = fabsf(kappa[0]) + 1e-6f;
        g_kap = kap;
        float nu_ = fmaxf(nu[0], (float)(D - 1) + 1e-6f);
        for (int c = 0; c < CLS; c++) {
            float Nj = (float)g_cnt[c];
            g_coef[c] = kap + Nj;
            g_invscale[c] = 1.0f / (nu_ + Nj + (float)D + 2.0f);
        }
    }
    __syncthreads();
    int off[CLS];
#pragma unroll
    for (int c = 0; c < CLS; c++) off[c] = s_start[c];
    unsigned below = (1u << lane) - 1u;
    for (int n0 = 0; n0 < NSAMP; n0 += 32) {
        int v = y[n0 + lane];
#pragma unroll
        for (int c = 0; c < CLS; c++) {
            unsigned m = __ballot_sync(0xffffffffu, v == c);
            if (v == c) g_idx[off[c] + __popc(m & below)] = n0 + lane;
            off[c] += __popc(m);
        }
    }
}
__global__ void k_mu(const float* __restrict__ m) {
    int c = blockIdx.y;
    int k = blockIdx.x * blockDim.x + threadIdx.x;
    g_mu[c][k] = (g_kap * m[k] + g_sums[c][k]) / g_coef[c];
}
__global__ void k_buildL(const float* __restrict__ td, const float* __restrict__ tl) {
    int i = blockIdx.x;
    for (int k = threadIdx.x; k < D; k += blockDim.x) {
        float v;
        if (k < i) v = tl[(size_t)i * D + k];
        else if (k == i) v = fabsf(td[i]);
        else v = 0.f;
        g_L[i][k] = v;
    }
}

// ---------------- Base = L L^T + kap m m^T (triangular skip) ----------------
__global__ __launch_bounds__(256) void k_base(const float* __restrict__ m) {
    __shared__ float As[16][65];
    __shared__ float Bs[16][65];
    int i0 = blockIdx.x * 64, j0 = blockIdx.y * 64;
    int tid = threadIdx.x, tx = tid & 15, ty = tid >> 4;
    float acc[4][4] = {};
    int kend = ((i0 < j0) ? i0 : j0) + 64;
    for (int k0 = 0; k0 < kend; k0 += 16) {
#pragma unroll
        for (int t = 0; t < 4; t++) {
            int idx = tid + 256 * t;
            int ii = idx >> 4, kk = idx & 15;
            As[kk][ii] = g_L[i0 + ii][k0 + kk];
            Bs[kk][ii] = g_L[j0 + ii][k0 + kk];
        }
        __syncthreads();
#pragma unroll
        for (int kk = 0; kk < 16; kk++) {
            float a[4], b[4];
#pragma unroll
            for (int q = 0; q < 4; q++) a[q] = As[kk][4 * ty + q];
#pragma unroll
            for (int q = 0; q < 4; q++) b[q] = Bs[kk][4 * tx + q];
#pragma unroll
            for (int p = 0; p < 4; p++)
#pragma unroll
                for (int q = 0; q < 4; q++) acc[p][q] += a[p] * b[q];
        }
        __syncthreads();
    }
    float kap = g_kap;
#pragma unroll
    for (int p = 0; p < 4; p++) {
        int i = i0 + 4 * ty + p;
        float mi = m[i];
#pragma unroll
        for (int q = 0; q < 4; q++) {
            int j = j0 + 4 * tx + q;
            g_Base[i][j] = acc[p][q] + kap * mi * m[j];
        }
    }
}

// ---------------- Sigma via tf32-split mma: 128x64 tile, 8 warps ----------------
__global__ __launch_bounds__(256) void k_sigma_mma(const float* __restrict__ X) {
    __shared__ float Ah[16][136], Al[16][136];   // [k][i]
    __shared__ float Bh[16][72],  Bl[16][72];    // [k][j]
    int c = blockIdx.z;
    int i0 = blockIdx.x * 128, j0 = blockIdx.y * 64;
    int tid = threadIdx.x, lane = tid & 31, wid = tid >> 5;
    int wm = wid >> 1, wn = wid & 1;
    int r = lane >> 2, q = lane & 3;
    int cnt = g_cnt[c], start = g_start[c];
    float acc[2][4][4] = {};
    int kmax = (cnt + 15) & ~15;
    for (int k0 = 0; k0 < kmax; k0 += 16) {
        __syncthreads();
#pragma unroll
        for (int t = 0; t < 8; t++) {
            int e = tid + 256 * t;
            int kk = e >> 7, col = e & 127;
            int krow = k0 + kk;
            float v = (krow < cnt) ? X[(size_t)g_idx[start + krow] * D + i0 + col] : 0.f;
            float h = tf32_rn(v);
            Ah[kk][col] = h; Al[kk][col] = tf32_rn(v - h);
        }
#pragma unroll
        for (int t = 0; t < 4; t++) {
            int e = tid + 256 * t;
            int kk = e >> 6, col = e & 63;
            int krow = k0 + kk;
            float v = (krow < cnt) ? X[(size_t)g_idx[start + krow] * D + j0 + col] : 0.f;
            float h = tf32_rn(v);
            Bh[kk][col] = h; Bl[kk][col] = tf32_rn(v - h);
        }
        __syncthreads();
#pragma unroll
        for (int ks = 0; ks < 2; ks++) {
            int k8 = ks * 8;
            uint32_t ah[2][4], al[2][4], bh[4][2], bl[4][2];
#pragma unroll
            for (int ms = 0; ms < 2; ms++) {
                int mb = wm * 32 + ms * 16;
                ah[ms][0] = FB(Ah[k8 + q][mb + r]);     ah[ms][1] = FB(Ah[k8 + q][mb + 8 + r]);
                ah[ms][2] = FB(Ah[k8 + 4 + q][mb + r]); ah[ms][3] = FB(Ah[k8 + 4 + q][mb + 8 + r]);
                al[ms][0] = FB(Al[k8 + q][mb + r]);     al[ms][1] = FB(Al[k8 + q][mb + 8 + r]);
                al[ms][2] = FB(Al[k8 + 4 + q][mb + r]); al[ms][3] = FB(Al[k8 + 4 + q][mb + 8 + r]);
            }
#pragma unroll
            for (int nt = 0; nt < 4; nt++) {
                int nb = wn * 32 + nt * 8;
                bh[nt][0] = FB(Bh[k8 + q][nb + r]); bh[nt][1] = FB(Bh[k8 + 4 + q][nb + r]);
                bl[nt][0] = FB(Bl[k8 + q][nb + r]); bl[nt][1] = FB(Bl[k8 + 4 + q][nb + r]);
            }
#pragma unroll
            for (int ms = 0; ms < 2; ms++)
#pragma unroll
                for (int nt = 0; nt < 4; nt++)
                    MMA3(acc[ms][nt], ah[ms], bh[nt], al[ms], bl[nt]);
        }
    }
    float coef = g_coef[c], inv = g_invscale[c];
#pragma unroll
    for (int ms = 0; ms < 2; ms++)
#pragma unroll
        for (int nt = 0; nt < 4; nt++) {
            int i = i0 + wm * 32 + ms * 16 + r;
            int j = j0 + wn * 32 + nt * 8 + 2 * q;
            float* d = acc[ms][nt];
            float mui = g_mu[c][i], mui8 = g_mu[c][i + 8];
            float mj0 = g_mu[c][j], mj1 = g_mu[c][j + 1];
            g_Sigma[c][i][j]         = (g_Base[i][j]         + d[0] - coef * mui  * mj0) * inv;
            g_Sigma[c][i][j + 1]     = (g_Base[i][j + 1]     + d[1] - coef * mui  * mj1) * inv;
            g_Sigma[c][i + 8][j]     = (g_Base[i + 8][j]     + d[2] - coef * mui8 * mj0) * inv;
            g_Sigma[c][i + 8][j + 1] = (g_Base[i + 8][j + 1] + d[3] - coef * mui8 * mj1) * inv;
        }
}

// ---------------- diag factor 64x64 + invert -> g_V diag block ----------------
__global__ __launch_bounds__(256) void k_chol_diag(int kb) {
    __shared__ float Ds[64][65];
    int c = blockIdx.x;
    int tid = threadIdx.x;
    int base = kb * 64;
    for (int e = tid; e < 64 * 64; e += 256) {
        int i = e >> 6, j = e & 63;
        Ds[i][j] = g_Sigma[c][base + i][base + j];
    }
    __syncthreads();
    for (int j = 0; j < 64; j++) {
        if (tid == 0) Ds[j][j] = sqrtf(Ds[j][j]);
        __syncthreads();
        if (tid > j && tid < 64) Ds[tid][j] /= Ds[j][j];
        __syncthreads();
        for (int e = tid; e < 64 * 64; e += 256) {
            int i = e >> 6, kc = e & 63;
            if (i > j && kc > j && kc <= i) Ds[i][kc] -= Ds[i][j] * Ds[kc][j];
        }
        __syncthreads();
    }
    if (tid < 64) {
        int j = tid;
        float x[64];
#pragma unroll
        for (int i = 0; i < 64; i++) {
            float tval = (i == j) ? 1.0f : 0.0f;
#pragma unroll
            for (int k = 0; k < i; k++) tval -= Ds[i][k] * x[k];
            x[i] = tval / Ds[i][i];
        }
#pragma unroll
        for (int i = 0; i < 64; i++) g_V[c][base + i][base + j] = x[i];
    }
}

// ---------------- panel P = A21 * invL11^T (tf32), 64x64, 4 warps ----------------
__global__ __launch_bounds__(128) void k_pgemm(int kb) {
    __shared__ float Ah[64][20], Al[64][20], Bh[64][20], Bl[64][20];
    int c = blockIdx.y;
    int kbase = kb * 64;
    int i0 = kbase + 64 + blockIdx.x * 64;
    int tid = threadIdx.x, lane = tid & 31, wid = tid >> 5;
    int wy = wid >> 1, wx = wid & 1;
    int r = lane >> 2, q = lane & 3;
    float acc[2][4][4] = {};
    for (int k0 = 0; k0 < 64; k0 += 16) {
        __syncthreads();
#pragma unroll
        for (int t = 0; t < 8; t++) {
            int e = tid + 128 * t;
            int i = e >> 4, k = e & 15;
            float va = g_Sigma[c][i0 + i][kbase + k0 + k];
            float h = tf32_rn(va);
            Ah[i][k] = h; Al[i][k] = tf32_rn(va - h);
            float vb = g_V[c][kbase + i][kbase + k0 + k];
            h = tf32_rn(vb);
            Bh[i][k] = h; Bl[i][k] = tf32_rn(vb - h);
        }
        __syncthreads();
#pragma unroll
        for (int ks = 0; ks < 2; ks++) {
            int k8 = ks * 8;
            uint32_t ah[2][4], al[2][4], bh[4][2], bl[4][2];
#pragma unroll
            for (int ms = 0; ms < 2; ms++) {
                int mb = wy * 32 + ms * 16;
                ah[ms][0] = FB(Ah[mb + r][k8 + q]);     ah[ms][1] = FB(Ah[mb + 8 + r][k8 + q]);
                ah[ms][2] = FB(Ah[mb + r][k8 + 4 + q]); ah[ms][3] = FB(Ah[mb + 8 + r][k8 + 4 + q]);
                al[ms][0] = FB(Al[mb + r][k8 + q]);     al[ms][1] = FB(Al[mb + 8 + r][k8 + q]);
                al[ms][2] = FB(Al[mb + r][k8 + 4 + q]); al[ms][3] = FB(Al[mb + 8 + r][k8 + 4 + q]);
            }
#pragma unroll
            for (int nt = 0; nt < 4; nt++) {
                int nb = wx * 32 + nt * 8;
                bh[nt][0] = FB(Bh[nb + r][k8 + q]); bh[nt][1] = FB(Bh[nb + r][k8 + 4 + q]);
                bl[nt][0] = FB(Bl[nb + r][k8 + q]); bl[nt][1] = FB(Bl[nb + r][k8 + 4 + q]);
            }
#pragma unroll
            for (int ms = 0; ms < 2; ms++)
#pragma unroll
                for (int nt = 0; nt < 4; nt++)
                    MMA3(acc[ms][nt], ah[ms], bh[nt], al[ms], bl[nt]);
        }
    }
    __syncthreads();
#pragma unroll
    for (int ms = 0; ms < 2; ms++)
#pragma unroll
        for (int nt = 0; nt < 4; nt++) {
            int i = i0 + wy * 32 + ms * 16 + r;
            int j = kbase + wx * 32 + nt * 8 + 2 * q;
            float* d = acc[ms][nt];
            g_Sigma[c][i][j]         = d[0];
            g_Sigma[c][i][j + 1]     = d[1];
            g_Sigma[c][i + 8][j]     = d[2];
            g_Sigma[c][i + 8][j + 1] = d[3];
        }
}

// ---------------- trailing syrk: A[ti,tj] -= P_ti P_tj^T (tf32) ----------------
__global__ __launch_bounds__(128) void k_trail_mma(int kb) {
    __shared__ float Ah[64][20], Al[64][20], Bh[64][20], Bl[64][20];
    int c = blockIdx.y;
    int pidx = blockIdx.x;
    int ti = kb + 1;
    while (pidx >= ti - kb) { pidx -= ti - kb; ti++; }
    int tj = kb + 1 + pidx;
    int i0 = ti * 64, j0 = tj * 64, kbase = kb * 64;
    int tid = threadIdx.x, lane = tid & 31, wid = tid >> 5;
    int wy = wid >> 1, wx = wid & 1;
    int r = lane >> 2, q = lane & 3;
    float acc[2][4][4] = {};
    for (int k0 = 0; k0 < 64; k0 += 16) {
        __syncthreads();
#pragma unroll
        for (int t = 0; t < 8; t++) {
            int e = tid + 128 * t;
            int i = e >> 4, k = e & 15;
            float va = g_Sigma[c][i0 + i][kbase + k0 + k];
            float h = tf32_rn(va);
            Ah[i][k] = h; Al[i][k] = tf32_rn(va - h);
            float vb = g_Sigma[c][j0 + i][kbase + k0 + k];
            h = tf32_rn(vb);
            Bh[i][k] = h; Bl[i][k] = tf32_rn(vb - h);
        }
        __syncthreads();
#pragma unroll
        for (int ks = 0; ks < 2; ks++) {
            int k8 = ks * 8;
            uint32_t ah[2][4], al[2][4], bh[4][2], bl[4][2];
#pragma unroll
            for (int ms = 0; ms < 2; ms++) {
                int mb = wy * 32 + ms * 16;
                ah[ms][0] = FB(Ah[mb + r][k8 + q]);     ah[ms][1] = FB(Ah[mb + 8 + r][k8 + q]);
                ah[ms][2] = FB(Ah[mb + r][k8 + 4 + q]); ah[ms][3] = FB(Ah[mb + 8 + r][k8 + 4 + q]);
                al[ms][0] = FB(Al[mb + r][k8 + q]);     al[ms][1] = FB(Al[mb + 8 + r][k8 + q]);
                al[ms][2] = FB(Al[mb + r][k8 + 4 + q]); al[ms][3] = FB(Al[mb + 8 + r][k8 + 4 + q]);
            }
#pragma unroll
            for (int nt = 0; nt < 4; nt++) {
                int nb = wx * 32 + nt * 8;
                bh[nt][0] = FB(Bh[nb + r][k8 + q]); bh[nt][1] = FB(Bh[nb + r][k8 + 4 + q]);
                bl[nt][0] = FB(Bl[nb + r][k8 + q]); bl[nt][1] = FB(Bl[nb + r][k8 + 4 + q]);
            }
#pragma unroll
            for (int ms = 0; ms < 2; ms++)
#pragma unroll
                for (int nt = 0; nt < 4; nt++)
                    MMA3(acc[ms][nt], ah[ms], bh[nt], al[ms], bl[nt]);
        }
    }
    __syncthreads();
#pragma unroll
    for (int ms = 0; ms < 2; ms++)
#pragma unroll
        for (int nt = 0; nt < 4; nt++) {
            int i = i0 + wy * 32 + ms * 16 + r;
            int j = j0 + wx * 32 + nt * 8 + 2 * q;
            float* d = acc[ms][nt];
            g_Sigma[c][i][j]         -= d[0];
            g_Sigma[c][i][j + 1]     -= d[1];
            g_Sigma[c][i + 8][j]     -= d[2];
            g_Sigma[c][i + 8][j + 1] -= d[3];
        }
}

// ---------------- off-diag V blocks: tf32 first GEMM + fp32 second ----------------
__global__ __launch_bounds__(256) void k_triinv_off(int lev) {
    __shared__ char buf[19456 + 16640];
    float (*Ah)[20] = (float(*)[20])(buf);
    float (*Al)[20] = (float(*)[20])(buf + 5120);
    float (*Bh)[72] = (float(*)[72])(buf + 10240);
    float (*Bl)[72] = (float(*)[72])(buf + 14848);
    float (*Dsh)[65] = (float(*)[65])(buf);
    float (*Ts)[65]  = (float(*)[65])(buf + 19456);
    int c = blockIdx.y;
    int jb = blockIdx.x;
    int ib = jb + lev;
    int tid = threadIdx.x, lane = tid & 31, wid = tid >> 5;
    int wy = wid >> 1, wx = wid & 1;      // 4x2 warps, warp tile 16x32
    int r = lane >> 2, q = lane & 3;
    float acc[4][4] = {};
    int kr0 = jb * 64, nk = lev * 64;
    for (int k0 = 0; k0 < nk; k0 += 16) {
        __syncthreads();
#pragma unroll
        for (int t = 0; t < 4; t++) {
            int e = tid + 256 * t;
            int i = e >> 4, k = e & 15;
            float v = g_Sigma[c][ib * 64 + i][kr0 + k0 + k];
            float h = tf32_rn(v);
            Ah[i][k] = h; Al[i][k] = tf32_rn(v - h);
        }
#pragma unroll
        for (int t = 0; t < 4; t++) {
            int e = tid + 256 * t;
            int k = e >> 6, j = e & 63;
            float v = g_V[c][kr0 + k0 + k][jb * 64 + j];
            float h = tf32_rn(v);
            Bh[k][j] = h; Bl[k][j] = tf32_rn(v - h);
        }
        __syncthreads();
#pragma unroll
        for (int ks = 0; ks < 2; ks++) {
            int k8 = ks * 8;
            uint32_t ah[4], al[4], bh[4][2], bl[4][2];
            int mb = wy * 16;
            ah[0] = FB(Ah[mb + r][k8 + q]);     ah[1] = FB(Ah[mb + 8 + r][k8 + q]);
            ah[2] = FB(Ah[mb + r][k8 + 4 + q]); ah[3] = FB(Ah[mb + 8 + r][k8 + 4 + q]);
            al[0] = FB(Al[mb + r][k8 + q]);     al[1] = FB(Al[mb + 8 + r][k8 + q]);
            al[2] = FB(Al[mb + r][k8 + 4 + q]); al[3] = FB(Al[mb + 8 + r][k8 + 4 + q]);
#pragma unroll
            for (int nt = 0; nt < 4; nt++) {
                int nb = wx * 32 + nt * 8;
                bh[nt][0] = FB(Bh[k8 + q][nb + r]); bh[nt][1] = FB(Bh[k8 + 4 + q][nb + r]);
                bl[nt][0] = FB(Bl[k8 + q][nb + r]); bl[nt][1] = FB(Bl[k8 + 4 + q][nb + r]);
            }
#pragma unroll
            for (int nt = 0; nt < 4; nt++)
                MMA3(acc[nt], ah, bh[nt], al, bl[nt]);
        }
    }
    __syncthreads();
#pragma unroll
    for (int nt = 0; nt < 4; nt++) {
        int m = wy * 16 + r;
        int n = wx * 32 + nt * 8 + 2 * q;
        Ts[m][n] = acc[nt][0];     Ts[m][n + 1] = acc[nt][1];
        Ts[m + 8][n] = acc[nt][2]; Ts[m + 8][n + 1] = acc[nt][3];
    }
    for (int e = tid; e < 64 * 64; e += 256)
        Dsh[e >> 6][e & 63] = g_V[c][ib * 64 + (e >> 6)][ib * 64 + (e & 63)];
    __syncthreads();
    int tx = tid & 15, ty = tid >> 4;
    float acc2[4][4] = {};
#pragma unroll 4
    for (int qq = 0; qq < 64; qq++) {
        float dv[4], tv[4];
#pragma unroll
        for (int p = 0; p < 4; p++) dv[p] = Dsh[4 * ty + p][qq];
#pragma unroll
        for (int b = 0; b < 4; b++) tv[b] = Ts[qq][4 * tx + b];
#pragma unroll
        for (int p = 0; p < 4; p++)
#pragma unroll
            for (int b = 0; b < 4; b++) acc2[p][b] += dv[p] * tv[b];
    }
#pragma unroll
    for (int p = 0; p < 4; p++)
#pragma unroll
        for (int b = 0; b < 4; b++)
            g_V[c][ib * 64 + 4 * ty + p][jb * 64 + 4 * tx + b] = -acc2[p][b];
}

// ---------------- conversions / small vec kernels ----------------
__global__ void k_cvt_xq(const float* __restrict__ Xq) {
    int i = blockIdx.x * 256 + threadIdx.x;
    float x = Xq[i];
    __nv_bfloat16 h = __float2bfloat16(x);
    ((__nv_bfloat16*)g_Xqh)[i] = h;
    ((__nv_bfloat16*)g_Xql)[i] = __float2bfloat16(x - __bfloat162float(h));
}
__global__ void k_cvt_v() {
    size_t i = (size_t)blockIdx.x * 256 + threadIdx.x;
    float x = ((const float*)g_V)[i];
    __nv_bfloat16 h = __float2bfloat16(x);
    ((__nv_bfloat16*)g_Vh)[i] = h;
    ((__nv_bfloat16*)g_Vl)[i] = __float2bfloat16(x - __bfloat162float(h));
}
__global__ void k_svec() {
    int c = blockIdx.y;
    int warp = threadIdx.x >> 5, lane = threadIdx.x & 31;
    int row = blockIdx.x * 8 + warp;
    float acc = 0.f;
    for (int k = lane; k <= row; k += 32) acc += g_V[c][row][k] * g_mu[c][k];
    for (int o = 16; o > 0; o >>= 1) acc += __shfl_down_sync(0xffffffffu, acc, o);
    if (lane == 0) g_s[c][row] = acc;
}
__global__ void k_scalars() {
    int c = blockIdx.x;
    __shared__ float r1[256], r2[256];
    float a = 0.f, b = 0.f;
    for (int k = threadIdx.x; k < D; k += 256) {
        float sv = g_s[c][k];  a += sv * sv;
        float mv = g_mu[c][k]; b += mv * mv;
    }
    r1[threadIdx.x] = a; r2[threadIdx.x] = b;
    __syncthreads();
    for (int o = 128; o > 0; o >>= 1) {
        if (threadIdx.x < o) { r1[threadIdx.x] += r1[threadIdx.x + o]; r2[threadIdx.x] += r2[threadIdx.x + o]; }
        __syncthreads();
    }
    if (threadIdx.x == 0) { g_ssc[c] = r1[0]; g_mmc[c] = r2[0]; }
}
__global__ void k_nx(const float* __restrict__ Xq) {
    int warp = threadIdx.x >> 5, lane = threadIdx.x & 31;
    int row = blockIdx.x * 8 + warp;
    float acc = 0.f;
    for (int k = lane; k < D; k += 32) { float v = Xq[(size_t)row * D + k]; acc += v * v; }
    for (int o = 16; o > 0; o >>= 1) acc += __shfl_down_sync(0xffffffffu, acc, o);
    if (lane == 0) g_nx[row] = acc;
}
__global__ void k_xm(const float* __restrict__ Xq) {
    int warp = threadIdx.x >> 5, lane = threadIdx.x & 31;
    int row = blockIdx.x * 8 + warp;
    float acc[CLS];
#pragma unroll
    for (int c = 0; c < CLS; c++) acc[c] = 0.f;
    for (int k = lane; k < D; k += 32) {
        float v = Xq[(size_t)row * D + k];
#pragma unroll
        for (int c = 0; c < CLS; c++) acc[c] += v * g_mu[c][k];
    }
#pragma unroll
    for (int c = 0; c < CLS; c++) {
        float a = acc[c];
        for (int o = 16; o > 0; o >>= 1) a += __shfl_down_sync(0xffffffffu, a, o);
        if (lane == 0) g_xm[row][c] = a;
    }
}

// ---------------- logits (bf16-split mma, unchanged) ----------------
#define LG_ROWB 144
#define LG_SMEM 55296
__global__ __launch_bounds__(256) void k_logits_mma(float* __restrict__ out) {
    extern __shared__ char smem[];
    char* sAh = smem;
    char* sAl = smem + 18432;
    char* sBh = smem + 36864;
    char* sBl = smem + 46080;
    int tid = threadIdx.x, lane = tid & 31, wid = tid >> 5;
    int wm = wid >> 1, wn = wid & 1;
    int c = blockIdx.y, m0 = blockIdx.x * 128;
    uint32_t aH = smem_u32(sAh) + (uint32_t)((wm * 32 + (lane & 15)) * LG_ROWB + (lane >> 4) * 16);
    uint32_t aL = aH + 18432;
    uint32_t bH = smem_u32(sBh) + (uint32_t)((wn * 32 + ((lane & 16) >> 1) + (lane & 7)) * LG_ROWB
                                             + ((lane & 8) ? 16 : 0));
    uint32_t bL = bH + 9216;
    float q2[2][2] = {}, qb[2][2] = {};
    for (int jt = 0; jt < NT; jt++) {
        float acc[2][4][4];
#pragma unroll
        for (int ms = 0; ms < 2; ms++)
#pragma unroll
            for (int nt = 0; nt < 4; nt++)
#pragma unroll
                for (int q = 0; q < 4; q++) acc[ms][nt][q] = 0.f;
        for (int kt = 0; kt <= jt; kt++) {
            __syncthreads();
#pragma unroll
            for (int i = 0; i < 4; i++) {
                int idx = tid + 256 * i;
                int r = idx >> 3, c8 = idx & 7;
                int so = r * LG_ROWB + c8 * 16;
                *(uint4*)(sAh + so) = *(const uint4*)&g_Xqh[m0 + r][kt * 64 + c8 * 8];
                *(uint4*)(sAl + so) = *(const uint4*)&g_Xql[m0 + r][kt * 64 + c8 * 8];
            }
#pragma unroll
            for (int i = 0; i < 2; i++) {
                int idx = tid + 256 * i;
                int r = idx >> 3, c8 = idx & 7;
                int so = r * LG_ROWB + c8 * 16;
                *(uint4*)(sBh + so) = *(const uint4*)&g_Vh[c][jt * 64 + r][kt * 64 + c8 * 8];
                *(uint4*)(sBl + so) = *(const uint4*)&g_Vl[c][jt * 64 + r][kt * 64 + c8 * 8];
            }
            __syncthreads();
#pragma unroll
            for (int ks = 0; ks < 4; ks++) {
                uint32_t ah[2][4], al[2][4], bh[8], bl[8];
                ldsm4(ah[0], aH + ks * 32);
                ldsm4(ah[1], aH + 16 * LG_ROWB + ks * 32);
                ldsm4(al[0], aL + ks * 32);
                ldsm4(al[1], aL + 16 * LG_ROWB + ks * 32);
                ldsm4(&bh[0], bH + ks * 32);
                ldsm4(&bh[4], bH + 16 * LG_ROWB + ks * 32);
                ldsm4(&bl[0], bL + ks * 32);
                ldsm4(&bl[4], bL + 16 * LG_ROWB + ks * 32);
#pragma unroll
                for (int ms = 0; ms < 2; ms++)
#pragma unroll
                    for (int nt = 0; nt < 4; nt++) {
                        float* d = acc[ms][nt];
                        mma16816(d, ah[ms], &bh[nt * 2]);
                        mma16816(d, al[ms], &bh[nt * 2]);
                        mma16816(d, ah[ms], &bl[nt * 2]);
                    }
            }
        }
#pragma unroll
        for (int ms = 0; ms < 2; ms++)
#pragma unroll
            for (int nt = 0; nt < 4; nt++) {
                int jc = jt * 64 + wn * 32 + nt * 8 + 2 * (lane & 3);
                float s0 = g_s[c][jc], s1 = g_s[c][jc + 1];
                float* d = acc[ms][nt];
                q2[ms][0] += d[0] * d[0] + d[1] * d[1];
                qb[ms][0] += d[0] * s0 + d[1] * s1;
                q2[ms][1] += d[2] * d[2] + d[3] * d[3];
                qb[ms][1] += d[2] * s0 + d[3] * s1;
            }
    }
    __syncthreads();
    float* rq = (float*)smem;
    float* rb = (float*)(smem + 4096);
    int slot = wn * 4 + (lane & 3);
    int g = lane >> 2;
#pragma unroll
    for (int ms = 0; ms < 2; ms++)
#pragma unroll
        for (int go = 0; go < 2; go++) {
            int row = wm * 32 + ms * 16 + go * 8 + g;
            rq[row * 8 + slot] = q2[ms][go];
            rb[row * 8 + slot] = qb[ms][go];
        }
    __syncthreads();
    if (tid < 128) {
        float q2r = 0.f, qbr = 0.f;
#pragma unroll
        for (int t = 0; t < 8; t++) { q2r += rq[tid * 8 + t]; qbr += rb[tid * 8 + t]; }
        int row = m0 + tid;
        float dq = g_nx[row] - 2.f * g_xm[row][c] + g_mmc[c];
        float qm = q2r - 2.f * qbr + g_ssc[c];
        out[(size_t)row * CLS + c] = -0.9f * qm - 0.1f * dq;
    }
}

// ---------------- launch ----------------
extern "C" void kernel_launch(void* const* d_in, const int* in_sizes, int n_in,
                              void* d_out, int out_size) {
    const float* X     = (const float*)d_in[0];
    const int*   y     = (const int*)d_in[1];
    const float* Xq    = (const float*)d_in[2];
    const float* m     = (const float*)d_in[3];
    const float* kappa = (const float*)d_in[4];
    const float* nu    = (const float*)d_in[5];
    const float* td    = (const float*)d_in[6];
    const float* tl    = (const float*)d_in[7];
    float* out = (float*)d_out;

    cudaFuncSetAttribute(k_logits_mma, cudaFuncAttributeMaxDynamicSharedMemorySize, LG_SMEM);

    k_stats1<<<dim3(8, 8), 128>>>(X, y);
    k_sort_params<<<1, 32>>>(y, kappa, nu);
    k_stats2<<<64, 256>>>();
    k_mu<<<dim3(4, CLS), 256>>>(m);
    k_cvt_xq<<<16384, 256>>>(Xq);
    k_buildL<<<D, 256>>>(td, tl);
    k_base<<<dim3(NT, NT), 256>>>(m);
    k_sigma_mma<<<dim3(8, 16, CLS), 256>>>(X);

    for (int kb = 0; kb < NT; kb++) {
        k_chol_diag<<<CLS, 256>>>(kb);
        int T = NT - 1 - kb;
        if (T > 0) {
            k_pgemm<<<dim3(T, CLS), 128>>>(kb);
            k_trail_mma<<<dim3(T * (T + 1) / 2, CLS), 128>>>(kb);
        }
    }

    for (int lev = 1; lev < NT; lev++)
        k_triinv_off<<<dim3(NT - lev, CLS), 256>>>(lev);

    k_cvt_v<<<65536, 256>>>();
    k_svec<<<dim3(D / 8, CLS), 256>>>();
    k_scalars<<<CLS, 256>>>();
    k_nx<<<MQ / 8, 256>>>(Xq);
    k_xm<<<MQ / 8, 256>>>(Xq);
    k_logits_mma<<<dim3(MQ / 128, CLS), 256, LG_SMEM>>>(out);
}

// round 7
// speedup vs baseline: 2.8939x; 1.0122x over previous
#include <cuda_runtime.h>
#include <cuda_bf16.h>
#include <math.h>
#include <stdint.h>

#define D      1024
#define CLS    16
#define NSAMP  4096
#define MQ     4096
#define NT     16

__device__ float g_Sigma[CLS][D][D];
__device__ float g_V[CLS][D][D];
__device__ float g_T1[CLS][262144];
__device__ float g_Base[D][D];
__device__ float g_L[D][D];
__device__ float g_part[8][CLS][D];
__device__ float g_sums[CLS][D];
__device__ float g_mu[CLS][D];
__device__ float g_s[CLS][D];
__device__ float g_nx[MQ];
__device__ float g_xm[MQ][CLS];
__device__ float g_ssc[CLS];
__device__ float g_mmc[CLS];
__device__ int   g_cnt[CLS];
__device__ int   g_cntp[8][CLS];
__device__ int   g_start[CLS];
__device__ int   g_idx[NSAMP];
__device__ float g_kap;
__device__ float g_coef[CLS];
__device__ float g_invscale[CLS];

__device__ __nv_bfloat16 g_Xqh[MQ][D];
__device__ __nv_bfloat16 g_Xql[MQ][D];
__device__ __nv_bfloat16 g_Vh[CLS][D][D];
__device__ __nv_bfloat16 g_Vl[CLS][D][D];

__device__ __forceinline__ uint32_t smem_u32(const void* p) {
    uint32_t a;
    asm("{ .reg .u64 t; cvta.to.shared.u64 t, %1; cvt.u32.u64 %0, t; }" : "=r"(a) : "l"(p));
    return a;
}
__device__ __forceinline__ void ldsm4(uint32_t* r, uint32_t a) {
    asm volatile("ldmatrix.sync.aligned.m8n8.x4.shared.b16 {%0,%1,%2,%3}, [%4];"
                 : "=r"(r[0]), "=r"(r[1]), "=r"(r[2]), "=r"(r[3]) : "r"(a));
}
__device__ __forceinline__ void mma16816(float* d, const uint32_t* a, const uint32_t* b) {
    asm volatile(
        "mma.sync.aligned.m16n8k16.row.col.f32.bf16.bf16.f32 "
        "{%0,%1,%2,%3}, {%4,%5,%6,%7}, {%8,%9}, {%0,%1,%2,%3};"
        : "+f"(d[0]), "+f"(d[1]), "+f"(d[2]), "+f"(d[3])
        : "r"(a[0]), "r"(a[1]), "r"(a[2]), "r"(a[3]), "r"(b[0]), "r"(b[1]));
}
__device__ __forceinline__ void mma_tf32(float* d, const uint32_t* a, const uint32_t* b) {
    asm volatile(
        "mma.sync.aligned.m16n8k8.row.col.f32.tf32.tf32.f32 "
        "{%0,%1,%2,%3}, {%4,%5,%6,%7}, {%8,%9}, {%0,%1,%2,%3};"
        : "+f"(d[0]), "+f"(d[1]), "+f"(d[2]), "+f"(d[3])
        : "r"(a[0]), "r"(a[1]), "r"(a[2]), "r"(a[3]), "r"(b[0]), "r"(b[1]));
}
__device__ __forceinline__ float tf32_rn(float x) {
    uint32_t u;
    asm("cvt.rna.tf32.f32 %0, %1;" : "=r"(u) : "f"(x));
    return __uint_as_float(u);
}
#define FB(x) (__float_as_uint(x))
#define MMA3(d, ah, bh, al, bl) { mma_tf32(d, ah, bh); mma_tf32(d, ah, bl); mma_tf32(d, al, bh); }

__device__ __forceinline__ void writeV(int c, int i, int j, float v) {
    g_V[c][i][j] = v;
    __nv_bfloat16 hb = __float2bfloat16(v);
    g_Vh[c][i][j] = hb;
    g_Vl[c][i][j] = __float2bfloat16(v - __bfloat162float(hb));
}

// ---------------- stats ----------------
__global__ void k_stats1(const float* __restrict__ X, const int* __restrict__ y) {
    __shared__ int sy[512];
    int tid = threadIdx.x;
    int r0 = blockIdx.y * 512;
    for (int n = tid; n < 512; n += 128) sy[n] = y[r0 + n];
    __syncthreads();
    int k = blockIdx.x * 128 + tid;
    float acc[CLS];
#pragma unroll
    for (int c = 0; c < CLS; c++) acc[c] = 0.f;
    for (int n = 0; n < 512; n++) {
        float v = X[(size_t)(r0 + n) * D + k];
        int cls = sy[n];
#pragma unroll
        for (int c = 0; c < CLS; c++) acc[c] += (cls == c) ? v : 0.f;
    }
#pragma unroll
    for (int c = 0; c < CLS; c++) g_part[blockIdx.y][c][k] = acc[c];
    if (blockIdx.x == 0) {
        __shared__ int scnt[CLS];
        if (tid < CLS) scnt[tid] = 0;
        __syncthreads();
        for (int n = tid; n < 512; n += 128) atomicAdd(&scnt[sy[n]], 1);
        __syncthreads();
        if (tid < CLS) g_cntp[blockIdx.y][tid] = scnt[tid];
    }
}
__global__ void k_stats2() {
    int idx = blockIdx.x * 256 + threadIdx.x;
    int c = idx >> 10, k = idx & 1023;
    float s = 0.f;
#pragma unroll
    for (int r = 0; r < 8; r++) s += g_part[r][c][k];
    g_sums[c][k] = s;
}
__global__ void k_sort_params(const int* __restrict__ y, const float* __restrict__ kappa,
                              const float* __restrict__ nu) {
    __shared__ int s_start[CLS];
    int lane = threadIdx.x;
    if (lane == 0) {
        int s = 0;
        for (int c = 0; c < CLS; c++) {
            int t = 0;
            for (int r = 0; r < 8; r++) t += g_cntp[r][c];
            g_cnt[c] = t; g_start[c] = s; s_start[c] = s; s += t;
        }
        float kap = fabsf(kappa[0]) + 1e-6f;
        g_kap = kap;
        float nu_ = fmaxf(nu[0], (float)(D - 1) + 1e-6f);
        for (int c = 0; c < CLS; c++) {
            float Nj = (float)g_cnt[c];
            g_coef[c] = kap + Nj;
            g_invscale[c] = 1.0f / (nu_ + Nj + (float)D + 2.0f);
        }
    }
    __syncthreads();
    int off[CLS];
#pragma unroll
    for (int c = 0; c < CLS; c++) off[c] = s_start[c];
    unsigned below = (1u << lane) - 1u;
    for (int n0 = 0; n0 < NSAMP; n0 += 32) {
        int v = y[n0 + lane];
#pragma unroll
        for (int c = 0; c < CLS; c++) {
            unsigned m = __ballot_sync(0xffffffffu, v == c);
            if (v == c) g_idx[off[c] + __popc(m & below)] = n0 + lane;
            off[c] += __popc(m);
        }
    }
}
__global__ void k_mu(const float* __restrict__ m) {
    int c = blockIdx.y;
    int k = blockIdx.x * blockDim.x + threadIdx.x;
    g_mu[c][k] = (g_kap * m[k] + g_sums[c][k]) / g_coef[c];
}
__global__ void k_buildL(const float* __restrict__ td, const float* __restrict__ tl) {
    int i = blockIdx.x;
    for (int k = threadIdx.x; k < D; k += blockDim.x) {
        float v;
        if (k < i) v = tl[(size_t)i * D + k];
        else if (k == i) v = fabsf(td[i]);
        else v = 0.f;
        g_L[i][k] = v;
    }
}

// ---------------- Base = L L^T + kap m m^T (triangular skip) ----------------
__global__ __launch_bounds__(256) void k_base(const float* __restrict__ m) {
    __shared__ float As[16][65];
    __shared__ float Bs[16][65];
    int i0 = blockIdx.x * 64, j0 = blockIdx.y * 64;
    int tid = threadIdx.x, tx = tid & 15, ty = tid >> 4;
    float acc[4][4] = {};
    int kend = ((i0 < j0) ? i0 : j0) + 64;
    for (int k0 = 0; k0 < kend; k0 += 16) {
#pragma unroll
        for (int t = 0; t < 4; t++) {
            int idx = tid + 256 * t;
            int ii = idx >> 4, kk = idx & 15;
            As[kk][ii] = g_L[i0 + ii][k0 + kk];
            Bs[kk][ii] = g_L[j0 + ii][k0 + kk];
        }
        __syncthreads();
#pragma unroll
        for (int kk = 0; kk < 16; kk++) {
            float a[4], b[4];
#pragma unroll
            for (int q = 0; q < 4; q++) a[q] = As[kk][4 * ty + q];
#pragma unroll
            for (int q = 0; q < 4; q++) b[q] = Bs[kk][4 * tx + q];
#pragma unroll
            for (int p = 0; p < 4; p++)
#pragma unroll
                for (int q = 0; q < 4; q++) acc[p][q] += a[p] * b[q];
        }
        __syncthreads();
    }
    float kap = g_kap;
#pragma unroll
    for (int p = 0; p < 4; p++) {
        int i = i0 + 4 * ty + p;
        float mi = m[i];
#pragma unroll
        for (int q = 0; q < 4; q++) {
            int j = j0 + 4 * tx + q;
            g_Base[i][j] = acc[p][q] + kap * mi * m[j];
        }
    }
}

// ---------------- Sigma via tf32-split mma (classes batched in grid.z) -----------
__global__ __launch_bounds__(256) void k_sigma_mma(const float* __restrict__ X) {
    __shared__ float Ah[16][136], Al[16][136];
    __shared__ float Bh[16][72],  Bl[16][72];
    int c = blockIdx.z;
    int i0 = blockIdx.x * 128, j0 = blockIdx.y * 64;
    int tid = threadIdx.x, lane = tid & 31, wid = tid >> 5;
    int wm = wid >> 1, wn = wid & 1;
    int r = lane >> 2, q = lane & 3;
    int cnt = g_cnt[c], start = g_start[c];
    float acc[2][4][4] = {};
    int kmax = (cnt + 15) & ~15;
    for (int k0 = 0; k0 < kmax; k0 += 16) {
        __syncthreads();
#pragma unroll
        for (int t = 0; t < 8; t++) {
            int e = tid + 256 * t;
            int kk = e >> 7, col = e & 127;
            int krow = k0 + kk;
            float v = (krow < cnt) ? X[(size_t)g_idx[start + krow] * D + i0 + col] : 0.f;
            float h = tf32_rn(v);
            Ah[kk][col] = h; Al[kk][col] = tf32_rn(v - h);
        }
#pragma unroll
        for (int t = 0; t < 4; t++) {
            int e = tid + 256 * t;
            int kk = e >> 6, col = e & 63;
            int krow = k0 + kk;
            float v = (krow < cnt) ? X[(size_t)g_idx[start + krow] * D + j0 + col] : 0.f;
            float h = tf32_rn(v);
            Bh[kk][col] = h; Bl[kk][col] = tf32_rn(v - h);
        }
        __syncthreads();
#pragma unroll
        for (int ks = 0; ks < 2; ks++) {
            int k8 = ks * 8;
            uint32_t ah[2][4], al[2][4], bh[4][2], bl[4][2];
#pragma unroll
            for (int ms = 0; ms < 2; ms++) {
                int mb = wm * 32 + ms * 16;
                ah[ms][0] = FB(Ah[k8 + q][mb + r]);     ah[ms][1] = FB(Ah[k8 + q][mb + 8 + r]);
                ah[ms][2] = FB(Ah[k8 + 4 + q][mb + r]); ah[ms][3] = FB(Ah[k8 + 4 + q][mb + 8 + r]);
                al[ms][0] = FB(Al[k8 + q][mb + r]);     al[ms][1] = FB(Al[k8 + q][mb + 8 + r]);
                al[ms][2] = FB(Al[k8 + 4 + q][mb + r]); al[ms][3] = FB(Al[k8 + 4 + q][mb + 8 + r]);
            }
#pragma unroll
            for (int nt = 0; nt < 4; nt++) {
                int nb = wn * 32 + nt * 8;
                bh[nt][0] = FB(Bh[k8 + q][nb + r]); bh[nt][1] = FB(Bh[k8 + 4 + q][nb + r]);
                bl[nt][0] = FB(Bl[k8 + q][nb + r]); bl[nt][1] = FB(Bl[k8 + 4 + q][nb + r]);
            }
#pragma unroll
            for (int ms = 0; ms < 2; ms++)
#pragma unroll
                for (int nt = 0; nt < 4; nt++)
                    MMA3(acc[ms][nt], ah[ms], bh[nt], al[ms], bl[nt]);
        }
    }
    float coef = g_coef[c], inv = g_invscale[c];
#pragma unroll
    for (int ms = 0; ms < 2; ms++)
#pragma unroll
        for (int nt = 0; nt < 4; nt++) {
            int i = i0 + wm * 32 + ms * 16 + r;
            int j = j0 + wn * 32 + nt * 8 + 2 * q;
            float* d = acc[ms][nt];
            float mui = g_mu[c][i], mui8 = g_mu[c][i + 8];
            float mj0 = g_mu[c][j], mj1 = g_mu[c][j + 1];
            g_Sigma[c][i][j]         = (g_Base[i][j]         + d[0] - coef * mui  * mj0) * inv;
            g_Sigma[c][i][j + 1]     = (g_Base[i][j + 1]     + d[1] - coef * mui  * mj1) * inv;
            g_Sigma[c][i + 8][j]     = (g_Base[i + 8][j]     + d[2] - coef * mui8 * mj0) * inv;
            g_Sigma[c][i + 8][j + 1] = (g_Base[i + 8][j + 1] + d[3] - coef * mui8 * mj1) * inv;
        }
}

// ---------------- initial diag: factor tile 0 + invert -> V diag (+bf16) ---------
__global__ __launch_bounds__(256) void k_chol_diag0() {
    __shared__ float Ds[64][65];
    int c = blockIdx.x;
    int tid = threadIdx.x;
    for (int e = tid; e < 4096; e += 256) {
        Ds[e >> 6][e & 63] = g_Sigma[c][e >> 6][e & 63];
    }
    __syncthreads();
    for (int j = 0; j < 64; j++) {
        if (tid == 0) Ds[j][j] = sqrtf(Ds[j][j]);
        __syncthreads();
        if (tid > j && tid < 64) Ds[tid][j] /= Ds[j][j];
        __syncthreads();
        for (int e = tid; e < 4096; e += 256) {
            int i = e >> 6, kc = e & 63;
            if (i > j && kc > j && kc <= i) Ds[i][kc] -= Ds[i][j] * Ds[kc][j];
        }
        __syncthreads();
    }
    if (tid < 64) {
        int j = tid;
        float x[64];
#pragma unroll
        for (int i = 0; i < 64; i++) {
            float tv = (i == j) ? 1.0f : 0.0f;
#pragma unroll
            for (int k = 0; k < i; k++) tv -= Ds[i][k] * x[k];
            x[i] = tv / Ds[i][i];
        }
#pragma unroll
        for (int i = 0; i < 64; i++) writeV(c, i, j, x[i]);
    }
}

// ---------------- panel P = A21 * invL11^T (tf32) ----------------
__global__ __launch_bounds__(128) void k_pgemm(int kb) {
    __shared__ float Ah[64][20], Al[64][20], Bh[64][20], Bl[64][20];
    int c = blockIdx.y;
    int kbase = kb * 64;
    int i0 = kbase + 64 + blockIdx.x * 64;
    int tid = threadIdx.x, lane = tid & 31, wid = tid >> 5;
    int wy = wid >> 1, wx = wid & 1;
    int r = lane >> 2, q = lane & 3;
    float acc[2][4][4] = {};
    for (int k0 = 0; k0 < 64; k0 += 16) {
        __syncthreads();
#pragma unroll
        for (int t = 0; t < 8; t++) {
            int e = tid + 128 * t;
            int i = e >> 4, k = e & 15;
            float va = g_Sigma[c][i0 + i][kbase + k0 + k];
            float h = tf32_rn(va);
            Ah[i][k] = h; Al[i][k] = tf32_rn(va - h);
            float vb = g_V[c][kbase + i][kbase + k0 + k];
            h = tf32_rn(vb);
            Bh[i][k] = h; Bl[i][k] = tf32_rn(vb - h);
        }
        __syncthreads();
#pragma unroll
        for (int ks = 0; ks < 2; ks++) {
            int k8 = ks * 8;
            uint32_t ah[2][4], al[2][4], bh[4][2], bl[4][2];
#pragma unroll
            for (int ms = 0; ms < 2; ms++) {
                int mb = wy * 32 + ms * 16;
                ah[ms][0] = FB(Ah[mb + r][k8 + q]);     ah[ms][1] = FB(Ah[mb + 8 + r][k8 + q]);
                ah[ms][2] = FB(Ah[mb + r][k8 + 4 + q]); ah[ms][3] = FB(Ah[mb + 8 + r][k8 + 4 + q]);
                al[ms][0] = FB(Al[mb + r][k8 + q]);     al[ms][1] = FB(Al[mb + 8 + r][k8 + q]);
                al[ms][2] = FB(Al[mb + r][k8 + 4 + q]); al[ms][3] = FB(Al[mb + 8 + r][k8 + 4 + q]);
            }
#pragma unroll
            for (int nt = 0; nt < 4; nt++) {
                int nb = wx * 32 + nt * 8;
                bh[nt][0] = FB(Bh[nb + r][k8 + q]); bh[nt][1] = FB(Bh[nb + r][k8 + 4 + q]);
                bl[nt][0] = FB(Bl[nb + r][k8 + q]); bl[nt][1] = FB(Bl[nb + r][k8 + 4 + q]);
            }
#pragma unroll
            for (int ms = 0; ms < 2; ms++)
#pragma unroll
                for (int nt = 0; nt < 4; nt++)
                    MMA3(acc[ms][nt], ah[ms], bh[nt], al[ms], bl[nt]);
        }
    }
    __syncthreads();
#pragma unroll
    for (int ms = 0; ms < 2; ms++)
#pragma unroll
        for (int nt = 0; nt < 4; nt++) {
            int i = i0 + wy * 32 + ms * 16 + r;
            int j = kbase + wx * 32 + nt * 8 + 2 * q;
            float* d = acc[ms][nt];
            g_Sigma[c][i][j]         = d[0];
            g_Sigma[c][i][j + 1]     = d[1];
            g_Sigma[c][i + 8][j]     = d[2];
            g_Sigma[c][i + 8][j + 1] = d[3];
        }
}

// ---------------- trailing syrk (tf32) + fused next-diag factor/invert ------------
__global__ __launch_bounds__(128) void k_trail_mma(int kb) {
    __shared__ char buf[20480];
    float (*Ah)[20] = (float(*)[20])buf;
    float (*Al)[20] = (float(*)[20])(buf + 5120);
    float (*Bh)[20] = (float(*)[20])(buf + 10240);
    float (*Bl)[20] = (float(*)[20])(buf + 15360);
    int c = blockIdx.y;
    int pidx = blockIdx.x;
    int ti = kb + 1;
    while (pidx >= ti - kb) { pidx -= ti - kb; ti++; }
    int tj = kb + 1 + pidx;
    int i0 = ti * 64, j0 = tj * 64, kbase = kb * 64;
    int tid = threadIdx.x, lane = tid & 31, wid = tid >> 5;
    int wy = wid >> 1, wx = wid & 1;
    int r = lane >> 2, q = lane & 3;
    float acc[2][4][4] = {};
    for (int k0 = 0; k0 < 64; k0 += 16) {
        __syncthreads();
#pragma unroll
        for (int t = 0; t < 8; t++) {
            int e = tid + 128 * t;
            int i = e >> 4, k = e & 15;
            float va = g_Sigma[c][i0 + i][kbase + k0 + k];
            float h = tf32_rn(va);
            Ah[i][k] = h; Al[i][k] = tf32_rn(va - h);
            float vb = g_Sigma[c][j0 + i][kbase + k0 + k];
            h = tf32_rn(vb);
            Bh[i][k] = h; Bl[i][k] = tf32_rn(vb - h);
        }
        __syncthreads();
#pragma unroll
        for (int ks = 0; ks < 2; ks++) {
            int k8 = ks * 8;
            uint32_t ah[2][4], al[2][4], bh[4][2], bl[4][2];
#pragma unroll
            for (int ms = 0; ms < 2; ms++) {
                int mb = wy * 32 + ms * 16;
                ah[ms][0] = FB(Ah[mb + r][k8 + q]);     ah[ms][1] = FB(Ah[mb + 8 + r][k8 + q]);
                ah[ms][2] = FB(Ah[mb + r][k8 + 4 + q]); ah[ms][3] = FB(Ah[mb + 8 + r][k8 + 4 + q]);
                al[ms][0] = FB(Al[mb + r][k8 + q]);     al[ms][1] = FB(Al[mb + 8 + r][k8 + q]);
                al[ms][2] = FB(Al[mb + r][k8 + 4 + q]); al[ms][3] = FB(Al[mb + 8 + r][k8 + 4 + q]);
            }
#pragma unroll
            for (int nt = 0; nt < 4; nt++) {
                int nb = wx * 32 + nt * 8;
                bh[nt][0] = FB(Bh[nb + r][k8 + q]); bh[nt][1] = FB(Bh[nb + r][k8 + 4 + q]);
                bl[nt][0] = FB(Bl[nb + r][k8 + q]); bl[nt][1] = FB(Bl[nb + r][k8 + 4 + q]);
            }
#pragma unroll
            for (int ms = 0; ms < 2; ms++)
#pragma unroll
                for (int nt = 0; nt < 4; nt++)
                    MMA3(acc[ms][nt], ah[ms], bh[nt], al[ms], bl[nt]);
        }
    }
    __syncthreads();
#pragma unroll
    for (int ms = 0; ms < 2; ms++)
#pragma unroll
        for (int nt = 0; nt < 4; nt++) {
            int i = i0 + wy * 32 + ms * 16 + r;
            int j = j0 + wx * 32 + nt * 8 + 2 * q;
            float* d = acc[ms][nt];
            g_Sigma[c][i][j]         -= d[0];
            g_Sigma[c][i][j + 1]     -= d[1];
            g_Sigma[c][i + 8][j]     -= d[2];
            g_Sigma[c][i + 8][j + 1] -= d[3];
        }
    // block 0 owns tile (kb+1, kb+1): factor + invert it now (saves a launch)
    if (blockIdx.x == 0) {
        int base = (kb + 1) * 64;
        __syncthreads();
        float (*Ds)[65] = (float(*)[65])buf;
        for (int e = tid; e < 4096; e += 128)
            Ds[e >> 6][e & 63] = g_Sigma[c][base + (e >> 6)][base + (e & 63)];
        __syncthreads();
        for (int j = 0; j < 64; j++) {
            if (tid == 0) Ds[j][j] = sqrtf(Ds[j][j]);
            __syncthreads();
            if (tid > j && tid < 64) Ds[tid][j] /= Ds[j][j];
            __syncthreads();
            for (int e = tid; e < 4096; e += 128) {
                int i = e >> 6, kc = e & 63;
                if (i > j && kc > j && kc <= i) Ds[i][kc] -= Ds[i][j] * Ds[kc][j];
            }
            __syncthreads();
        }
        if (tid < 64) {
            int j = tid;
            float x[64];
#pragma unroll
            for (int i = 0; i < 64; i++) {
                float tv = (i == j) ? 1.0f : 0.0f;
#pragma unroll
                for (int k = 0; k < i; k++) tv -= Ds[i][k] * x[k];
                x[i] = tv / Ds[i][i];
            }
#pragma unroll
            for (int i = 0; i < 64; i++) writeV(c, base + i, base + j, x[i]);
        }
    }
}

// ---------------- recursive triinv stage GEMM 1: T1 = A21 * V11 -------------------
__global__ __launch_bounds__(128) void k_tri1(int h) {
    __shared__ float Ah[64][20], Al[64][20], Bh[16][72], Bl[16][72];
    int c = blockIdx.y;
    int tpr = h >> 6, t2 = tpr * tpr;
    int p = blockIdx.x / t2;
    int rem = blockIdx.x % t2;
    int mi = rem / tpr, ni = rem % tpr;
    int base = p * 2 * h;
    int r0 = base + h + mi * 64;
    int n0 = ni * 64;
    int tid = threadIdx.x, lane = tid & 31, wid = tid >> 5;
    int wy = wid >> 1, wx = wid & 1;
    int r = lane >> 2, q = lane & 3;
    float acc[2][4][4] = {};
    for (int k0 = 0; k0 < h; k0 += 16) {
        __syncthreads();
        for (int t = 0; t < 8; t++) {
            int e = tid + 128 * t;
            {
                int i = e >> 4, k = e & 15;
                float v = g_Sigma[c][r0 + i][base + k0 + k];
                float hh = tf32_rn(v);
                Ah[i][k] = hh; Al[i][k] = tf32_rn(v - hh);
            }
            {
                int k = e >> 6, j = e & 63;
                float v = ((k0 + k) >= (n0 + j)) ? g_V[c][base + k0 + k][base + n0 + j] : 0.f;
                float hh = tf32_rn(v);
                Bh[k][j] = hh; Bl[k][j] = tf32_rn(v - hh);
            }
        }
        __syncthreads();
#pragma unroll
        for (int ks = 0; ks < 2; ks++) {
            int k8 = ks * 8;
            uint32_t ah[2][4], al[2][4], bh[4][2], bl[4][2];
#pragma unroll
            for (int ms = 0; ms < 2; ms++) {
                int mb = wy * 32 + ms * 16;
                ah[ms][0] = FB(Ah[mb + r][k8 + q]);     ah[ms][1] = FB(Ah[mb + 8 + r][k8 + q]);
                ah[ms][2] = FB(Ah[mb + r][k8 + 4 + q]); ah[ms][3] = FB(Ah[mb + 8 + r][k8 + 4 + q]);
                al[ms][0] = FB(Al[mb + r][k8 + q]);     al[ms][1] = FB(Al[mb + 8 + r][k8 + q]);
                al[ms][2] = FB(Al[mb + r][k8 + 4 + q]); al[ms][3] = FB(Al[mb + 8 + r][k8 + 4 + q]);
            }
#pragma unroll
            for (int nt = 0; nt < 4; nt++) {
                int nb = wx * 32 + nt * 8;
                bh[nt][0] = FB(Bh[k8 + q][nb + r]); bh[nt][1] = FB(Bh[k8 + 4 + q][nb + r]);
                bl[nt][0] = FB(Bl[k8 + q][nb + r]); bl[nt][1] = FB(Bl[k8 + 4 + q][nb + r]);
            }
#pragma unroll
            for (int ms = 0; ms < 2; ms++)
#pragma unroll
                for (int nt = 0; nt < 4; nt++)
                    MMA3(acc[ms][nt], ah[ms], bh[nt], al[ms], bl[nt]);
        }
    }
    int pb = p * h * h;
#pragma unroll
    for (int ms = 0; ms < 2; ms++)
#pragma unroll
        for (int nt = 0; nt < 4; nt++) {
            int il = mi * 64 + wy * 32 + ms * 16 + r;
            int jl = n0 + wx * 32 + nt * 8 + 2 * q;
            float* d = acc[ms][nt];
            g_T1[c][pb + il * h + jl]           = d[0];
            g_T1[c][pb + il * h + jl + 1]       = d[1];
            g_T1[c][pb + (il + 8) * h + jl]     = d[2];
            g_T1[c][pb + (il + 8) * h + jl + 1] = d[3];
        }
}

// ---------------- stage GEMM 2: V21 = -V22 * T1 (writes V + bf16) -----------------
__global__ __launch_bounds__(128) void k_tri2(int h) {
    __shared__ float Ah[64][20], Al[64][20], Bh[16][72], Bl[16][72];
    int c = blockIdx.y;
    int tpr = h >> 6, t2 = tpr * tpr;
    int p = blockIdx.x / t2;
    int rem = blockIdx.x % t2;
    int mi = rem / tpr, ni = rem % tpr;
    int base = p * 2 * h;
    int rv = base + h;            // V22 block origin
    int n0 = ni * 64;
    int tid = threadIdx.x, lane = tid & 31, wid = tid >> 5;
    int wy = wid >> 1, wx = wid & 1;
    int r = lane >> 2, q = lane & 3;
    int pb = p * h * h;
    float acc[2][4][4] = {};
    for (int k0 = 0; k0 < h; k0 += 16) {
        __syncthreads();
        for (int t = 0; t < 8; t++) {
            int e = tid + 128 * t;
            {
                int i = e >> 4, k = e & 15;
                float v = ((mi * 64 + i) >= (k0 + k)) ? g_V[c][rv + mi * 64 + i][rv + k0 + k] : 0.f;
                float hh = tf32_rn(v);
                Ah[i][k] = hh; Al[i][k] = tf32_rn(v - hh);
            }
            {
                int k = e >> 6, j = e & 63;
                float v = g_T1[c][pb + (k0 + k) * h + n0 + j];
                float hh = tf32_rn(v);
                Bh[k][j] = hh; Bl[k][j] = tf32_rn(v - hh);
            }
        }
        __syncthreads();
#pragma unroll
        for (int ks = 0; ks < 2; ks++) {
            int k8 = ks * 8;
            uint32_t ah[2][4], al[2][4], bh[4][2], bl[4][2];
#pragma unroll
            for (int ms = 0; ms < 2; ms++) {
                int mb = wy * 32 + ms * 16;
                ah[ms][0] = FB(Ah[mb + r][k8 + q]);     ah[ms][1] = FB(Ah[mb + 8 + r][k8 + q]);
                ah[ms][2] = FB(Ah[mb + r][k8 + 4 + q]); ah[ms][3] = FB(Ah[mb + 8 + r][k8 + 4 + q]);
                al[ms][0] = FB(Al[mb + r][k8 + q]);     al[ms][1] = FB(Al[mb + 8 + r][k8 + q]);
                al[ms][2] = FB(Al[mb + r][k8 + 4 + q]); al[ms][3] = FB(Al[mb + 8 + r][k8 + 4 + q]);
            }
#pragma unroll
            for (int nt = 0; nt < 4; nt++) {
                int nb = wx * 32 + nt * 8;
                bh[nt][0] = FB(Bh[k8 + q][nb + r]); bh[nt][1] = FB(Bh[k8 + 4 + q][nb + r]);
                bl[nt][0] = FB(Bl[k8 + q][nb + r]); bl[nt][1] = FB(Bl[k8 + 4 + q][nb + r]);
            }
#pragma unroll
            for (int ms = 0; ms < 2; ms++)
#pragma unroll
                for (int nt = 0; nt < 4; nt++)
                    MMA3(acc[ms][nt], ah[ms], bh[nt], al[ms], bl[nt]);
        }
    }
#pragma unroll
    for (int ms = 0; ms < 2; ms++)
#pragma unroll
        for (int nt = 0; nt < 4; nt++) {
            int ig = rv + mi * 64 + wy * 32 + ms * 16 + r;
            int jg = base + n0 + wx * 32 + nt * 8 + 2 * q;
            float* d = acc[ms][nt];
            writeV(c, ig, jg, -d[0]);
            writeV(c, ig, jg + 1, -d[1]);
            writeV(c, ig + 8, jg, -d[2]);
            writeV(c, ig + 8, jg + 1, -d[3]);
        }
}

// ---------------- conversions / small vec kernels ----------------
__global__ void k_cvt_xq(const float* __restrict__ Xq) {
    int i = blockIdx.x * 256 + threadIdx.x;
    float x = Xq[i];
    __nv_bfloat16 h = __float2bfloat16(x);
    ((__nv_bfloat16*)g_Xqh)[i] = h;
    ((__nv_bfloat16*)g_Xql)[i] = __float2bfloat16(x - __bfloat162float(h));
}
__global__ void k_svec() {
    int c = blockIdx.y;
    int warp = threadIdx.x >> 5, lane = threadIdx.x & 31;
    int row = blockIdx.x * 8 + warp;
    float acc = 0.f;
    for (int k = lane; k <= row; k += 32) acc += g_V[c][row][k] * g_mu[c][k];
    for (int o = 16; o > 0; o >>= 1) acc += __shfl_down_sync(0xffffffffu, acc, o);
    if (lane == 0) g_s[c][row] = acc;
}
__global__ void k_scalars() {
    int c = blockIdx.x;
    __shared__ float r1[256], r2[256];
    float a = 0.f, b = 0.f;
    for (int k = threadIdx.x; k < D; k += 256) {
        float sv = g_s[c][k];  a += sv * sv;
        float mv = g_mu[c][k]; b += mv * mv;
    }
    r1[threadIdx.x] = a; r2[threadIdx.x] = b;
    __syncthreads();
    for (int o = 128; o > 0; o >>= 1) {
        if (threadIdx.x < o) { r1[threadIdx.x] += r1[threadIdx.x + o]; r2[threadIdx.x] += r2[threadIdx.x + o]; }
        __syncthreads();
    }
    if (threadIdx.x == 0) { g_ssc[c] = r1[0]; g_mmc[c] = r2[0]; }
}
__global__ void k_nx(const float* __restrict__ Xq) {
    int warp = threadIdx.x >> 5, lane = threadIdx.x & 31;
    int row = blockIdx.x * 8 + warp;
    float acc = 0.f;
    for (int k = lane; k < D; k += 32) { float v = Xq[(size_t)row * D + k]; acc += v * v; }
    for (int o = 16; o > 0; o >>= 1) acc += __shfl_down_sync(0xffffffffu, acc, o);
    if (lane == 0) g_nx[row] = acc;
}
__global__ void k_xm(const float* __restrict__ Xq) {
    int warp = threadIdx.x >> 5, lane = threadIdx.x & 31;
    int row = blockIdx.x * 8 + warp;
    float acc[CLS];
#pragma unroll
    for (int c = 0; c < CLS; c++) acc[c] = 0.f;
    for (int k = lane; k < D; k += 32) {
        float v = Xq[(size_t)row * D + k];
#pragma unroll
        for (int c = 0; c < CLS; c++) acc[c] += v * g_mu[c][k];
    }
#pragma unroll
    for (int c = 0; c < CLS; c++) {
        float a = acc[c];
        for (int o = 16; o > 0; o >>= 1) a += __shfl_down_sync(0xffffffffu, a, o);
        if (lane == 0) g_xm[row][c] = a;
    }
}

// ---------------- logits (bf16-split mma) ----------------
#define LG_ROWB 144
#define LG_SMEM 55296
__global__ __launch_bounds__(256) void k_logits_mma(float* __restrict__ out) {
    extern __shared__ char smem[];
    char* sAh = smem;
    char* sAl = smem + 18432;
    char* sBh = smem + 36864;
    char* sBl = smem + 46080;
    int tid = threadIdx.x, lane = tid & 31, wid = tid >> 5;
    int wm = wid >> 1, wn = wid & 1;
    int c = blockIdx.y, m0 = blockIdx.x * 128;
    uint32_t aH = smem_u32(sAh) + (uint32_t)((wm * 32 + (lane & 15)) * LG_ROWB + (lane >> 4) * 16);
    uint32_t aL = aH + 18432;
    uint32_t bH = smem_u32(sBh) + (uint32_t)((wn * 32 + ((lane & 16) >> 1) + (lane & 7)) * LG_ROWB
                                             + ((lane & 8) ? 16 : 0));
    uint32_t bL = bH + 9216;
    float q2[2][2] = {}, qb[2][2] = {};
    for (int jt = 0; jt < NT; jt++) {
        float acc[2][4][4];
#pragma unroll
        for (int ms = 0; ms < 2; ms++)
#pragma unroll
            for (int nt = 0; nt < 4; nt++)
#pragma unroll
                for (int q = 0; q < 4; q++) acc[ms][nt][q] = 0.f;
        for (int kt = 0; kt <= jt; kt++) {
            __syncthreads();
#pragma unroll
            for (int i = 0; i < 4; i++) {
                int idx = tid + 256 * i;
                int r = idx >> 3, c8 = idx & 7;
                int so = r * LG_ROWB + c8 * 16;
                *(uint4*)(sAh + so) = *(const uint4*)&g_Xqh[m0 + r][kt * 64 + c8 * 8];
                *(uint4*)(sAl + so) = *(const uint4*)&g_Xql[m0 + r][kt * 64 + c8 * 8];
            }
#pragma unroll
            for (int i = 0; i < 2; i++) {
                int idx = tid + 256 * i;
                int r = idx >> 3, c8 = idx & 7;
                int so = r * LG_ROWB + c8 * 16;
                *(uint4*)(sBh + so) = *(const uint4*)&g_Vh[c][jt * 64 + r][kt * 64 + c8 * 8];
                *(uint4*)(sBl + so) = *(const uint4*)&g_Vl[c][jt * 64 + r][kt * 64 + c8 * 8];
            }
            __syncthreads();
#pragma unroll
            for (int ks = 0; ks < 4; ks++) {
                uint32_t ah[2][4], al[2][4], bh[8], bl[8];
                ldsm4(ah[0], aH + ks * 32);
                ldsm4(ah[1], aH + 16 * LG_ROWB + ks * 32);
                ldsm4(al[0], aL + ks * 32);
                ldsm4(al[1], aL + 16 * LG_ROWB + ks * 32);
                ldsm4(&bh[0], bH + ks * 32);
                ldsm4(&bh[4], bH + 16 * LG_ROWB + ks * 32);
                ldsm4(&bl[0], bL + ks * 32);
                ldsm4(&bl[4], bL + 16 * LG_ROWB + ks * 32);
#pragma unroll
                for (int ms = 0; ms < 2; ms++)
#pragma unroll
                    for (int nt = 0; nt < 4; nt++) {
                        float* d = acc[ms][nt];
                        mma16816(d, ah[ms], &bh[nt * 2]);
                        mma16816(d, al[ms], &bh[nt * 2]);
                        mma16816(d, ah[ms], &bl[nt * 2]);
                    }
            }
        }
#pragma unroll
        for (int ms = 0; ms < 2; ms++)
#pragma unroll
            for (int nt = 0; nt < 4; nt++) {
                int jc = jt * 64 + wn * 32 + nt * 8 + 2 * (lane & 3);
                float s0 = g_s[c][jc], s1 = g_s[c][jc + 1];
                float* d = acc[ms][nt];
                q2[ms][0] += d[0] * d[0] + d[1] * d[1];
                qb[ms][0] += d[0] * s0 + d[1] * s1;
                q2[ms][1] += d[2] * d[2] + d[3] * d[3];
                qb[ms][1] += d[2] * s0 + d[3] * s1;
            }
    }
    __syncthreads();
    float* rq = (float*)smem;
    float* rb = (float*)(smem + 4096);
    int slot = wn * 4 + (lane & 3);
    int g = lane >> 2;
#pragma unroll
    for (int ms = 0; ms < 2; ms++)
#pragma unroll
        for (int go = 0; go < 2; go++) {
            int row = wm * 32 + ms * 16 + go * 8 + g;
            rq[row * 8 + slot] = q2[ms][go];
            rb[row * 8 + slot] = qb[ms][go];
        }
    __syncthreads();
    if (tid < 128) {
        float q2r = 0.f, qbr = 0.f;
#pragma unroll
        for (int t = 0; t < 8; t++) { q2r += rq[tid * 8 + t]; qbr += rb[tid * 8 + t]; }
        int row = m0 + tid;
        float dq = g_nx[row] - 2.f * g_xm[row][c] + g_mmc[c];
        float qm = q2r - 2.f * qbr + g_ssc[c];
        out[(size_t)row * CLS + c] = -0.9f * qm - 0.1f * dq;
    }
}

// ---------------- launch (single stream) ----------------
extern "C" void kernel_launch(void* const* d_in, const int* in_sizes, int n_in,
                              void* d_out, int out_size) {
    const float* X     = (const float*)d_in[0];
    const int*   y     = (const int*)d_in[1];
    const float* Xq    = (const float*)d_in[2];
    const float* m     = (const float*)d_in[3];
    const float* kappa = (const float*)d_in[4];
    const float* nu    = (const float*)d_in[5];
    const float* td    = (const float*)d_in[6];
    const float* tl    = (const float*)d_in[7];
    float* out = (float*)d_out;

    cudaFuncSetAttribute(k_logits_mma, cudaFuncAttributeMaxDynamicSharedMemorySize, LG_SMEM);

    k_stats1<<<dim3(8, 8), 128>>>(X, y);
    k_sort_params<<<1, 32>>>(y, kappa, nu);
    k_stats2<<<64, 256>>>();
    k_mu<<<dim3(4, CLS), 256>>>(m);
    k_cvt_xq<<<16384, 256>>>(Xq);
    k_buildL<<<D, 256>>>(td, tl);
    k_base<<<dim3(NT, NT), 256>>>(m);
    k_nx<<<MQ / 8, 256>>>(Xq);
    k_xm<<<MQ / 8, 256>>>(Xq);

    k_sigma_mma<<<dim3(8, 16, CLS), 256>>>(X);
    k_chol_diag0<<<CLS, 256>>>();
    for (int kb = 0; kb < NT - 1; kb++) {
        int T = NT - 1 - kb;
        k_pgemm<<<dim3(T, CLS), 128>>>(kb);
        k_trail_mma<<<dim3(T * (T + 1) / 2, CLS), 128>>>(kb);
    }
    for (int s = 0; s < 4; s++) {
        int h = 64 << s;
        int tpr = h >> 6;
        int tiles = (D / (2 * h)) * tpr * tpr;
        k_tri1<<<dim3(tiles, CLS), 128>>>(h);
        k_tri2<<<dim3(tiles, CLS), 128>>>(h);
    }
    k_svec<<<dim3(D / 8, CLS), 256>>>();
    k_scalars<<<CLS, 256>>>();
    k_logits_mma<<<dim3(MQ / 128, CLS), 256, LG_SMEM>>>(out);
}

// round 8
// speedup vs baseline: 2.9799x; 1.0297x over previous
#include <cuda_runtime.h>
#include <cuda_bf16.h>
#include <math.h>
#include <stdint.h>

#define D      1024
#define CLS    16
#define NSAMP  4096
#define MQ     4096
#define NT     16

__device__ float g_Sigma[CLS][D][D];
__device__ float g_V[CLS][D][D];
__device__ float g_T1[CLS][262144];
__device__ float g_Base[D][D];
__device__ float g_L[D][D];
__device__ float g_part[8][CLS][D];
__device__ float g_mu[CLS][D];
__device__ float g_s[CLS][D];
__device__ float g_nx[MQ];
__device__ float g_xm[MQ][CLS];
__device__ float g_ssc[CLS];
__device__ float g_mmc[CLS];
__device__ int   g_cnt[CLS];
__device__ int   g_cntp[8][CLS];
__device__ int   g_start[CLS];
__device__ int   g_idx[NSAMP];
__device__ float g_kap;
__device__ float g_coef[CLS];
__device__ float g_invscale[CLS];

__device__ __nv_bfloat16 g_Xqh[MQ][D];
__device__ __nv_bfloat16 g_Xql[MQ][D];
__device__ __nv_bfloat16 g_Vh[CLS][D][D];
__device__ __nv_bfloat16 g_Vl[CLS][D][D];

__device__ __forceinline__ uint32_t smem_u32(const void* p) {
    uint32_t a;
    asm("{ .reg .u64 t; cvta.to.shared.u64 t, %1; cvt.u32.u64 %0, t; }" : "=r"(a) : "l"(p));
    return a;
}
__device__ __forceinline__ void ldsm4(uint32_t* r, uint32_t a) {
    asm volatile("ldmatrix.sync.aligned.m8n8.x4.shared.b16 {%0,%1,%2,%3}, [%4];"
                 : "=r"(r[0]), "=r"(r[1]), "=r"(r[2]), "=r"(r[3]) : "r"(a));
}
__device__ __forceinline__ void mma16816(float* d, const uint32_t* a, const uint32_t* b) {
    asm volatile(
        "mma.sync.aligned.m16n8k16.row.col.f32.bf16.bf16.f32 "
        "{%0,%1,%2,%3}, {%4,%5,%6,%7}, {%8,%9}, {%0,%1,%2,%3};"
        : "+f"(d[0]), "+f"(d[1]), "+f"(d[2]), "+f"(d[3])
        : "r"(a[0]), "r"(a[1]), "r"(a[2]), "r"(a[3]), "r"(b[0]), "r"(b[1]));
}
__device__ __forceinline__ void mma_tf32(float* d, const uint32_t* a, const uint32_t* b) {
    asm volatile(
        "mma.sync.aligned.m16n8k8.row.col.f32.tf32.tf32.f32 "
        "{%0,%1,%2,%3}, {%4,%5,%6,%7}, {%8,%9}, {%0,%1,%2,%3};"
        : "+f"(d[0]), "+f"(d[1]), "+f"(d[2]), "+f"(d[3])
        : "r"(a[0]), "r"(a[1]), "r"(a[2]), "r"(a[3]), "r"(b[0]), "r"(b[1]));
}
__device__ __forceinline__ float tf32_rn(float x) {
    uint32_t u;
    asm("cvt.rna.tf32.f32 %0, %1;" : "=r"(u) : "f"(x));
    return __uint_as_float(u);
}
__device__ __forceinline__ void cpa16(uint32_t s, const void* g) {
    asm volatile("{ .reg .u64 gg; cvta.to.global.u64 gg, %1; cp.async.ca.shared.global [%0], [gg], 16; }"
                 :: "r"(s), "l"(g) : "memory");
}
#define CPA_COMMIT asm volatile("cp.async.commit_group;" ::: "memory")
#define CPA_WAIT1  asm volatile("cp.async.wait_group 1;" ::: "memory")
#define CPA_WAIT0  asm volatile("cp.async.wait_group 0;" ::: "memory")
#define FB(x) (__float_as_uint(x))
#define MMA3(d, ah, bh, al, bl) { mma_tf32(d, ah, bh); mma_tf32(d, ah, bl); mma_tf32(d, al, bh); }

__device__ __forceinline__ void writeV(int c, int i, int j, float v) {
    g_V[c][i][j] = v;
    __nv_bfloat16 hb = __float2bfloat16(v);
    g_Vh[c][i][j] = hb;
    g_Vl[c][i][j] = __float2bfloat16(v - __bfloat162float(hb));
}

// ---------------- stats ----------------
__global__ void k_stats1(const float* __restrict__ X, const int* __restrict__ y) {
    __shared__ int sy[512];
    int tid = threadIdx.x;
    int r0 = blockIdx.y * 512;
    for (int n = tid; n < 512; n += 128) sy[n] = y[r0 + n];
    __syncthreads();
    int k = blockIdx.x * 128 + tid;
    float acc[CLS];
#pragma unroll
    for (int c = 0; c < CLS; c++) acc[c] = 0.f;
    for (int n = 0; n < 512; n++) {
        float v = X[(size_t)(r0 + n) * D + k];
        int cls = sy[n];
#pragma unroll
        for (int c = 0; c < CLS; c++) acc[c] += (cls == c) ? v : 0.f;
    }
#pragma unroll
    for (int c = 0; c < CLS; c++) g_part[blockIdx.y][c][k] = acc[c];
    if (blockIdx.x == 0) {
        __shared__ int scnt[CLS];
        if (tid < CLS) scnt[tid] = 0;
        __syncthreads();
        for (int n = tid; n < 512; n += 128) atomicAdd(&scnt[sy[n]], 1);
        __syncthreads();
        if (tid < CLS) g_cntp[blockIdx.y][tid] = scnt[tid];
    }
}
__global__ void k_sort_params(const int* __restrict__ y, const float* __restrict__ kappa,
                              const float* __restrict__ nu) {
    __shared__ int s_start[CLS];
    int lane = threadIdx.x;
    if (lane == 0) {
        int s = 0;
        for (int c = 0; c < CLS; c++) {
            int t = 0;
            for (int r = 0; r < 8; r++) t += g_cntp[r][c];
            g_cnt[c] = t; g_start[c] = s; s_start[c] = s; s += t;
        }
        float kap = fabsf(kappa[0]) + 1e-6f;
        g_kap = kap;
        float nu_ = fmaxf(nu[0], (float)(D - 1) + 1e-6f);
        for (int c = 0; c < CLS; c++) {
            float Nj = (float)g_cnt[c];
            g_coef[c] = kap + Nj;
            g_invscale[c] = 1.0f / (nu_ + Nj + (float)D + 2.0f);
        }
    }
    __syncthreads();
    int off[CLS];
#pragma unroll
    for (int c = 0; c < CLS; c++) off[c] = s_start[c];
    unsigned below = (1u << lane) - 1u;
    for (int n0 = 0; n0 < NSAMP; n0 += 32) {
        int v = y[n0 + lane];
#pragma unroll
        for (int c = 0; c < CLS; c++) {
            unsigned m = __ballot_sync(0xffffffffu, v == c);
            if (v == c) g_idx[off[c] + __popc(m & below)] = n0 + lane;
            off[c] += __popc(m);
        }
    }
}
// merged: partial-sum reduce + mu
__global__ void k_mu(const float* __restrict__ m) {
    int c = blockIdx.y;
    int k = blockIdx.x * blockDim.x + threadIdx.x;
    float s = 0.f;
#pragma unroll
    for (int r = 0; r < 8; r++) s += g_part[r][c][k];
    g_mu[c][k] = (g_kap * m[k] + s) / g_coef[c];
}
__global__ void k_buildL(const float* __restrict__ td, const float* __restrict__ tl) {
    int i = blockIdx.x;
    for (int k = threadIdx.x; k < D; k += blockDim.x) {
        float v;
        if (k < i) v = tl[(size_t)i * D + k];
        else if (k == i) v = fabsf(td[i]);
        else v = 0.f;
        g_L[i][k] = v;
    }
}

// ---------------- Base = L L^T + kap m m^T (triangular skip) ----------------
__global__ __launch_bounds__(256) void k_base(const float* __restrict__ m) {
    __shared__ float As[16][65];
    __shared__ float Bs[16][65];
    int i0 = blockIdx.x * 64, j0 = blockIdx.y * 64;
    int tid = threadIdx.x, tx = tid & 15, ty = tid >> 4;
    float acc[4][4] = {};
    int kend = ((i0 < j0) ? i0 : j0) + 64;
    for (int k0 = 0; k0 < kend; k0 += 16) {
#pragma unroll
        for (int t = 0; t < 4; t++) {
            int idx = tid + 256 * t;
            int ii = idx >> 4, kk = idx & 15;
            As[kk][ii] = g_L[i0 + ii][k0 + kk];
            Bs[kk][ii] = g_L[j0 + ii][k0 + kk];
        }
        __syncthreads();
#pragma unroll
        for (int kk = 0; kk < 16; kk++) {
            float a[4], b[4];
#pragma unroll
            for (int q = 0; q < 4; q++) a[q] = As[kk][4 * ty + q];
#pragma unroll
            for (int q = 0; q < 4; q++) b[q] = Bs[kk][4 * tx + q];
#pragma unroll
            for (int p = 0; p < 4; p++)
#pragma unroll
                for (int q = 0; q < 4; q++) acc[p][q] += a[p] * b[q];
        }
        __syncthreads();
    }
    float kap = g_kap;
#pragma unroll
    for (int p = 0; p < 4; p++) {
        int i = i0 + 4 * ty + p;
        float mi = m[i];
#pragma unroll
        for (int q = 0; q < 4; q++) {
            int j = j0 + 4 * tx + q;
            g_Base[i][j] = acc[p][q] + kap * mi * m[j];
        }
    }
}

// ---------------- Sigma via tf32-split mma ----------------
__global__ __launch_bounds__(256) void k_sigma_mma(const float* __restrict__ X) {
    __shared__ float Ah[16][136], Al[16][136];
    __shared__ float Bh[16][72],  Bl[16][72];
    int c = blockIdx.z;
    int i0 = blockIdx.x * 128, j0 = blockIdx.y * 64;
    int tid = threadIdx.x, lane = tid & 31, wid = tid >> 5;
    int wm = wid >> 1, wn = wid & 1;
    int r = lane >> 2, q = lane & 3;
    int cnt = g_cnt[c], start = g_start[c];
    float acc[2][4][4] = {};
    int kmax = (cnt + 15) & ~15;
    for (int k0 = 0; k0 < kmax; k0 += 16) {
        __syncthreads();
#pragma unroll
        for (int t = 0; t < 8; t++) {
            int e = tid + 256 * t;
            int kk = e >> 7, col = e & 127;
            int krow = k0 + kk;
            float v = (krow < cnt) ? X[(size_t)g_idx[start + krow] * D + i0 + col] : 0.f;
            float h = tf32_rn(v);
            Ah[kk][col] = h; Al[kk][col] = tf32_rn(v - h);
        }
#pragma unroll
        for (int t = 0; t < 4; t++) {
            int e = tid + 256 * t;
            int kk = e >> 6, col = e & 63;
            int krow = k0 + kk;
            float v = (krow < cnt) ? X[(size_t)g_idx[start + krow] * D + j0 + col] : 0.f;
            float h = tf32_rn(v);
            Bh[kk][col] = h; Bl[kk][col] = tf32_rn(v - h);
        }
        __syncthreads();
#pragma unroll
        for (int ks = 0; ks < 2; ks++) {
            int k8 = ks * 8;
            uint32_t ah[2][4], al[2][4], bh[4][2], bl[4][2];
#pragma unroll
            for (int ms = 0; ms < 2; ms++) {
                int mb = wm * 32 + ms * 16;
                ah[ms][0] = FB(Ah[k8 + q][mb + r]);     ah[ms][1] = FB(Ah[k8 + q][mb + 8 + r]);
                ah[ms][2] = FB(Ah[k8 + 4 + q][mb + r]); ah[ms][3] = FB(Ah[k8 + 4 + q][mb + 8 + r]);
                al[ms][0] = FB(Al[k8 + q][mb + r]);     al[ms][1] = FB(Al[k8 + q][mb + 8 + r]);
                al[ms][2] = FB(Al[k8 + 4 + q][mb + r]); al[ms][3] = FB(Al[k8 + 4 + q][mb + 8 + r]);
            }
#pragma unroll
            for (int nt = 0; nt < 4; nt++) {
                int nb = wn * 32 + nt * 8;
                bh[nt][0] = FB(Bh[k8 + q][nb + r]); bh[nt][1] = FB(Bh[k8 + 4 + q][nb + r]);
                bl[nt][0] = FB(Bl[k8 + q][nb + r]); bl[nt][1] = FB(Bl[k8 + 4 + q][nb + r]);
            }
#pragma unroll
            for (int ms = 0; ms < 2; ms++)
#pragma unroll
                for (int nt = 0; nt < 4; nt++)
                    MMA3(acc[ms][nt], ah[ms], bh[nt], al[ms], bl[nt]);
        }
    }
    float coef = g_coef[c], inv = g_invscale[c];
#pragma unroll
    for (int ms = 0; ms < 2; ms++)
#pragma unroll
        for (int nt = 0; nt < 4; nt++) {
            int i = i0 + wm * 32 + ms * 16 + r;
            int j = j0 + wn * 32 + nt * 8 + 2 * q;
            float* d = acc[ms][nt];
            float mui = g_mu[c][i], mui8 = g_mu[c][i + 8];
            float mj0 = g_mu[c][j], mj1 = g_mu[c][j + 1];
            g_Sigma[c][i][j]         = (g_Base[i][j]         + d[0] - coef * mui  * mj0) * inv;
            g_Sigma[c][i][j + 1]     = (g_Base[i][j + 1]     + d[1] - coef * mui  * mj1) * inv;
            g_Sigma[c][i + 8][j]     = (g_Base[i + 8][j]     + d[2] - coef * mui8 * mj0) * inv;
            g_Sigma[c][i + 8][j + 1] = (g_Base[i + 8][j + 1] + d[3] - coef * mui8 * mj1) * inv;
        }
}

// ---------------- initial diag: factor tile 0 + invert -> V diag (+bf16) ---------
__global__ __launch_bounds__(256) void k_chol_diag0() {
    __shared__ float Ds[64][65];
    int c = blockIdx.x;
    int tid = threadIdx.x;
    for (int e = tid; e < 4096; e += 256)
        Ds[e >> 6][e & 63] = g_Sigma[c][e >> 6][e & 63];
    __syncthreads();
    for (int j = 0; j < 64; j++) {
        if (tid == 0) Ds[j][j] = sqrtf(Ds[j][j]);
        __syncthreads();
        if (tid > j && tid < 64) Ds[tid][j] /= Ds[j][j];
        __syncthreads();
        for (int e = tid; e < 4096; e += 256) {
            int i = e >> 6, kc = e & 63;
            if (i > j && kc > j && kc <= i) Ds[i][kc] -= Ds[i][j] * Ds[kc][j];
        }
        __syncthreads();
    }
    if (tid < 64) {
        int j = tid;
        float x[64];
#pragma unroll
        for (int i = 0; i < 64; i++) {
            float tv = (i == j) ? 1.0f : 0.0f;
#pragma unroll
            for (int k = 0; k < i; k++) tv -= Ds[i][k] * x[k];
            x[i] = tv / Ds[i][i];
        }
#pragma unroll
        for (int i = 0; i < 64; i++) writeV(c, i, j, x[i]);
    }
}

// ---------------- panel P = A21 * invL11^T (tf32) ----------------
__global__ __launch_bounds__(128) void k_pgemm(int kb) {
    __shared__ float Ah[64][20], Al[64][20], Bh[64][20], Bl[64][20];
    int c = blockIdx.y;
    int kbase = kb * 64;
    int i0 = kbase + 64 + blockIdx.x * 64;
    int tid = threadIdx.x, lane = tid & 31, wid = tid >> 5;
    int wy = wid >> 1, wx = wid & 1;
    int r = lane >> 2, q = lane & 3;
    float acc[2][4][4] = {};
    for (int k0 = 0; k0 < 64; k0 += 16) {
        __syncthreads();
#pragma unroll
        for (int t = 0; t < 8; t++) {
            int e = tid + 128 * t;
            int i = e >> 4, k = e & 15;
            float va = g_Sigma[c][i0 + i][kbase + k0 + k];
            float h = tf32_rn(va);
            Ah[i][k] = h; Al[i][k] = tf32_rn(va - h);
            float vb = g_V[c][kbase + i][kbase + k0 + k];
            h = tf32_rn(vb);
            Bh[i][k] = h; Bl[i][k] = tf32_rn(vb - h);
        }
        __syncthreads();
#pragma unroll
        for (int ks = 0; ks < 2; ks++) {
            int k8 = ks * 8;
            uint32_t ah[2][4], al[2][4], bh[4][2], bl[4][2];
#pragma unroll
            for (int ms = 0; ms < 2; ms++) {
                int mb = wy * 32 + ms * 16;
                ah[ms][0] = FB(Ah[mb + r][k8 + q]);     ah[ms][1] = FB(Ah[mb + 8 + r][k8 + q]);
                ah[ms][2] = FB(Ah[mb + r][k8 + 4 + q]); ah[ms][3] = FB(Ah[mb + 8 + r][k8 + 4 + q]);
                al[ms][0] = FB(Al[mb + r][k8 + q]);     al[ms][1] = FB(Al[mb + 8 + r][k8 + q]);
                al[ms][2] = FB(Al[mb + r][k8 + 4 + q]); al[ms][3] = FB(Al[mb + 8 + r][k8 + 4 + q]);
            }
#pragma unroll
            for (int nt = 0; nt < 4; nt++) {
                int nb = wx * 32 + nt * 8;
                bh[nt][0] = FB(Bh[nb + r][k8 + q]); bh[nt][1] = FB(Bh[nb + r][k8 + 4 + q]);
                bl[nt][0] = FB(Bl[nb + r][k8 + q]); bl[nt][1] = FB(Bl[nb + r][k8 + 4 + q]);
            }
#pragma unroll
            for (int ms = 0; ms < 2; ms++)
#pragma unroll
                for (int nt = 0; nt < 4; nt++)
                    MMA3(acc[ms][nt], ah[ms], bh[nt], al[ms], bl[nt]);
        }
    }
    __syncthreads();
#pragma unroll
    for (int ms = 0; ms < 2; ms++)
#pragma unroll
        for (int nt = 0; nt < 4; nt++) {
            int i = i0 + wy * 32 + ms * 16 + r;
            int j = kbase + wx * 32 + nt * 8 + 2 * q;
            float* d = acc[ms][nt];
            g_Sigma[c][i][j]         = d[0];
            g_Sigma[c][i][j + 1]     = d[1];
            g_Sigma[c][i + 8][j]     = d[2];
            g_Sigma[c][i + 8][j + 1] = d[3];
        }
}

// ---------------- trailing syrk (tf32) + fused next-diag factor/invert ------------
__global__ __launch_bounds__(128) void k_trail_mma(int kb) {
    __shared__ char buf[20480];
    float (*Ah)[20] = (float(*)[20])buf;
    float (*Al)[20] = (float(*)[20])(buf + 5120);
    float (*Bh)[20] = (float(*)[20])(buf + 10240);
    float (*Bl)[20] = (float(*)[20])(buf + 15360);
    int c = blockIdx.y;
    int pidx = blockIdx.x;
    int ti = kb + 1;
    while (pidx >= ti - kb) { pidx -= ti - kb; ti++; }
    int tj = kb + 1 + pidx;
    int i0 = ti * 64, j0 = tj * 64, kbase = kb * 64;
    int tid = threadIdx.x, lane = tid & 31, wid = tid >> 5;
    int wy = wid >> 1, wx = wid & 1;
    int r = lane >> 2, q = lane & 3;
    float acc[2][4][4] = {};
    for (int k0 = 0; k0 < 64; k0 += 16) {
        __syncthreads();
#pragma unroll
        for (int t = 0; t < 8; t++) {
            int e = tid + 128 * t;
            int i = e >> 4, k = e & 15;
            float va = g_Sigma[c][i0 + i][kbase + k0 + k];
            float h = tf32_rn(va);
            Ah[i][k] = h; Al[i][k] = tf32_rn(va - h);
            float vb = g_Sigma[c][j0 + i][kbase + k0 + k];
            h = tf32_rn(vb);
            Bh[i][k] = h; Bl[i][k] = tf32_rn(vb - h);
        }
        __syncthreads();
#pragma unroll
        for (int ks = 0; ks < 2; ks++) {
            int k8 = ks * 8;
            uint32_t ah[2][4], al[2][4], bh[4][2], bl[4][2];
#pragma unroll
            for (int ms = 0; ms < 2; ms++) {
                int mb = wy * 32 + ms * 16;
                ah[ms][0] = FB(Ah[mb + r][k8 + q]);     ah[ms][1] = FB(Ah[mb + 8 + r][k8 + q]);
                ah[ms][2] = FB(Ah[mb + r][k8 + 4 + q]); ah[ms][3] = FB(Ah[mb + 8 + r][k8 + 4 + q]);
                al[ms][0] = FB(Al[mb + r][k8 + q]);     al[ms][1] = FB(Al[mb + 8 + r][k8 + q]);
                al[ms][2] = FB(Al[mb + r][k8 + 4 + q]); al[ms][3] = FB(Al[mb + 8 + r][k8 + 4 + q]);
            }
#pragma unroll
            for (int nt = 0; nt < 4; nt++) {
                int nb = wx * 32 + nt * 8;
                bh[nt][0] = FB(Bh[nb + r][k8 + q]); bh[nt][1] = FB(Bh[nb + r][k8 + 4 + q]);
                bl[nt][0] = FB(Bl[nb + r][k8 + q]); bl[nt][1] = FB(Bl[nb + r][k8 + 4 + q]);
            }
#pragma unroll
            for (int ms = 0; ms < 2; ms++)
#pragma unroll
                for (int nt = 0; nt < 4; nt++)
                    MMA3(acc[ms][nt], ah[ms], bh[nt], al[ms], bl[nt]);
        }
    }
    __syncthreads();
#pragma unroll
    for (int ms = 0; ms < 2; ms++)
#pragma unroll
        for (int nt = 0; nt < 4; nt++) {
            int i = i0 + wy * 32 + ms * 16 + r;
            int j = j0 + wx * 32 + nt * 8 + 2 * q;
            float* d = acc[ms][nt];
            g_Sigma[c][i][j]         -= d[0];
            g_Sigma[c][i][j + 1]     -= d[1];
            g_Sigma[c][i + 8][j]     -= d[2];
            g_Sigma[c][i + 8][j + 1] -= d[3];
        }
    if (blockIdx.x == 0) {
        int base = (kb + 1) * 64;
        __syncthreads();
        float (*Ds)[65] = (float(*)[65])buf;
        for (int e = tid; e < 4096; e += 128)
            Ds[e >> 6][e & 63] = g_Sigma[c][base + (e >> 6)][base + (e & 63)];
        __syncthreads();
        for (int j = 0; j < 64; j++) {
            if (tid == 0) Ds[j][j] = sqrtf(Ds[j][j]);
            __syncthreads();
            if (tid > j && tid < 64) Ds[tid][j] /= Ds[j][j];
            __syncthreads();
            for (int e = tid; e < 4096; e += 128) {
                int i = e >> 6, kc = e & 63;
                if (i > j && kc > j && kc <= i) Ds[i][kc] -= Ds[i][j] * Ds[kc][j];
            }
            __syncthreads();
        }
        if (tid < 64) {
            int j = tid;
            float x[64];
#pragma unroll
            for (int i = 0; i < 64; i++) {
                float tv = (i == j) ? 1.0f : 0.0f;
#pragma unroll
                for (int k = 0; k < i; k++) tv -= Ds[i][k] * x[k];
                x[i] = tv / Ds[i][i];
            }
#pragma unroll
            for (int i = 0; i < 64; i++) writeV(c, base + i, base + j, x[i]);
        }
    }
}

// ---------------- recursive triinv stage GEMM 1: T1 = A21 * V11 -------------------
__global__ __launch_bounds__(128) void k_tri1(int h) {
    __shared__ float Ah[64][20], Al[64][20], Bh[16][72], Bl[16][72];
    int c = blockIdx.y;
    int tpr = h >> 6, t2 = tpr * tpr;
    int p = blockIdx.x / t2;
    int rem = blockIdx.x % t2;
    int mi = rem / tpr, ni = rem % tpr;
    int base = p * 2 * h;
    int r0 = base + h + mi * 64;
    int n0 = ni * 64;
    int tid = threadIdx.x, lane = tid & 31, wid = tid >> 5;
    int wy = wid >> 1, wx = wid & 1;
    int r = lane >> 2, q = lane & 3;
    float acc[2][4][4] = {};
    for (int k0 = 0; k0 < h; k0 += 16) {
        __syncthreads();
        for (int t = 0; t < 8; t++) {
            int e = tid + 128 * t;
            {
                int i = e >> 4, k = e & 15;
                float v = g_Sigma[c][r0 + i][base + k0 + k];
                float hh = tf32_rn(v);
                Ah[i][k] = hh; Al[i][k] = tf32_rn(v - hh);
            }
            {
                int k = e >> 6, j = e & 63;
                float v = ((k0 + k) >= (n0 + j)) ? g_V[c][base + k0 + k][base + n0 + j] : 0.f;
                float hh = tf32_rn(v);
                Bh[k][j] = hh; Bl[k][j] = tf32_rn(v - hh);
            }
        }
        __syncthreads();
#pragma unroll
        for (int ks = 0; ks < 2; ks++) {
            int k8 = ks * 8;
            uint32_t ah[2][4], al[2][4], bh[4][2], bl[4][2];
#pragma unroll
            for (int ms = 0; ms < 2; ms++) {
                int mb = wy * 32 + ms * 16;
                ah[ms][0] = FB(Ah[mb + r][k8 + q]);     ah[ms][1] = FB(Ah[mb + 8 + r][k8 + q]);
                ah[ms][2] = FB(Ah[mb + r][k8 + 4 + q]); ah[ms][3] = FB(Ah[mb + 8 + r][k8 + 4 + q]);
                al[ms][0] = FB(Al[mb + r][k8 + q]);     al[ms][1] = FB(Al[mb + 8 + r][k8 + q]);
                al[ms][2] = FB(Al[mb + r][k8 + 4 + q]); al[ms][3] = FB(Al[mb + 8 + r][k8 + 4 + q]);
            }
#pragma unroll
            for (int nt = 0; nt < 4; nt++) {
                int nb = wx * 32 + nt * 8;
                bh[nt][0] = FB(Bh[k8 + q][nb + r]); bh[nt][1] = FB(Bh[k8 + 4 + q][nb + r]);
                bl[nt][0] = FB(Bl[k8 + q][nb + r]); bl[nt][1] = FB(Bl[k8 + 4 + q][nb + r]);
            }
#pragma unroll
            for (int ms = 0; ms < 2; ms++)
#pragma unroll
                for (int nt = 0; nt < 4; nt++)
                    MMA3(acc[ms][nt], ah[ms], bh[nt], al[ms], bl[nt]);
        }
    }
    int pb = p * h * h;
#pragma unroll
    for (int ms = 0; ms < 2; ms++)
#pragma unroll
        for (int nt = 0; nt < 4; nt++) {
            int il = mi * 64 + wy * 32 + ms * 16 + r;
            int jl = n0 + wx * 32 + nt * 8 + 2 * q;
            float* d = acc[ms][nt];
            g_T1[c][pb + il * h + jl]           = d[0];
            g_T1[c][pb + il * h + jl + 1]       = d[1];
            g_T1[c][pb + (il + 8) * h + jl]     = d[2];
            g_T1[c][pb + (il + 8) * h + jl + 1] = d[3];
        }
}

// ---------------- stage GEMM 2: V21 = -V22 * T1 (writes V + bf16) -----------------
__global__ __launch_bounds__(128) void k_tri2(int h) {
    __shared__ float Ah[64][20], Al[64][20], Bh[16][72], Bl[16][72];
    int c = blockIdx.y;
    int tpr = h >> 6, t2 = tpr * tpr;
    int p = blockIdx.x / t2;
    int rem = blockIdx.x % t2;
    int mi = rem / tpr, ni = rem % tpr;
    int base = p * 2 * h;
    int rv = base + h;
    int n0 = ni * 64;
    int tid = threadIdx.x, lane = tid & 31, wid = tid >> 5;
    int wy = wid >> 1, wx = wid & 1;
    int r = lane >> 2, q = lane & 3;
    int pb = p * h * h;
    float acc[2][4][4] = {};
    for (int k0 = 0; k0 < h; k0 += 16) {
        __syncthreads();
        for (int t = 0; t < 8; t++) {
            int e = tid + 128 * t;
            {
                int i = e >> 4, k = e & 15;
                float v = ((mi * 64 + i) >= (k0 + k)) ? g_V[c][rv + mi * 64 + i][rv + k0 + k] : 0.f;
                float hh = tf32_rn(v);
                Ah[i][k] = hh; Al[i][k] = tf32_rn(v - hh);
            }
            {
                int k = e >> 6, j = e & 63;
                float v = g_T1[c][pb + (k0 + k) * h + n0 + j];
                float hh = tf32_rn(v);
                Bh[k][j] = hh; Bl[k][j] = tf32_rn(v - hh);
            }
        }
        __syncthreads();
#pragma unroll
        for (int ks = 0; ks < 2; ks++) {
            int k8 = ks * 8;
            uint32_t ah[2][4], al[2][4], bh[4][2], bl[4][2];
#pragma unroll
            for (int ms = 0; ms < 2; ms++) {
                int mb = wy * 32 + ms * 16;
                ah[ms][0] = FB(Ah[mb + r][k8 + q]);     ah[ms][1] = FB(Ah[mb + 8 + r][k8 + q]);
                ah[ms][2] = FB(Ah[mb + r][k8 + 4 + q]); ah[ms][3] = FB(Ah[mb + 8 + r][k8 + 4 + q]);
                al[ms][0] = FB(Al[mb + r][k8 + q]);     al[ms][1] = FB(Al[mb + 8 + r][k8 + q]);
                al[ms][2] = FB(Al[mb + r][k8 + 4 + q]); al[ms][3] = FB(Al[mb + 8 + r][k8 + 4 + q]);
            }
#pragma unroll
            for (int nt = 0; nt < 4; nt++) {
                int nb = wx * 32 + nt * 8;
                bh[nt][0] = FB(Bh[k8 + q][nb + r]); bh[nt][1] = FB(Bh[k8 + 4 + q][nb + r]);
                bl[nt][0] = FB(Bl[k8 + q][nb + r]); bl[nt][1] = FB(Bl[k8 + 4 + q][nb + r]);
            }
#pragma unroll
            for (int ms = 0; ms < 2; ms++)
#pragma unroll
                for (int nt = 0; nt < 4; nt++)
                    MMA3(acc[ms][nt], ah[ms], bh[nt], al[ms], bl[nt]);
        }
    }
#pragma unroll
    for (int ms = 0; ms < 2; ms++)
#pragma unroll
        for (int nt = 0; nt < 4; nt++) {
            int ig = rv + mi * 64 + wy * 32 + ms * 16 + r;
            int jg = base + n0 + wx * 32 + nt * 8 + 2 * q;
            float* d = acc[ms][nt];
            writeV(c, ig, jg, -d[0]);
            writeV(c, ig, jg + 1, -d[1]);
            writeV(c, ig + 8, jg, -d[2]);
            writeV(c, ig + 8, jg + 1, -d[3]);
        }
}

// ---------------- conversions / small vec kernels ----------------
__global__ void k_cvt_xq(const float* __restrict__ Xq) {
    int i = blockIdx.x * 256 + threadIdx.x;
    float x = Xq[i];
    __nv_bfloat16 h = __float2bfloat16(x);
    ((__nv_bfloat16*)g_Xqh)[i] = h;
    ((__nv_bfloat16*)g_Xql)[i] = __float2bfloat16(x - __bfloat162float(h));
}
__global__ void k_svec() {
    int c = blockIdx.y;
    int warp = threadIdx.x >> 5, lane = threadIdx.x & 31;
    int row = blockIdx.x * 8 + warp;
    float acc = 0.f;
    for (int k = lane; k <= row; k += 32) acc += g_V[c][row][k] * g_mu[c][k];
    for (int o = 16; o > 0; o >>= 1) acc += __shfl_down_sync(0xffffffffu, acc, o);
    if (lane == 0) g_s[c][row] = acc;
}
__global__ void k_scalars() {
    int c = blockIdx.x;
    __shared__ float r1[256], r2[256];
    float a = 0.f, b = 0.f;
    for (int k = threadIdx.x; k < D; k += 256) {
        float sv = g_s[c][k];  a += sv * sv;
        float mv = g_mu[c][k]; b += mv * mv;
    }
    r1[threadIdx.x] = a; r2[threadIdx.x] = b;
    __syncthreads();
    for (int o = 128; o > 0; o >>= 1) {
        if (threadIdx.x < o) { r1[threadIdx.x] += r1[threadIdx.x + o]; r2[threadIdx.x] += r2[threadIdx.x + o]; }
        __syncthreads();
    }
    if (threadIdx.x == 0) { g_ssc[c] = r1[0]; g_mmc[c] = r2[0]; }
}
__global__ void k_nx(const float* __restrict__ Xq) {
    int warp = threadIdx.x >> 5, lane = threadIdx.x & 31;
    int row = blockIdx.x * 8 + warp;
    float acc = 0.f;
    for (int k = lane; k < D; k += 32) { float v = Xq[(size_t)row * D + k]; acc += v * v; }
    for (int o = 16; o > 0; o >>= 1) acc += __shfl_down_sync(0xffffffffu, acc, o);
    if (lane == 0) g_nx[row] = acc;
}
__global__ void k_xm(const float* __restrict__ Xq) {
    int warp = threadIdx.x >> 5, lane = threadIdx.x & 31;
    int row = blockIdx.x * 8 + warp;
    float acc[CLS];
#pragma unroll
    for (int c = 0; c < CLS; c++) acc[c] = 0.f;
    for (int k = lane; k < D; k += 32) {
        float v = Xq[(size_t)row * D + k];
#pragma unroll
        for (int c = 0; c < CLS; c++) acc[c] += v * g_mu[c][k];
    }
#pragma unroll
    for (int c = 0; c < CLS; c++) {
        float a = acc[c];
        for (int o = 16; o > 0; o >>= 1) a += __shfl_down_sync(0xffffffffu, a, o);
        if (lane == 0) g_xm[row][c] = a;
    }
}

// ====== logits: bf16-split mma, jt-paired + cp.async double-buffered pipeline =====
#define LG2_ROWB  144
#define LG2_SAH   0
#define LG2_SAL   18432
#define LG2_SBH   36864
#define LG2_SBL   55296
#define LG2_STAGE 73728
#define LG2_SMEM  147456

__device__ __forceinline__ void lg_stage(uint32_t sb, int s, int c, int m0, int jt0,
                                         int kt, int tid) {
    uint32_t base = sb + (uint32_t)(s * LG2_STAGE);
#pragma unroll
    for (int t = 0; t < 4; t++) {
        int idx = tid + 256 * t;
        int r = idx >> 3, c8 = idx & 7;
        uint32_t off = (uint32_t)(r * LG2_ROWB + c8 * 16);
        cpa16(base + LG2_SAH + off, &g_Xqh[m0 + r][kt * 64 + c8 * 8]);
        cpa16(base + LG2_SAL + off, &g_Xql[m0 + r][kt * 64 + c8 * 8]);
    }
#pragma unroll
    for (int t = 0; t < 4; t++) {
        int idx = tid + 256 * t;
        int tt = idx >> 9;
        int rr = (idx >> 3) & 63, c8 = idx & 7;
        uint32_t off = (uint32_t)(tt * 9216 + rr * LG2_ROWB + c8 * 16);
        int row = (jt0 + tt) * 64 + rr;
        cpa16(base + LG2_SBH + off, &g_Vh[c][row][kt * 64 + c8 * 8]);
        cpa16(base + LG2_SBL + off, &g_Vl[c][row][kt * 64 + c8 * 8]);
    }
}

__global__ __launch_bounds__(256) void k_logits_mma(float* __restrict__ out) {
    extern __shared__ char smem[];
    uint32_t sb = smem_u32(smem);
    int tid = threadIdx.x, lane = tid & 31, wid = tid >> 5;
    int wm = wid >> 1, wn = wid & 1;
    int c = blockIdx.y, m0 = blockIdx.x * 128;

    uint32_t aoff = (uint32_t)((wm * 32 + (lane & 15)) * LG2_ROWB + (lane >> 4) * 16);
    uint32_t boff = (uint32_t)((wn * 32 + ((lane & 16) >> 1) + (lane & 7)) * LG2_ROWB
                               + ((lane & 8) ? 16 : 0));

    float q2[2][2] = {}, qb[2][2] = {};

    for (int pj = 0; pj < 8; pj++) {
        int jt0 = 2 * pj, jt1 = jt0 + 1;
        float acc[2][2][4][4] = {};
        lg_stage(sb, 0, c, m0, jt0, 0, tid);
        CPA_COMMIT;
        for (int kt = 0; kt <= jt1; kt++) {
            if (kt < jt1) {
                lg_stage(sb, (kt + 1) & 1, c, m0, jt0, kt + 1, tid);
                CPA_COMMIT;
                CPA_WAIT1;
            } else {
                CPA_WAIT0;
            }
            __syncthreads();
            uint32_t s0 = sb + (uint32_t)((kt & 1) * LG2_STAGE);
            uint32_t aH = s0 + LG2_SAH + aoff, aL = s0 + LG2_SAL + aoff;
            uint32_t bH0 = s0 + LG2_SBH + boff, bL0 = s0 + LG2_SBL + boff;
#pragma unroll
            for (int ks = 0; ks < 4; ks++) {
                uint32_t ah[2][4], al[2][4];
                ldsm4(ah[0], aH + ks * 32);
                ldsm4(ah[1], aH + 16 * LG2_ROWB + ks * 32);
                ldsm4(al[0], aL + ks * 32);
                ldsm4(al[1], aL + 16 * LG2_ROWB + ks * 32);
#pragma unroll
                for (int t = 0; t < 2; t++) {
                    if (t == 0 && kt > jt0) continue;
                    uint32_t bh[8], bl[8];
                    ldsm4(&bh[0], bH0 + t * 9216 + ks * 32);
                    ldsm4(&bh[4], bH0 + t * 9216 + 16 * LG2_ROWB + ks * 32);
                    ldsm4(&bl[0], bL0 + t * 9216 + ks * 32);
                    ldsm4(&bl[4], bL0 + t * 9216 + 16 * LG2_ROWB + ks * 32);
#pragma unroll
                    for (int ms = 0; ms < 2; ms++)
#pragma unroll
                        for (int nt = 0; nt < 4; nt++) {
                            float* d = acc[t][ms][nt];
                            mma16816(d, ah[ms], &bh[nt * 2]);
                            mma16816(d, al[ms], &bh[nt * 2]);
                            mma16816(d, ah[ms], &bl[nt * 2]);
                        }
                }
            }
            __syncthreads();
        }
#pragma unroll
        for (int t = 0; t < 2; t++) {
            int jt = jt0 + t;
#pragma unroll
            for (int ms = 0; ms < 2; ms++)
#pragma unroll
                for (int nt = 0; nt < 4; nt++) {
                    int jc = jt * 64 + wn * 32 + nt * 8 + 2 * (lane & 3);
                    float s0 = g_s[c][jc], s1 = g_s[c][jc + 1];
                    float* d = acc[t][ms][nt];
                    q2[ms][0] += d[0] * d[0] + d[1] * d[1];
                    qb[ms][0] += d[0] * s0 + d[1] * s1;
                    q2[ms][1] += d[2] * d[2] + d[3] * d[3];
                    qb[ms][1] += d[2] * s0 + d[3] * s1;
                }
        }
    }

    __syncthreads();
    float* rq = (float*)smem;
    float* rb = (float*)(smem + 4096);
    int slot = wn * 4 + (lane & 3);
    int g = lane >> 2;
#pragma unroll
    for (int ms = 0; ms < 2; ms++)
#pragma unroll
        for (int go = 0; go < 2; go++) {
            int row = wm * 32 + ms * 16 + go * 8 + g;
            rq[row * 8 + slot] = q2[ms][go];
            rb[row * 8 + slot] = qb[ms][go];
        }
    __syncthreads();
    if (tid < 128) {
        float q2r = 0.f, qbr = 0.f;
#pragma unroll
        for (int t = 0; t < 8; t++) { q2r += rq[tid * 8 + t]; qbr += rb[tid * 8 + t]; }
        int row = m0 + tid;
        float dq = g_nx[row] - 2.f * g_xm[row][c] + g_mmc[c];
        float qm = q2r - 2.f * qbr + g_ssc[c];
        out[(size_t)row * CLS + c] = -0.9f * qm - 0.1f * dq;
    }
}

// ---------------- launch ----------------
extern "C" void kernel_launch(void* const* d_in, const int* in_sizes, int n_in,
                              void* d_out, int out_size) {
    const float* X     = (const float*)d_in[0];
    const int*   y     = (const int*)d_in[1];
    const float* Xq    = (const float*)d_in[2];
    const float* m     = (const float*)d_in[3];
    const float* kappa = (const float*)d_in[4];
    const float* nu    = (const float*)d_in[5];
    const float* td    = (const float*)d_in[6];
    const float* tl    = (const float*)d_in[7];
    float* out = (float*)d_out;

    cudaFuncSetAttribute(k_logits_mma, cudaFuncAttributeMaxDynamicSharedMemorySize, LG2_SMEM);

    k_stats1<<<dim3(8, 8), 128>>>(X, y);
    k_sort_params<<<1, 32>>>(y, kappa, nu);
    k_mu<<<dim3(4, CLS), 256>>>(m);
    k_cvt_xq<<<16384, 256>>>(Xq);
    k_buildL<<<D, 256>>>(td, tl);
    k_base<<<dim3(NT, NT), 256>>>(m);
    k_nx<<<MQ / 8, 256>>>(Xq);
    k_xm<<<MQ / 8, 256>>>(Xq);

    k_sigma_mma<<<dim3(8, 16, CLS), 256>>>(X);
    k_chol_diag0<<<CLS, 256>>>();
    for (int kb = 0; kb < NT - 1; kb++) {
        int T = NT - 1 - kb;
        k_pgemm<<<dim3(T, CLS), 128>>>(kb);
        k_trail_mma<<<dim3(T * (T + 1) / 2, CLS), 128>>>(kb);
    }
    for (int s = 0; s < 4; s++) {
        int h = 64 << s;
        int tpr = h >> 6;
        int tiles = (D / (2 * h)) * tpr * tpr;
        k_tri1<<<dim3(tiles, CLS), 128>>>(h);
        k_tri2<<<dim3(tiles, CLS), 128>>>(h);
    }
    k_svec<<<dim3(D / 8, CLS), 256>>>();
    k_scalars<<<CLS, 256>>>();
    k_logits_mma<<<dim3(MQ / 128, CLS), 256, LG2_SMEM>>>(out);
}